// round 1
// baseline (speedup 1.0000x reference)
#include <cuda_runtime.h>

// Fused 2-block tiny-transformer over 131072 independent sequences.
// One warp = one batch element. Weights (both blocks) staged in shared once
// per CTA with conflict-free transposed layouts (odd strides). Activations:
// h[12][32] and g[12][128] per warp in shared; accumulators in registers.

namespace {
constexpr int S  = 11;
constexpr int NW = 12;              // warps per CTA
constexpr int THREADS = NW * 32;
constexpr int BTOT = 131072;

// --- per-block weight sub-offsets (floats), odd strides kill STS conflicts ---
constexpr int QKVW_STR = 97;        // [32][97] used cols 0..95
constexpr int OUTW_STR = 33;        // [32][33] used cols 0..31
constexpr int W1_STR   = 129;       // [32][129] used cols 0..127
constexpr int W2_STR   = 33;        // [128][33] used cols 0..31

constexpr int O_QKVW = 0;                         // 32*97  = 3104
constexpr int O_QKVB = O_QKVW + 32 * QKVW_STR;    // 3104 (96)
constexpr int O_OUTW = O_QKVB + 96;               // 3200 (32*33 = 1056)
constexpr int O_OUTB = O_OUTW + 32 * OUTW_STR;    // 4256 (32)
constexpr int O_LNAG = O_OUTB + 32;               // 4288
constexpr int O_LNAB = O_LNAG + 32;               // 4320
constexpr int O_W1   = O_LNAB + 32;               // 4352 (32*129 = 4128)
constexpr int O_B1   = O_W1 + 32 * W1_STR;        // 8480 (128)
constexpr int O_W2   = O_B1 + 128;                // 8608 (128*33 = 4224)
constexpr int O_B2   = O_W2 + 128 * W2_STR;       // 12832 (32)
constexpr int O_LNBG = O_B2 + 32;                 // 12864
constexpr int O_LNBB = O_LNBG + 32;               // 12896
constexpr int BLK_SZ = O_LNBB + 32;               // 12928

// --- global smem layout (floats) ---
constexpr int O_WFEAT = 0;                        // [10][32]
constexpr int O_BFEAT = O_WFEAT + 320;            // [10][32]
constexpr int O_CLS   = O_BFEAT + 320;            // 32
constexpr int O_CLFW  = O_CLS + 32;               // 32
constexpr int O_CLFB  = O_CLFW + 32;              // 1 (+pad)
constexpr int O_BLK0  = 720;
constexpr int O_BLK1  = O_BLK0 + BLK_SZ;          // 13648
constexpr int O_ACT   = O_BLK1 + BLK_SZ;          // 26576 (16B-aligned *4)
constexpr int H_FLOATS = 12 * 32;                 // per-warp token buffer
constexpr int G_FLOATS = 12 * 128;                // per-warp ffn scratch
constexpr int ACT_PER_WARP = H_FLOATS + G_FLOATS; // 1920
constexpr int SMEM_FLOATS = O_ACT + NW * ACT_PER_WARP;   // 49616
constexpr int SMEM_BYTES  = SMEM_FLOATS * 4;             // 198464
}

extern __shared__ float smem[];

struct KParams {
    const float* in[30];
    float* out;
};

// One transformer block for one warp. h = smem[hoff] : [12][32] tokens.
// g = smem[goff] : [12][128] scratch. W = smem[woff] : block weights.
__device__ __noinline__ void block_forward(int hoff, int goff, int woff, int lane)
{
    float* __restrict__ h = &smem[hoff];
    float* __restrict__ g = &smem[goff];
    const float* __restrict__ W = &smem[woff];

    // ---------------- QKV projection ----------------
    float qa[S], ka[S], va[S];
    {
        const float bq = W[O_QKVB + lane];
        const float bk = W[O_QKVB + 32 + lane];
        const float bv = W[O_QKVB + 64 + lane];
#pragma unroll
        for (int s = 0; s < S; s++) { qa[s] = bq; ka[s] = bk; va[s] = bv; }
    }
    for (int d0 = 0; d0 < 32; d0 += 4) {
        float wq[4], wk[4], wv[4];
#pragma unroll
        for (int j = 0; j < 4; j++) {
            const float* wr = &W[O_QKVW + (d0 + j) * QKVW_STR];
            wq[j] = wr[lane]; wk[j] = wr[32 + lane]; wv[j] = wr[64 + lane];
        }
#pragma unroll
        for (int s = 0; s < S; s++) {
            float4 hv = *reinterpret_cast<const float4*>(&h[s * 32 + d0]);
            qa[s] = fmaf(hv.x, wq[0], qa[s]); qa[s] = fmaf(hv.y, wq[1], qa[s]);
            qa[s] = fmaf(hv.z, wq[2], qa[s]); qa[s] = fmaf(hv.w, wq[3], qa[s]);
            ka[s] = fmaf(hv.x, wk[0], ka[s]); ka[s] = fmaf(hv.y, wk[1], ka[s]);
            ka[s] = fmaf(hv.z, wk[2], ka[s]); ka[s] = fmaf(hv.w, wk[3], ka[s]);
            va[s] = fmaf(hv.x, wv[0], va[s]); va[s] = fmaf(hv.y, wv[1], va[s]);
            va[s] = fmaf(hv.z, wv[2], va[s]); va[s] = fmaf(hv.w, wv[3], va[s]);
        }
    }
#pragma unroll
    for (int s = 0; s < S; s++) qa[s] *= 0.35355339059327373f;  // 1/sqrt(8)

    // ---------------- attention (4 heads x 8 dims; lane = global dim) -------
#pragma unroll
    for (int qi = 0; qi < S; qi++) {
        float sc[S];
#pragma unroll
        for (int ki = 0; ki < S; ki++) {
            float p = qa[qi] * ka[ki];
            p += __shfl_xor_sync(0xffffffffu, p, 1);
            p += __shfl_xor_sync(0xffffffffu, p, 2);
            p += __shfl_xor_sync(0xffffffffu, p, 4);   // head-local dot
            sc[ki] = p;
        }
        float m = sc[0];
#pragma unroll
        for (int ki = 1; ki < S; ki++) m = fmaxf(m, sc[ki]);
        float den = 0.f;
#pragma unroll
        for (int ki = 0; ki < S; ki++) { sc[ki] = __expf(sc[ki] - m); den += sc[ki]; }
        float c = 0.f;
#pragma unroll
        for (int ki = 0; ki < S; ki++) c = fmaf(sc[ki], va[ki], c);
        g[qi * 128 + lane] = c / den;        // stage ctx for out-proj broadcast
    }
    __syncwarp();

    // ---------------- output projection + residual + LN_A ------------------
    float o[S];
    {
        const float bo = W[O_OUTB + lane];
#pragma unroll
        for (int s = 0; s < S; s++) o[s] = bo;
    }
    for (int d0 = 0; d0 < 32; d0 += 4) {
        float wr[4];
#pragma unroll
        for (int j = 0; j < 4; j++) wr[j] = W[O_OUTW + (d0 + j) * OUTW_STR + lane];
#pragma unroll
        for (int s = 0; s < S; s++) {
            float4 cv = *reinterpret_cast<const float4*>(&g[s * 128 + d0]);
            o[s] = fmaf(cv.x, wr[0], o[s]); o[s] = fmaf(cv.y, wr[1], o[s]);
            o[s] = fmaf(cv.z, wr[2], o[s]); o[s] = fmaf(cv.w, wr[3], o[s]);
        }
    }
    {
        const float lg = W[O_LNAG + lane], lb = W[O_LNAB + lane];
#pragma unroll
        for (int s = 0; s < S; s++) {
            float v = o[s] + h[s * 32 + lane];
            float sum = v, sq = v * v;
#pragma unroll
            for (int mk = 16; mk; mk >>= 1) {
                sum += __shfl_xor_sync(0xffffffffu, sum, mk);
                sq  += __shfl_xor_sync(0xffffffffu, sq,  mk);
            }
            float mu  = sum * 0.03125f;
            float var = fmaf(-mu, mu, sq * 0.03125f);
            float xn  = (v - mu) * rsqrtf(var + 1e-5f);
            h[s * 32 + lane] = fmaf(xn, lg, lb);
        }
    }
    __syncwarp();

    // ---------------- FFN1 (32 -> 128) + exact GELU -------------------------
    float ga[4][S];
#pragma unroll
    for (int j = 0; j < 4; j++) {
        const float bb = W[O_B1 + lane + 32 * j];
#pragma unroll
        for (int s = 0; s < S; s++) ga[j][s] = bb;
    }
    for (int d0 = 0; d0 < 32; d0 += 4) {
        float w1r[4][4];
#pragma unroll
        for (int jj = 0; jj < 4; jj++) {
            const float* wr = &W[O_W1 + (d0 + jj) * W1_STR + lane];
#pragma unroll
            for (int j = 0; j < 4; j++) w1r[j][jj] = wr[32 * j];
        }
#pragma unroll
        for (int s = 0; s < S; s++) {
            float4 hv = *reinterpret_cast<const float4*>(&h[s * 32 + d0]);
#pragma unroll
            for (int j = 0; j < 4; j++) {
                ga[j][s] = fmaf(hv.x, w1r[j][0], ga[j][s]);
                ga[j][s] = fmaf(hv.y, w1r[j][1], ga[j][s]);
                ga[j][s] = fmaf(hv.z, w1r[j][2], ga[j][s]);
                ga[j][s] = fmaf(hv.w, w1r[j][3], ga[j][s]);
            }
        }
    }
#pragma unroll
    for (int j = 0; j < 4; j++)
#pragma unroll
        for (int s = 0; s < S; s++) {
            float v = ga[j][s];
            v = 0.5f * v * (1.f + erff(v * 0.7071067811865475f));
            g[s * 128 + lane + 32 * j] = v;
        }
    __syncwarp();

    // ---------------- FFN2 (128 -> 32) + residual + LN_B --------------------
    float o2[S];
    {
        const float b2 = W[O_B2 + lane];
#pragma unroll
        for (int s = 0; s < S; s++) o2[s] = b2;
    }
    for (int f0 = 0; f0 < 128; f0 += 4) {
        float w2r[4];
#pragma unroll
        for (int j = 0; j < 4; j++) w2r[j] = W[O_W2 + (f0 + j) * W2_STR + lane];
#pragma unroll
        for (int s = 0; s < S; s++) {
            float4 gv = *reinterpret_cast<const float4*>(&g[s * 128 + f0]);
            o2[s] = fmaf(gv.x, w2r[0], o2[s]); o2[s] = fmaf(gv.y, w2r[1], o2[s]);
            o2[s] = fmaf(gv.z, w2r[2], o2[s]); o2[s] = fmaf(gv.w, w2r[3], o2[s]);
        }
    }
    {
        const float lg = W[O_LNBG + lane], lb = W[O_LNBB + lane];
#pragma unroll
        for (int s = 0; s < S; s++) {
            float v = o2[s] + h[s * 32 + lane];
            float sum = v, sq = v * v;
#pragma unroll
            for (int mk = 16; mk; mk >>= 1) {
                sum += __shfl_xor_sync(0xffffffffu, sum, mk);
                sq  += __shfl_xor_sync(0xffffffffu, sq,  mk);
            }
            float mu  = sum * 0.03125f;
            float var = fmaf(-mu, mu, sq * 0.03125f);
            float xn  = (v - mu) * rsqrtf(var + 1e-5f);
            h[s * 32 + lane] = fmaf(xn, lg, lb);
        }
    }
    __syncwarp();
}

__global__ void __launch_bounds__(THREADS)
tab_transformer_kernel(KParams p)
{
    const int tid = threadIdx.x;

    // ================== stage weights into shared (conflict-free) ==========
    for (int i = tid; i < 320; i += THREADS) smem[O_WFEAT + i] = p.in[1][i];
    for (int i = tid; i < 320; i += THREADS) smem[O_BFEAT + i] = p.in[2][i];
    if (tid < 32) {
        smem[O_CLS  + tid] = p.in[3][tid];
        smem[O_CLFW + tid] = p.in[28][tid];
    }
    if (tid == 0) smem[O_CLFB] = p.in[29][0];

#pragma unroll
    for (int blk = 0; blk < 2; blk++) {
        float* W = &smem[blk ? O_BLK1 : O_BLK0];
        const float* const* q = &p.in[4 + blk * 12];
        // q: in_w, in_b, out_w, out_b, lnag, lnab, w1, b1, w2, b2, lnbg, lnbb
        for (int i = tid; i < 3072; i += THREADS) {           // [96][32] -> [32][97]
            int e = i >> 5, d = i & 31;
            W[O_QKVW + d * QKVW_STR + e] = q[0][i];
        }
        for (int i = tid; i < 96; i += THREADS) W[O_QKVB + i] = q[1][i];
        for (int i = tid; i < 1024; i += THREADS) {           // [32][32] -> [32][33]
            int e = i >> 5, d = i & 31;
            W[O_OUTW + d * OUTW_STR + e] = q[2][i];
        }
        if (tid < 32) {
            W[O_OUTB + tid] = q[3][tid];
            W[O_LNAG + tid] = q[4][tid];
            W[O_LNAB + tid] = q[5][tid];
        }
        for (int i = tid; i < 4096; i += THREADS) {           // [128][32] -> [32][129]
            int f = i >> 5, d = i & 31;
            W[O_W1 + d * W1_STR + f] = q[6][i];
        }
        for (int i = tid; i < 128; i += THREADS) W[O_B1 + i] = q[7][i];
        for (int i = tid; i < 4096; i += THREADS) {           // [32][128] -> [128][33]
            int d = i >> 7, f = i & 127;
            W[O_W2 + f * W2_STR + d] = q[8][i];
        }
        if (tid < 32) {
            W[O_B2   + tid] = q[9][tid];
            W[O_LNBG + tid] = q[10][tid];
            W[O_LNBB + tid] = q[11][tid];
        }
    }
    __syncthreads();

    const int warp = tid >> 5, lane = tid & 31;
    const int b = blockIdx.x * NW + warp;
    if (b >= BTOT) return;

    const int hoff = O_ACT + warp * ACT_PER_WARP;
    const int goff = hoff + H_FLOATS;
    float* h = &smem[hoff];

    // ================== embedding: cls + per-feature Linear(1,32) ==========
    float xv = (lane < 10) ? p.in[0][(size_t)b * 10 + lane] : 0.f;
    h[lane] = smem[O_CLS + lane];
#pragma unroll
    for (int i = 0; i < 10; i++) {
        float xi = __shfl_sync(0xffffffffu, xv, i);
        h[(i + 1) * 32 + lane] = fmaf(xi, smem[O_WFEAT + i * 32 + lane],
                                          smem[O_BFEAT + i * 32 + lane]);
    }
    __syncwarp();

    block_forward(hoff, goff, O_BLK0, lane);
    block_forward(hoff, goff, O_BLK1, lane);

    // ================== classifier on cls token ============================
    float v = h[lane] * smem[O_CLFW + lane];
#pragma unroll
    for (int mk = 16; mk; mk >>= 1) v += __shfl_xor_sync(0xffffffffu, v, mk);
    if (lane == 0) p.out[b] = v + smem[O_CLFB];
}

extern "C" void kernel_launch(void* const* d_in, const int* in_sizes, int n_in,
                              void* d_out, int out_size)
{
    (void)in_sizes; (void)n_in; (void)out_size;
    KParams p;
    for (int i = 0; i < 30; i++) p.in[i] = (const float*)d_in[i];
    p.out = (float*)d_out;

    cudaFuncSetAttribute(tab_transformer_kernel,
                         cudaFuncAttributeMaxDynamicSharedMemorySize, SMEM_BYTES);

    const int grid = (BTOT + NW - 1) / NW;   // 10923
    tab_transformer_kernel<<<grid, THREADS, SMEM_BYTES>>>(p);
}

// round 2
// speedup vs baseline: 1.1928x; 1.1928x over previous
#include <cuda_runtime.h>

// Fused 2-block tiny-transformer, 131072 sequences. One warp = TWO batch
// elements packed as f32x2 (fma.rn.f32x2 / add / mul via PTX). Weights staged
// in shared with odd strides (conflict-free transposed layouts). Activations
// per warp: h2[12][32] float2 tokens + g2[6][128] float2 FFN/ctx scratch.

namespace {
constexpr int S  = 11;
constexpr int NW = 12;              // warps per CTA
constexpr int THREADS = NW * 32;
constexpr int BTOT = 131072;
constexpr int NPAIR = BTOT / 2;     // 65536 batch-pairs, one per warp

// --- per-block weight sub-offsets (floats), odd strides kill STS conflicts ---
constexpr int QKVW_STR = 97;
constexpr int OUTW_STR = 33;
constexpr int W1_STR   = 129;
constexpr int W2_STR   = 33;

constexpr int O_QKVW = 0;
constexpr int O_QKVB = O_QKVW + 32 * QKVW_STR;    // 3104
constexpr int O_OUTW = O_QKVB + 96;               // 3200
constexpr int O_OUTB = O_OUTW + 32 * OUTW_STR;    // 4256
constexpr int O_LNAG = O_OUTB + 32;
constexpr int O_LNAB = O_LNAG + 32;
constexpr int O_W1   = O_LNAB + 32;               // 4352
constexpr int O_B1   = O_W1 + 32 * W1_STR;        // 8480
constexpr int O_W2   = O_B1 + 128;                // 8608
constexpr int O_B2   = O_W2 + 128 * W2_STR;       // 12832
constexpr int O_LNBG = O_B2 + 32;
constexpr int O_LNBB = O_LNBG + 32;
constexpr int BLK_SZ = O_LNBB + 32;               // 12928

// --- global smem layout (floats) ---
constexpr int O_WFEAT = 0;                        // [10][32]
constexpr int O_BFEAT = O_WFEAT + 320;
constexpr int O_CLS   = O_BFEAT + 320;
constexpr int O_CLFW  = O_CLS + 32;
constexpr int O_CLFB  = O_CLFW + 32;
constexpr int O_BLK0  = 720;
constexpr int O_BLK1  = O_BLK0 + BLK_SZ;          // 13648
constexpr int O_ACT   = O_BLK1 + BLK_SZ;          // 26576 (16B aligned *4)
constexpr int H2_F = 12 * 32 * 2;                 // h2: [12][32] float2 = 768 floats
constexpr int G2_F = 6 * 128 * 2;                 // g2: [6][128] float2 = 1536 floats
constexpr int ACT_F = H2_F + G2_F;                // 2304 floats / warp
constexpr int SMEM_FLOATS = O_ACT + NW * ACT_F;   // 54224
constexpr int SMEM_BYTES  = SMEM_FLOATS * 4;      // 216896 (< 227KB)
}

extern __shared__ float smem[];

using u64 = unsigned long long;

static __device__ __forceinline__ u64 pack2(float x, float y) {
    u64 r; asm("mov.b64 %0,{%1,%2};" : "=l"(r) : "f"(x), "f"(y)); return r;
}
static __device__ __forceinline__ void unpack2(u64 v, float& x, float& y) {
    asm("mov.b64 {%0,%1},%2;" : "=f"(x), "=f"(y) : "l"(v));
}
static __device__ __forceinline__ u64 dup2(float x) { return pack2(x, x); }
static __device__ __forceinline__ u64 fma2(u64 a, u64 b, u64 c) {
    u64 d; asm("fma.rn.f32x2 %0,%1,%2,%3;" : "=l"(d) : "l"(a), "l"(b), "l"(c)); return d;
}
static __device__ __forceinline__ u64 add2(u64 a, u64 b) {
    u64 d; asm("add.rn.f32x2 %0,%1,%2;" : "=l"(d) : "l"(a), "l"(b)); return d;
}
static __device__ __forceinline__ u64 mul2(u64 a, u64 b) {
    u64 d; asm("mul.rn.f32x2 %0,%1,%2;" : "=l"(d) : "l"(a), "l"(b)); return d;
}
static __device__ __forceinline__ u64 shflx2(u64 v, int m) {
    float x, y; unpack2(v, x, y);
    x = __shfl_xor_sync(0xffffffffu, x, m);
    y = __shfl_xor_sync(0xffffffffu, y, m);
    return pack2(x, y);
}
static __device__ __forceinline__ float gelu1(float x) {
    return 0.5f * x * (1.0f + erff(x * 0.7071067811865475f));
}

struct KParams {
    const float* in[30];
    float* out;
};

// FFN over tokens [SB, SB+SN): FFN1 -> GELU (staged to g2) -> FFN2 -> +res -> LN_B
template <int SB, int SN>
static __device__ __forceinline__ void ffn_pass(float2* h2, float2* g2,
                                                const float* W, int lane)
{
    u64* h2u = reinterpret_cast<u64*>(h2);
    u64* g2u = reinterpret_cast<u64*>(g2);

    // ---- FFN1: 32 -> 128 ----
    u64 ga[4][SN];
#pragma unroll
    for (int j = 0; j < 4; j++) {
        u64 b = dup2(W[O_B1 + lane + 32 * j]);
#pragma unroll
        for (int t = 0; t < SN; t++) ga[j][t] = b;
    }
    for (int d0 = 0; d0 < 32; d0 += 2) {
        u64 w[4][2];
#pragma unroll
        for (int j = 0; j < 4; j++) {
            w[j][0] = dup2(W[O_W1 + d0 * W1_STR + lane + 32 * j]);
            w[j][1] = dup2(W[O_W1 + (d0 + 1) * W1_STR + lane + 32 * j]);
        }
#pragma unroll
        for (int t = 0; t < SN; t++) {
            float4 hv = *reinterpret_cast<const float4*>(&h2[(SB + t) * 32 + d0]);
            u64 x0 = pack2(hv.x, hv.y), x1 = pack2(hv.z, hv.w);
#pragma unroll
            for (int j = 0; j < 4; j++) {
                ga[j][t] = fma2(x0, w[j][0], ga[j][t]);
                ga[j][t] = fma2(x1, w[j][1], ga[j][t]);
            }
        }
    }
    // ---- GELU + stage to g2 ----
#pragma unroll
    for (int j = 0; j < 4; j++)
#pragma unroll
        for (int t = 0; t < SN; t++) {
            float a, b; unpack2(ga[j][t], a, b);
            g2u[t * 128 + lane + 32 * j] = pack2(gelu1(a), gelu1(b));
        }
    __syncwarp();

    // ---- FFN2: 128 -> 32 ----
    u64 o2[SN];
    {
        u64 b = dup2(W[O_B2 + lane]);
#pragma unroll
        for (int t = 0; t < SN; t++) o2[t] = b;
    }
    for (int f0 = 0; f0 < 128; f0 += 2) {
        u64 w0 = dup2(W[O_W2 + f0 * W2_STR + lane]);
        u64 w1 = dup2(W[O_W2 + (f0 + 1) * W2_STR + lane]);
#pragma unroll
        for (int t = 0; t < SN; t++) {
            float4 gv = *reinterpret_cast<const float4*>(&g2[t * 128 + f0]);
            o2[t] = fma2(pack2(gv.x, gv.y), w0, o2[t]);
            o2[t] = fma2(pack2(gv.z, gv.w), w1, o2[t]);
        }
    }
    // ---- residual + LN_B ----
    u64 lg = dup2(W[O_LNBG + lane]), lb = dup2(W[O_LNBB + lane]);
#pragma unroll
    for (int t = 0; t < SN; t++) {
        u64 v = add2(o2[t], h2u[(SB + t) * 32 + lane]);
        u64 sum = v, sq = mul2(v, v);
#pragma unroll
        for (int mk = 16; mk; mk >>= 1) {
            sum = add2(sum, shflx2(sum, mk));
            sq  = add2(sq,  shflx2(sq,  mk));
        }
        float s0, s1, q0, q1, v0, v1;
        unpack2(sum, s0, s1); unpack2(sq, q0, q1); unpack2(v, v0, v1);
        float mu0 = s0 * 0.03125f, mu1 = s1 * 0.03125f;
        float r0 = rsqrtf(fmaf(-mu0, mu0, q0 * 0.03125f) + 1e-5f);
        float r1 = rsqrtf(fmaf(-mu1, mu1, q1 * 0.03125f) + 1e-5f);
        h2u[(SB + t) * 32 + lane] = fma2(pack2((v0 - mu0) * r0, (v1 - mu1) * r1), lg, lb);
    }
    __syncwarp();
}

// One transformer block for a packed batch-pair.
__device__ __noinline__ void block_pair(int hoff, int goff, int woff, int lane)
{
    float2* h2 = reinterpret_cast<float2*>(&smem[hoff]);
    float2* g2 = reinterpret_cast<float2*>(&smem[goff]);
    const float* W = &smem[woff];
    u64* h2u = reinterpret_cast<u64*>(h2);
    u64* ctx = reinterpret_cast<u64*>(g2);   // [qi][32] float2 staging

    // ---------------- QKV projection ----------------
    u64 qa[S], ka[S], va[S];
    {
        u64 bq = dup2(W[O_QKVB + lane]);
        u64 bk = dup2(W[O_QKVB + 32 + lane]);
        u64 bv = dup2(W[O_QKVB + 64 + lane]);
#pragma unroll
        for (int s = 0; s < S; s++) { qa[s] = bq; ka[s] = bk; va[s] = bv; }
    }
    for (int d0 = 0; d0 < 32; d0 += 2) {
        const float* wr0 = &W[O_QKVW + d0 * QKVW_STR];
        const float* wr1 = wr0 + QKVW_STR;
        u64 wq0 = dup2(wr0[lane]), wk0 = dup2(wr0[32 + lane]), wv0 = dup2(wr0[64 + lane]);
        u64 wq1 = dup2(wr1[lane]), wk1 = dup2(wr1[32 + lane]), wv1 = dup2(wr1[64 + lane]);
#pragma unroll
        for (int s = 0; s < S; s++) {
            float4 hv = *reinterpret_cast<const float4*>(&h2[s * 32 + d0]);
            u64 x0 = pack2(hv.x, hv.y), x1 = pack2(hv.z, hv.w);
            qa[s] = fma2(x0, wq0, qa[s]); qa[s] = fma2(x1, wq1, qa[s]);
            ka[s] = fma2(x0, wk0, ka[s]); ka[s] = fma2(x1, wk1, ka[s]);
            va[s] = fma2(x0, wv0, va[s]); va[s] = fma2(x1, wv1, va[s]);
        }
    }
    {
        u64 scl = dup2(0.35355339059327373f);   // 1/sqrt(8)
#pragma unroll
        for (int s = 0; s < S; s++) qa[s] = mul2(qa[s], scl);
    }

    // ---------------- attention (4 heads x 8 dims; lane = global dim) -------
#pragma unroll
    for (int qi = 0; qi < S; qi++) {
        float e0[S], e1[S];
#pragma unroll
        for (int ki = 0; ki < S; ki++) {
            u64 p = mul2(qa[qi], ka[ki]);
            p = add2(p, shflx2(p, 1));
            p = add2(p, shflx2(p, 2));
            p = add2(p, shflx2(p, 4));      // head-local dot, both batches
            unpack2(p, e0[ki], e1[ki]);
        }
        float m0 = e0[0], m1 = e1[0];
#pragma unroll
        for (int ki = 1; ki < S; ki++) { m0 = fmaxf(m0, e0[ki]); m1 = fmaxf(m1, e1[ki]); }
        float den0 = 0.f, den1 = 0.f;
#pragma unroll
        for (int ki = 0; ki < S; ki++) {
            e0[ki] = __expf(e0[ki] - m0); den0 += e0[ki];
            e1[ki] = __expf(e1[ki] - m1); den1 += e1[ki];
        }
        u64 c = pack2(0.f, 0.f);
#pragma unroll
        for (int ki = 0; ki < S; ki++) c = fma2(pack2(e0[ki], e1[ki]), va[ki], c);
        c = mul2(c, pack2(1.0f / den0, 1.0f / den1));
        ctx[qi * 32 + lane] = c;
    }
    __syncwarp();

    // ---------------- output projection ----------------
    u64 o[S];
    {
        u64 bo = dup2(W[O_OUTB + lane]);
#pragma unroll
        for (int s = 0; s < S; s++) o[s] = bo;
    }
    for (int d0 = 0; d0 < 32; d0 += 2) {
        u64 w0 = dup2(W[O_OUTW + d0 * OUTW_STR + lane]);
        u64 w1 = dup2(W[O_OUTW + (d0 + 1) * OUTW_STR + lane]);
#pragma unroll
        for (int s = 0; s < S; s++) {
            float4 cv = *reinterpret_cast<const float4*>(&g2[s * 32 + d0]);
            o[s] = fma2(pack2(cv.x, cv.y), w0, o[s]);
            o[s] = fma2(pack2(cv.z, cv.w), w1, o[s]);
        }
    }
    // ---------------- residual + LN_A ----------------
    {
        u64 lg = dup2(W[O_LNAG + lane]), lb = dup2(W[O_LNAB + lane]);
#pragma unroll
        for (int s = 0; s < S; s++) {
            u64 v = add2(o[s], h2u[s * 32 + lane]);
            u64 sum = v, sq = mul2(v, v);
#pragma unroll
            for (int mk = 16; mk; mk >>= 1) {
                sum = add2(sum, shflx2(sum, mk));
                sq  = add2(sq,  shflx2(sq,  mk));
            }
            float s0, s1, q0, q1, v0, v1;
            unpack2(sum, s0, s1); unpack2(sq, q0, q1); unpack2(v, v0, v1);
            float mu0 = s0 * 0.03125f, mu1 = s1 * 0.03125f;
            float r0 = rsqrtf(fmaf(-mu0, mu0, q0 * 0.03125f) + 1e-5f);
            float r1 = rsqrtf(fmaf(-mu1, mu1, q1 * 0.03125f) + 1e-5f);
            h2u[s * 32 + lane] = fma2(pack2((v0 - mu0) * r0, (v1 - mu1) * r1), lg, lb);
        }
    }
    __syncwarp();

    // ---------------- FFN in two token-halves (smem/register budget) --------
    ffn_pass<0, 6>(h2, g2, W, lane);
    ffn_pass<6, 5>(h2, g2, W, lane);
}

__global__ void __launch_bounds__(THREADS)
tab_transformer_kernel(KParams p)
{
    const int tid = threadIdx.x;

    // ================== stage weights into shared (conflict-free) ==========
    for (int i = tid; i < 320; i += THREADS) smem[O_WFEAT + i] = p.in[1][i];
    for (int i = tid; i < 320; i += THREADS) smem[O_BFEAT + i] = p.in[2][i];
    if (tid < 32) {
        smem[O_CLS  + tid] = p.in[3][tid];
        smem[O_CLFW + tid] = p.in[28][tid];
    }
    if (tid == 0) smem[O_CLFB] = p.in[29][0];

#pragma unroll
    for (int blk = 0; blk < 2; blk++) {
        float* W = &smem[blk ? O_BLK1 : O_BLK0];
        const float* const* q = &p.in[4 + blk * 12];
        for (int i = tid; i < 3072; i += THREADS) {           // [96][32] -> [32][97]
            int e = i >> 5, d = i & 31;
            W[O_QKVW + d * QKVW_STR + e] = q[0][i];
        }
        for (int i = tid; i < 96; i += THREADS) W[O_QKVB + i] = q[1][i];
        for (int i = tid; i < 1024; i += THREADS) {           // [32][32] -> [32][33]
            int e = i >> 5, d = i & 31;
            W[O_OUTW + d * OUTW_STR + e] = q[2][i];
        }
        if (tid < 32) {
            W[O_OUTB + tid] = q[3][tid];
            W[O_LNAG + tid] = q[4][tid];
            W[O_LNAB + tid] = q[5][tid];
        }
        for (int i = tid; i < 4096; i += THREADS) {           // [128][32] -> [32][129]
            int f = i >> 5, d = i & 31;
            W[O_W1 + d * W1_STR + f] = q[6][i];
        }
        for (int i = tid; i < 128; i += THREADS) W[O_B1 + i] = q[7][i];
        for (int i = tid; i < 4096; i += THREADS) {           // [32][128] -> [128][33]
            int d = i >> 7, f = i & 127;
            W[O_W2 + f * W2_STR + d] = q[8][i];
        }
        if (tid < 32) {
            W[O_B2   + tid] = q[9][tid];
            W[O_LNBG + tid] = q[10][tid];
            W[O_LNBB + tid] = q[11][tid];
        }
    }
    __syncthreads();

    const int warp = tid >> 5, lane = tid & 31;
    const int pr = blockIdx.x * NW + warp;
    if (pr >= NPAIR) return;
    const int b0 = pr * 2;

    const int hoff = O_ACT + warp * ACT_F;
    const int goff = hoff + H2_F;
    u64* h2u = reinterpret_cast<u64*>(&smem[hoff]);

    // ================== embedding: cls + per-feature Linear(1,32) ==========
    float xv0 = (lane < 10) ? p.in[0][(size_t)b0 * 10 + lane] : 0.f;
    float xv1 = (lane < 10) ? p.in[0][(size_t)(b0 + 1) * 10 + lane] : 0.f;
    h2u[lane] = dup2(smem[O_CLS + lane]);
#pragma unroll
    for (int i = 0; i < 10; i++) {
        float a = __shfl_sync(0xffffffffu, xv0, i);
        float b = __shfl_sync(0xffffffffu, xv1, i);
        u64 w  = dup2(smem[O_WFEAT + i * 32 + lane]);
        u64 bb = dup2(smem[O_BFEAT + i * 32 + lane]);
        h2u[(i + 1) * 32 + lane] = fma2(pack2(a, b), w, bb);
    }
    __syncwarp();

    block_pair(hoff, goff, O_BLK0, lane);
    block_pair(hoff, goff, O_BLK1, lane);

    // ================== classifier on cls token ============================
    u64 v = mul2(h2u[lane], dup2(smem[O_CLFW + lane]));
#pragma unroll
    for (int mk = 16; mk; mk >>= 1) v = add2(v, shflx2(v, mk));
    if (lane == 0) {
        float r0, r1; unpack2(v, r0, r1);
        float cb = smem[O_CLFB];
        *reinterpret_cast<float2*>(&p.out[b0]) = make_float2(r0 + cb, r1 + cb);
    }
}

extern "C" void kernel_launch(void* const* d_in, const int* in_sizes, int n_in,
                              void* d_out, int out_size)
{
    (void)in_sizes; (void)n_in; (void)out_size;
    KParams p;
    for (int i = 0; i < 30; i++) p.in[i] = (const float*)d_in[i];
    p.out = (float*)d_out;

    cudaFuncSetAttribute(tab_transformer_kernel,
                         cudaFuncAttributeMaxDynamicSharedMemorySize, SMEM_BYTES);

    const int grid = (NPAIR + NW - 1) / NW;   // 5462
    tab_transformer_kernel<<<grid, THREADS, SMEM_BYTES>>>(p);
}

// round 4
// speedup vs baseline: 1.3351x; 1.1193x over previous
#include <cuda_runtime.h>

// Fused 2-block tiny-transformer, 131072 sequences. One warp = TWO batches
// packed as f32x2. Attention computed shuffle-free: q/k/v staged to shared,
// lane = (query, head) computes scores/softmax/ctx locally. LayerNorm uses
// shfl_xor butterfly on packed f32x2 (redux.f32 not available on sm_103).

namespace {
constexpr int S  = 11;
constexpr int NW = 12;
constexpr int THREADS = NW * 32;
constexpr int BTOT = 131072;
constexpr int NPAIR = BTOT / 2;

// --- per-block weight sub-offsets (floats), odd strides kill STS conflicts ---
constexpr int QKVW_STR = 97;
constexpr int OUTW_STR = 33;
constexpr int W1_STR   = 129;
constexpr int W2_STR   = 33;

constexpr int O_QKVW = 0;
constexpr int O_QKVB = O_QKVW + 32 * QKVW_STR;    // 3104
constexpr int O_OUTW = O_QKVB + 96;               // 3200
constexpr int O_OUTB = O_OUTW + 32 * OUTW_STR;    // 4256
constexpr int O_LNAG = O_OUTB + 32;
constexpr int O_LNAB = O_LNAG + 32;
constexpr int O_W1   = O_LNAB + 32;               // 4352
constexpr int O_B1   = O_W1 + 32 * W1_STR;        // 8480
constexpr int O_W2   = O_B1 + 128;                // 8608
constexpr int O_B2   = O_W2 + 128 * W2_STR;       // 12832
constexpr int O_LNBG = O_B2 + 32;
constexpr int O_LNBB = O_LNBG + 32;
constexpr int BLK_SZ = O_LNBB + 32;               // 12928

// --- global smem layout (floats) ---
constexpr int O_WFEAT = 0;
constexpr int O_BFEAT = O_WFEAT + 320;
constexpr int O_CLS   = O_BFEAT + 320;
constexpr int O_CLFW  = O_CLS + 32;
constexpr int O_CLFB  = O_CLFW + 32;
constexpr int O_BLK0  = 720;
constexpr int O_BLK1  = O_BLK0 + BLK_SZ;          // 13648
constexpr int O_ACT   = O_BLK1 + BLK_SZ;          // 26576 (16B-aligned*4)

// per-warp activation region (floats)
constexpr int H2_F   = 12 * 32 * 2;               // h2 [12][32] float2 = 768
// staging region (float2 units): q[11][16], k[11][16], v[11][16], ctx[11][34]
constexpr int F2_QS  = 0;
constexpr int F2_KS  = 176;
constexpr int F2_VS  = 352;
constexpr int F2_CTX = 528;
constexpr int CTX_STR = 34;                       // f2 stride, 16B-aligned rows
constexpr int STG_F2 = 912;                       // >= 528+374, >= g2 768
constexpr int ACT_F  = H2_F + STG_F2 * 2;         // 2592 floats / warp
constexpr int SMEM_FLOATS = O_ACT + NW * ACT_F;   // 57680
constexpr int SMEM_BYTES  = SMEM_FLOATS * 4;      // 230720 (<= 232448)
}

extern __shared__ float smem[];

using u64 = unsigned long long;

static __device__ __forceinline__ u64 pack2(float x, float y) {
    u64 r; asm("mov.b64 %0,{%1,%2};" : "=l"(r) : "f"(x), "f"(y)); return r;
}
static __device__ __forceinline__ void unpack2(u64 v, float& x, float& y) {
    asm("mov.b64 {%0,%1},%2;" : "=f"(x), "=f"(y) : "l"(v));
}
static __device__ __forceinline__ u64 dup2(float x) { return pack2(x, x); }
static __device__ __forceinline__ u64 fma2(u64 a, u64 b, u64 c) {
    u64 d; asm("fma.rn.f32x2 %0,%1,%2,%3;" : "=l"(d) : "l"(a), "l"(b), "l"(c)); return d;
}
static __device__ __forceinline__ u64 add2(u64 a, u64 b) {
    u64 d; asm("add.rn.f32x2 %0,%1,%2;" : "=l"(d) : "l"(a), "l"(b)); return d;
}
static __device__ __forceinline__ u64 mul2(u64 a, u64 b) {
    u64 d; asm("mul.rn.f32x2 %0,%1,%2;" : "=l"(d) : "l"(a), "l"(b)); return d;
}
static __device__ __forceinline__ u64 shflx2(u64 v, int m) {
    float x, y; unpack2(v, x, y);
    x = __shfl_xor_sync(0xffffffffu, x, m);
    y = __shfl_xor_sync(0xffffffffu, y, m);
    return pack2(x, y);
}
static __device__ __forceinline__ float gelu1(float x) {
    return 0.5f * x * (1.0f + erff(x * 0.7071067811865475f));
}
// residual-normed value via butterfly warp reduction (mean/var over 32 lanes)
static __device__ __forceinline__ u64 ln_norm(u64 v, u64 lg, u64 lb) {
    u64 sum = v, sq = mul2(v, v);
#pragma unroll
    for (int mk = 16; mk; mk >>= 1) {
        sum = add2(sum, shflx2(sum, mk));
        sq  = add2(sq,  shflx2(sq,  mk));
    }
    float s0, s1, q0, q1, v0, v1;
    unpack2(sum, s0, s1); unpack2(sq, q0, q1); unpack2(v, v0, v1);
    float mu0 = s0 * 0.03125f, mu1 = s1 * 0.03125f;
    float r0 = rsqrtf(fmaf(-mu0, mu0, q0 * 0.03125f) + 1e-5f);
    float r1 = rsqrtf(fmaf(-mu1, mu1, q1 * 0.03125f) + 1e-5f);
    return fma2(pack2((v0 - mu0) * r0, (v1 - mu1) * r1), lg, lb);
}

struct KParams {
    const float* in[30];
    float* out;
};

// FFN over tokens [SB, SB+SN): FFN1 -> GELU (staged) -> FFN2 -> +res -> LN_B
template <int SB, int SN>
static __device__ __forceinline__ void ffn_pass(u64* h2u, u64* g2u,
                                                const float* W, int lane)
{
    const float2* g2f = reinterpret_cast<const float2*>(g2u);
    const float2* h2f = reinterpret_cast<const float2*>(h2u);

    // ---- FFN1: 32 -> 128 ----
    u64 ga[4][SN];
#pragma unroll
    for (int j = 0; j < 4; j++) {
        u64 b = dup2(W[O_B1 + lane + 32 * j]);
#pragma unroll
        for (int t = 0; t < SN; t++) ga[j][t] = b;
    }
    for (int d0 = 0; d0 < 32; d0 += 2) {
        u64 w[4][2];
#pragma unroll
        for (int j = 0; j < 4; j++) {
            w[j][0] = dup2(W[O_W1 + d0 * W1_STR + lane + 32 * j]);
            w[j][1] = dup2(W[O_W1 + (d0 + 1) * W1_STR + lane + 32 * j]);
        }
#pragma unroll
        for (int t = 0; t < SN; t++) {
            float4 hv = *reinterpret_cast<const float4*>(&h2f[(SB + t) * 32 + d0]);
            u64 x0 = pack2(hv.x, hv.y), x1 = pack2(hv.z, hv.w);
#pragma unroll
            for (int j = 0; j < 4; j++) {
                ga[j][t] = fma2(x0, w[j][0], ga[j][t]);
                ga[j][t] = fma2(x1, w[j][1], ga[j][t]);
            }
        }
    }
#pragma unroll
    for (int j = 0; j < 4; j++)
#pragma unroll
        for (int t = 0; t < SN; t++) {
            float a, b; unpack2(ga[j][t], a, b);
            g2u[t * 128 + lane + 32 * j] = pack2(gelu1(a), gelu1(b));
        }
    __syncwarp();

    // ---- FFN2: 128 -> 32 ----
    u64 o2[SN];
    {
        u64 b = dup2(W[O_B2 + lane]);
#pragma unroll
        for (int t = 0; t < SN; t++) o2[t] = b;
    }
    for (int f0 = 0; f0 < 128; f0 += 2) {
        u64 w0 = dup2(W[O_W2 + f0 * W2_STR + lane]);
        u64 w1 = dup2(W[O_W2 + (f0 + 1) * W2_STR + lane]);
#pragma unroll
        for (int t = 0; t < SN; t++) {
            float4 gv = *reinterpret_cast<const float4*>(&g2f[t * 128 + f0]);
            o2[t] = fma2(pack2(gv.x, gv.y), w0, o2[t]);
            o2[t] = fma2(pack2(gv.z, gv.w), w1, o2[t]);
        }
    }
    u64 lg = dup2(W[O_LNBG + lane]), lb = dup2(W[O_LNBB + lane]);
#pragma unroll
    for (int t = 0; t < SN; t++)
        h2u[(SB + t) * 32 + lane] = ln_norm(add2(o2[t], h2u[(SB + t) * 32 + lane]), lg, lb);
    __syncwarp();
}

// One transformer block for a packed batch-pair.
__device__ __noinline__ void block_pair(int hoff, int soff, int woff, int lane)
{
    u64* h2u = reinterpret_cast<u64*>(&smem[hoff]);
    u64* stg = reinterpret_cast<u64*>(&smem[soff]);     // staging, f2 units
    const float2* h2f = reinterpret_cast<const float2*>(h2u);
    const float2* stf = reinterpret_cast<const float2*>(stg);
    const float* W = &smem[woff];

    // ---------------- QKV projection (lane = dim) ----------------
    u64 qa[S], ka[S], va[S];
    {
        u64 bq = dup2(W[O_QKVB + lane]);
        u64 bk = dup2(W[O_QKVB + 32 + lane]);
        u64 bv = dup2(W[O_QKVB + 64 + lane]);
#pragma unroll
        for (int s = 0; s < S; s++) { qa[s] = bq; ka[s] = bk; va[s] = bv; }
    }
    for (int d0 = 0; d0 < 32; d0 += 2) {
        const float* wr0 = &W[O_QKVW + d0 * QKVW_STR];
        const float* wr1 = wr0 + QKVW_STR;
        u64 wq0 = dup2(wr0[lane]), wk0 = dup2(wr0[32 + lane]), wv0 = dup2(wr0[64 + lane]);
        u64 wq1 = dup2(wr1[lane]), wk1 = dup2(wr1[32 + lane]), wv1 = dup2(wr1[64 + lane]);
#pragma unroll
        for (int s = 0; s < S; s++) {
            float4 hv = *reinterpret_cast<const float4*>(&h2f[s * 32 + d0]);
            u64 x0 = pack2(hv.x, hv.y), x1 = pack2(hv.z, hv.w);
            qa[s] = fma2(x0, wq0, qa[s]); qa[s] = fma2(x1, wq1, qa[s]);
            ka[s] = fma2(x0, wk0, ka[s]); ka[s] = fma2(x1, wk1, ka[s]);
            va[s] = fma2(x0, wv0, va[s]); va[s] = fma2(x1, wv1, va[s]);
        }
    }
    {
        u64 scl = dup2(0.35355339059327373f);   // 1/sqrt(8)
#pragma unroll
        for (int s = 0; s < S; s++) qa[s] = mul2(qa[s], scl);
    }

    // ---------------- attention: two head-pair passes, shuffle-free ---------
    const int qi = (lane >> 1) > 10 ? 10 : (lane >> 1);  // clamped map
    const int hl = lane & 1;                             // local head in pass
    const int hb = hl * 8;                               // f2 offset in slice
#pragma unroll
    for (int p = 0; p < 2; p++) {
        // stage this pass's 16 dims of q/k/v (lanes owning those dims)
        if ((lane >> 4) == p) {
            int ld = lane & 15;
#pragma unroll
            for (int s = 0; s < S; s++) {
                stg[F2_QS + s * 16 + ld] = qa[s];
                stg[F2_KS + s * 16 + ld] = ka[s];
                stg[F2_VS + s * 16 + ld] = va[s];
            }
        }
        __syncwarp();

        // lane-local q row (8 dims of its head)
        u64 qr[8];
#pragma unroll
        for (int j = 0; j < 8; j += 2) {
            float4 t = *reinterpret_cast<const float4*>(&stf[F2_QS + qi * 16 + hb + j]);
            qr[j] = pack2(t.x, t.y); qr[j + 1] = pack2(t.z, t.w);
        }
        // scores
        float e0[S], e1[S];
#pragma unroll
        for (int ki = 0; ki < S; ki++) {
            u64 acc = pack2(0.f, 0.f);
#pragma unroll
            for (int j = 0; j < 8; j += 2) {
                float4 kv = *reinterpret_cast<const float4*>(&stf[F2_KS + ki * 16 + hb + j]);
                acc = fma2(qr[j],     pack2(kv.x, kv.y), acc);
                acc = fma2(qr[j + 1], pack2(kv.z, kv.w), acc);
            }
            unpack2(acc, e0[ki], e1[ki]);
        }
        // softmax (lane-local)
        float m0 = e0[0], m1 = e1[0];
#pragma unroll
        for (int ki = 1; ki < S; ki++) { m0 = fmaxf(m0, e0[ki]); m1 = fmaxf(m1, e1[ki]); }
        float den0 = 0.f, den1 = 0.f;
#pragma unroll
        for (int ki = 0; ki < S; ki++) {
            e0[ki] = __expf(e0[ki] - m0); den0 += e0[ki];
            e1[ki] = __expf(e1[ki] - m1); den1 += e1[ki];
        }
        // ctx = attn @ v (lane-local over 8 dims)
        u64 cacc[8];
#pragma unroll
        for (int j = 0; j < 8; j++) cacc[j] = pack2(0.f, 0.f);
#pragma unroll
        for (int ki = 0; ki < S; ki++) {
            u64 ev = pack2(e0[ki], e1[ki]);
#pragma unroll
            for (int j = 0; j < 8; j += 2) {
                float4 vv = *reinterpret_cast<const float4*>(&stf[F2_VS + ki * 16 + hb + j]);
                cacc[j]     = fma2(ev, pack2(vv.x, vv.y), cacc[j]);
                cacc[j + 1] = fma2(ev, pack2(vv.z, vv.w), cacc[j + 1]);
            }
        }
        if (lane < 22) {
            u64 inv = pack2(1.0f / den0, 1.0f / den1);
            int cb = F2_CTX + qi * CTX_STR + (p * 2 + hl) * 8;
#pragma unroll
            for (int j = 0; j < 8; j++) stg[cb + j] = mul2(cacc[j], inv);
        }
        __syncwarp();
    }

    // ---------------- output projection + residual + LN_A -------------------
    u64 o[S];
    {
        u64 bo = dup2(W[O_OUTB + lane]);
#pragma unroll
        for (int s = 0; s < S; s++) o[s] = bo;
    }
    for (int d0 = 0; d0 < 32; d0 += 2) {
        u64 w0 = dup2(W[O_OUTW + d0 * OUTW_STR + lane]);
        u64 w1 = dup2(W[O_OUTW + (d0 + 1) * OUTW_STR + lane]);
#pragma unroll
        for (int s = 0; s < S; s++) {
            float4 cv = *reinterpret_cast<const float4*>(&stf[F2_CTX + s * CTX_STR + d0]);
            o[s] = fma2(pack2(cv.x, cv.y), w0, o[s]);
            o[s] = fma2(pack2(cv.z, cv.w), w1, o[s]);
        }
    }
    {
        u64 lg = dup2(W[O_LNAG + lane]), lb = dup2(W[O_LNAB + lane]);
#pragma unroll
        for (int s = 0; s < S; s++)
            h2u[s * 32 + lane] = ln_norm(add2(o[s], h2u[s * 32 + lane]), lg, lb);
    }
    __syncwarp();

    // ---------------- FFN in two token-halves (smem budget) -----------------
    ffn_pass<0, 6>(h2u, stg, W, lane);
    ffn_pass<6, 5>(h2u, stg, W, lane);
}

__global__ void __launch_bounds__(THREADS)
tab_transformer_kernel(KParams p)
{
    const int tid = threadIdx.x;

    // ================== stage weights into shared (conflict-free) ==========
    for (int i = tid; i < 320; i += THREADS) smem[O_WFEAT + i] = p.in[1][i];
    for (int i = tid; i < 320; i += THREADS) smem[O_BFEAT + i] = p.in[2][i];
    if (tid < 32) {
        smem[O_CLS  + tid] = p.in[3][tid];
        smem[O_CLFW + tid] = p.in[28][tid];
    }
    if (tid == 0) smem[O_CLFB] = p.in[29][0];

#pragma unroll
    for (int blk = 0; blk < 2; blk++) {
        float* W = &smem[blk ? O_BLK1 : O_BLK0];
        const float* const* q = &p.in[4 + blk * 12];
        for (int i = tid; i < 3072; i += THREADS) {           // [96][32] -> [32][97]
            int e = i >> 5, d = i & 31;
            W[O_QKVW + d * QKVW_STR + e] = q[0][i];
        }
        for (int i = tid; i < 96; i += THREADS) W[O_QKVB + i] = q[1][i];
        for (int i = tid; i < 1024; i += THREADS) {           // [32][32] -> [32][33]
            int e = i >> 5, d = i & 31;
            W[O_OUTW + d * OUTW_STR + e] = q[2][i];
        }
        if (tid < 32) {
            W[O_OUTB + tid] = q[3][tid];
            W[O_LNAG + tid] = q[4][tid];
            W[O_LNAB + tid] = q[5][tid];
        }
        for (int i = tid; i < 4096; i += THREADS) {           // [128][32] -> [32][129]
            int f = i >> 5, d = i & 31;
            W[O_W1 + d * W1_STR + f] = q[6][i];
        }
        for (int i = tid; i < 128; i += THREADS) W[O_B1 + i] = q[7][i];
        for (int i = tid; i < 4096; i += THREADS) {           // [32][128] -> [128][33]
            int d = i >> 7, f = i & 127;
            W[O_W2 + f * W2_STR + d] = q[8][i];
        }
        if (tid < 32) {
            W[O_B2   + tid] = q[9][tid];
            W[O_LNBG + tid] = q[10][tid];
            W[O_LNBB + tid] = q[11][tid];
        }
    }
    __syncthreads();

    const int warp = tid >> 5, lane = tid & 31;
    const int pr = blockIdx.x * NW + warp;
    if (pr >= NPAIR) return;
    const int b0 = pr * 2;

    const int hoff = O_ACT + warp * ACT_F;
    const int soff = hoff + H2_F;
    u64* h2u = reinterpret_cast<u64*>(&smem[hoff]);

    // ================== embedding ==========================================
    float xv0 = (lane < 10) ? p.in[0][(size_t)b0 * 10 + lane] : 0.f;
    float xv1 = (lane < 10) ? p.in[0][(size_t)(b0 + 1) * 10 + lane] : 0.f;
    h2u[lane] = dup2(smem[O_CLS + lane]);
#pragma unroll
    for (int i = 0; i < 10; i++) {
        float a = __shfl_sync(0xffffffffu, xv0, i);
        float b = __shfl_sync(0xffffffffu, xv1, i);
        u64 w  = dup2(smem[O_WFEAT + i * 32 + lane]);
        u64 bb = dup2(smem[O_BFEAT + i * 32 + lane]);
        h2u[(i + 1) * 32 + lane] = fma2(pack2(a, b), w, bb);
    }
    __syncwarp();

    block_pair(hoff, soff, O_BLK0, lane);
    block_pair(hoff, soff, O_BLK1, lane);

    // ================== classifier on cls token ============================
    u64 v = mul2(h2u[lane], dup2(smem[O_CLFW + lane]));
#pragma unroll
    for (int mk = 16; mk; mk >>= 1) v = add2(v, shflx2(v, mk));
    if (lane == 0) {
        float r0, r1; unpack2(v, r0, r1);
        float cb = smem[O_CLFB];
        *reinterpret_cast<float2*>(&p.out[b0]) = make_float2(r0 + cb, r1 + cb);
    }
}

extern "C" void kernel_launch(void* const* d_in, const int* in_sizes, int n_in,
                              void* d_out, int out_size)
{
    (void)in_sizes; (void)n_in; (void)out_size;
    KParams p;
    for (int i = 0; i < 30; i++) p.in[i] = (const float*)d_in[i];
    p.out = (float*)d_out;

    cudaFuncSetAttribute(tab_transformer_kernel,
                         cudaFuncAttributeMaxDynamicSharedMemorySize, SMEM_BYTES);

    const int grid = (NPAIR + NW - 1) / NW;   // 5462
    tab_transformer_kernel<<<grid, THREADS, SMEM_BYTES>>>(p);
}

// round 5
// speedup vs baseline: 1.3461x; 1.0082x over previous
#include <cuda_runtime.h>

// Fused 2-block tiny-transformer, 131072 sequences. One warp = TWO batches
// packed as f32x2. Shuffle-free attention via shared staging; LN via shfl
// butterfly. Weights staged ONE BLOCK AT A TIME (re-staged between blocks)
// to halve weight smem and fit 15 warps/CTA (occupancy 12 -> 15 warps/SM).

namespace {
constexpr int S  = 11;
constexpr int NW = 15;
constexpr int THREADS = NW * 32;                  // 480
constexpr int BTOT = 131072;
constexpr int NPAIR = BTOT / 2;                   // 65536

// --- per-block weight sub-offsets (floats), odd strides kill STS conflicts ---
constexpr int QKVW_STR = 97;
constexpr int OUTW_STR = 33;
constexpr int W1_STR   = 129;
constexpr int W2_STR   = 33;

constexpr int O_QKVW = 0;
constexpr int O_QKVB = O_QKVW + 32 * QKVW_STR;    // 3104
constexpr int O_OUTW = O_QKVB + 96;               // 3200
constexpr int O_OUTB = O_OUTW + 32 * OUTW_STR;    // 4256
constexpr int O_LNAG = O_OUTB + 32;
constexpr int O_LNAB = O_LNAG + 32;
constexpr int O_W1   = O_LNAB + 32;               // 4352
constexpr int O_B1   = O_W1 + 32 * W1_STR;        // 8480
constexpr int O_W2   = O_B1 + 128;                // 8608
constexpr int O_B2   = O_W2 + 128 * W2_STR;       // 12832
constexpr int O_LNBG = O_B2 + 32;
constexpr int O_LNBB = O_LNBG + 32;
constexpr int BLK_SZ = O_LNBB + 32;               // 12928

// --- global smem layout (floats) ---
constexpr int O_WFEAT = 0;
constexpr int O_BFEAT = O_WFEAT + 320;
constexpr int O_CLS   = O_BFEAT + 320;
constexpr int O_CLFW  = O_CLS + 32;
constexpr int O_CLFB  = O_CLFW + 32;
constexpr int O_BLKW  = 720;                      // single staged weight block
constexpr int O_ACT   = O_BLKW + BLK_SZ;          // 13648

// per-warp activation region (floats)
constexpr int H2_F   = 12 * 32 * 2;               // h2 [12][32] float2 = 768
// staging region (float2 units): q[11][16], k[11][16], v[11][16], ctx[11][34]
constexpr int F2_QS  = 0;
constexpr int F2_KS  = 176;
constexpr int F2_VS  = 352;
constexpr int F2_CTX = 528;
constexpr int CTX_STR = 34;                       // f2 stride, 16B-aligned rows
constexpr int STG_F2 = 912;                       // >= 528+374, >= g2 768
constexpr int ACT_F  = H2_F + STG_F2 * 2;         // 2592 floats / warp
constexpr int SMEM_FLOATS = O_ACT + NW * ACT_F;   // 52528
constexpr int SMEM_BYTES  = SMEM_FLOATS * 4;      // 210112 (<= 232448)
}

extern __shared__ float smem[];

using u64 = unsigned long long;

static __device__ __forceinline__ u64 pack2(float x, float y) {
    u64 r; asm("mov.b64 %0,{%1,%2};" : "=l"(r) : "f"(x), "f"(y)); return r;
}
static __device__ __forceinline__ void unpack2(u64 v, float& x, float& y) {
    asm("mov.b64 {%0,%1},%2;" : "=f"(x), "=f"(y) : "l"(v));
}
static __device__ __forceinline__ u64 dup2(float x) { return pack2(x, x); }
static __device__ __forceinline__ u64 fma2(u64 a, u64 b, u64 c) {
    u64 d; asm("fma.rn.f32x2 %0,%1,%2,%3;" : "=l"(d) : "l"(a), "l"(b), "l"(c)); return d;
}
static __device__ __forceinline__ u64 add2(u64 a, u64 b) {
    u64 d; asm("add.rn.f32x2 %0,%1,%2;" : "=l"(d) : "l"(a), "l"(b)); return d;
}
static __device__ __forceinline__ u64 mul2(u64 a, u64 b) {
    u64 d; asm("mul.rn.f32x2 %0,%1,%2;" : "=l"(d) : "l"(a), "l"(b)); return d;
}
static __device__ __forceinline__ u64 shflx2(u64 v, int m) {
    float x, y; unpack2(v, x, y);
    x = __shfl_xor_sync(0xffffffffu, x, m);
    y = __shfl_xor_sync(0xffffffffu, y, m);
    return pack2(x, y);
}
static __device__ __forceinline__ float gelu1(float x) {
    return 0.5f * x * (1.0f + erff(x * 0.7071067811865475f));
}
// residual-normed value via butterfly warp reduction (mean/var over 32 lanes)
static __device__ __forceinline__ u64 ln_norm(u64 v, u64 lg, u64 lb) {
    u64 sum = v, sq = mul2(v, v);
#pragma unroll
    for (int mk = 16; mk; mk >>= 1) {
        sum = add2(sum, shflx2(sum, mk));
        sq  = add2(sq,  shflx2(sq,  mk));
    }
    float s0, s1, q0, q1, v0, v1;
    unpack2(sum, s0, s1); unpack2(sq, q0, q1); unpack2(v, v0, v1);
    float mu0 = s0 * 0.03125f, mu1 = s1 * 0.03125f;
    float r0 = rsqrtf(fmaf(-mu0, mu0, q0 * 0.03125f) + 1e-5f);
    float r1 = rsqrtf(fmaf(-mu1, mu1, q1 * 0.03125f) + 1e-5f);
    return fma2(pack2((v0 - mu0) * r0, (v1 - mu1) * r1), lg, lb);
}

struct KParams {
    const float* in[30];
    float* out;
};

// Stage one block's weights into shared (transposed, odd strides).
static __device__ __forceinline__ void stage_block(float* W, const float* const* q,
                                                   int tid)
{
    // q: in_w, in_b, out_w, out_b, lnag, lnab, w1, b1, w2, b2, lnbg, lnbb
    for (int i4 = tid; i4 < 768; i4 += THREADS) {         // [96][32] -> [32][97]
        float4 v = reinterpret_cast<const float4*>(q[0])[i4];
        int i = i4 * 4, e = i >> 5, d = i & 31;
        float* base = &W[O_QKVW + e];
        base[(d + 0) * QKVW_STR] = v.x; base[(d + 1) * QKVW_STR] = v.y;
        base[(d + 2) * QKVW_STR] = v.z; base[(d + 3) * QKVW_STR] = v.w;
    }
    for (int i = tid; i < 96; i += THREADS) W[O_QKVB + i] = q[1][i];
    for (int i4 = tid; i4 < 256; i4 += THREADS) {         // [32][32] -> [32][33]
        float4 v = reinterpret_cast<const float4*>(q[2])[i4];
        int i = i4 * 4, e = i >> 5, d = i & 31;
        float* base = &W[O_OUTW + e];
        base[(d + 0) * OUTW_STR] = v.x; base[(d + 1) * OUTW_STR] = v.y;
        base[(d + 2) * OUTW_STR] = v.z; base[(d + 3) * OUTW_STR] = v.w;
    }
    if (tid < 32) {
        W[O_OUTB + tid] = q[3][tid];
        W[O_LNAG + tid] = q[4][tid];
        W[O_LNAB + tid] = q[5][tid];
    }
    for (int i4 = tid; i4 < 1024; i4 += THREADS) {        // [128][32] -> [32][129]
        float4 v = reinterpret_cast<const float4*>(q[6])[i4];
        int i = i4 * 4, f = i >> 5, d = i & 31;
        float* base = &W[O_W1 + f];
        base[(d + 0) * W1_STR] = v.x; base[(d + 1) * W1_STR] = v.y;
        base[(d + 2) * W1_STR] = v.z; base[(d + 3) * W1_STR] = v.w;
    }
    for (int i = tid; i < 128; i += THREADS) W[O_B1 + i] = q[7][i];
    for (int i4 = tid; i4 < 1024; i4 += THREADS) {        // [32][128] -> [128][33]
        float4 v = reinterpret_cast<const float4*>(q[8])[i4];
        int i = i4 * 4, d = i >> 7, f = i & 127;
        float* base = &W[O_W2 + d];
        base[(f + 0) * W2_STR] = v.x; base[(f + 1) * W2_STR] = v.y;
        base[(f + 2) * W2_STR] = v.z; base[(f + 3) * W2_STR] = v.w;
    }
    if (tid < 32) {
        W[O_B2   + tid] = q[9][tid];
        W[O_LNBG + tid] = q[10][tid];
        W[O_LNBB + tid] = q[11][tid];
    }
}

// FFN over tokens [SB, SB+SN): FFN1 -> GELU (staged) -> FFN2 -> +res -> LN_B
template <int SB, int SN>
static __device__ __forceinline__ void ffn_pass(u64* h2u, u64* g2u,
                                                const float* W, int lane)
{
    const float2* g2f = reinterpret_cast<const float2*>(g2u);
    const float2* h2f = reinterpret_cast<const float2*>(h2u);

    // ---- FFN1: 32 -> 128 ----
    u64 ga[4][SN];
#pragma unroll
    for (int j = 0; j < 4; j++) {
        u64 b = dup2(W[O_B1 + lane + 32 * j]);
#pragma unroll
        for (int t = 0; t < SN; t++) ga[j][t] = b;
    }
    for (int d0 = 0; d0 < 32; d0 += 2) {
        u64 w[4][2];
#pragma unroll
        for (int j = 0; j < 4; j++) {
            w[j][0] = dup2(W[O_W1 + d0 * W1_STR + lane + 32 * j]);
            w[j][1] = dup2(W[O_W1 + (d0 + 1) * W1_STR + lane + 32 * j]);
        }
#pragma unroll
        for (int t = 0; t < SN; t++) {
            float4 hv = *reinterpret_cast<const float4*>(&h2f[(SB + t) * 32 + d0]);
            u64 x0 = pack2(hv.x, hv.y), x1 = pack2(hv.z, hv.w);
#pragma unroll
            for (int j = 0; j < 4; j++) {
                ga[j][t] = fma2(x0, w[j][0], ga[j][t]);
                ga[j][t] = fma2(x1, w[j][1], ga[j][t]);
            }
        }
    }
#pragma unroll
    for (int j = 0; j < 4; j++)
#pragma unroll
        for (int t = 0; t < SN; t++) {
            float a, b; unpack2(ga[j][t], a, b);
            g2u[t * 128 + lane + 32 * j] = pack2(gelu1(a), gelu1(b));
        }
    __syncwarp();

    // ---- FFN2: 128 -> 32 ----
    u64 o2[SN];
    {
        u64 b = dup2(W[O_B2 + lane]);
#pragma unroll
        for (int t = 0; t < SN; t++) o2[t] = b;
    }
    for (int f0 = 0; f0 < 128; f0 += 2) {
        u64 w0 = dup2(W[O_W2 + f0 * W2_STR + lane]);
        u64 w1 = dup2(W[O_W2 + (f0 + 1) * W2_STR + lane]);
#pragma unroll
        for (int t = 0; t < SN; t++) {
            float4 gv = *reinterpret_cast<const float4*>(&g2f[t * 128 + f0]);
            o2[t] = fma2(pack2(gv.x, gv.y), w0, o2[t]);
            o2[t] = fma2(pack2(gv.z, gv.w), w1, o2[t]);
        }
    }
    u64 lg = dup2(W[O_LNBG + lane]), lb = dup2(W[O_LNBB + lane]);
#pragma unroll
    for (int t = 0; t < SN; t++)
        h2u[(SB + t) * 32 + lane] = ln_norm(add2(o2[t], h2u[(SB + t) * 32 + lane]), lg, lb);
    __syncwarp();
}

// One transformer block for a packed batch-pair.
__device__ __noinline__ void block_pair(int hoff, int soff, int lane)
{
    u64* h2u = reinterpret_cast<u64*>(&smem[hoff]);
    u64* stg = reinterpret_cast<u64*>(&smem[soff]);     // staging, f2 units
    const float2* h2f = reinterpret_cast<const float2*>(h2u);
    const float2* stf = reinterpret_cast<const float2*>(stg);
    const float* W = &smem[O_BLKW];

    // ---------------- QKV projection (lane = dim) ----------------
    u64 qa[S], ka[S], va[S];
    {
        u64 bq = dup2(W[O_QKVB + lane]);
        u64 bk = dup2(W[O_QKVB + 32 + lane]);
        u64 bv = dup2(W[O_QKVB + 64 + lane]);
#pragma unroll
        for (int s = 0; s < S; s++) { qa[s] = bq; ka[s] = bk; va[s] = bv; }
    }
    for (int d0 = 0; d0 < 32; d0 += 2) {
        const float* wr0 = &W[O_QKVW + d0 * QKVW_STR];
        const float* wr1 = wr0 + QKVW_STR;
        u64 wq0 = dup2(wr0[lane]), wk0 = dup2(wr0[32 + lane]), wv0 = dup2(wr0[64 + lane]);
        u64 wq1 = dup2(wr1[lane]), wk1 = dup2(wr1[32 + lane]), wv1 = dup2(wr1[64 + lane]);
#pragma unroll
        for (int s = 0; s < S; s++) {
            float4 hv = *reinterpret_cast<const float4*>(&h2f[s * 32 + d0]);
            u64 x0 = pack2(hv.x, hv.y), x1 = pack2(hv.z, hv.w);
            qa[s] = fma2(x0, wq0, qa[s]); qa[s] = fma2(x1, wq1, qa[s]);
            ka[s] = fma2(x0, wk0, ka[s]); ka[s] = fma2(x1, wk1, ka[s]);
            va[s] = fma2(x0, wv0, va[s]); va[s] = fma2(x1, wv1, va[s]);
        }
    }
    {
        u64 scl = dup2(0.35355339059327373f);   // 1/sqrt(8)
#pragma unroll
        for (int s = 0; s < S; s++) qa[s] = mul2(qa[s], scl);
    }

    // ---------------- attention: two head-pair passes, shuffle-free ---------
    const int qi = (lane >> 1) > 10 ? 10 : (lane >> 1);  // clamped map
    const int hl = lane & 1;                             // local head in pass
    const int hb = hl * 8;                               // f2 offset in slice
#pragma unroll
    for (int p = 0; p < 2; p++) {
        // stage this pass's 16 dims of q/k/v (lanes owning those dims)
        if ((lane >> 4) == p) {
            int ld = lane & 15;
#pragma unroll
            for (int s = 0; s < S; s++) {
                stg[F2_QS + s * 16 + ld] = qa[s];
                stg[F2_KS + s * 16 + ld] = ka[s];
                stg[F2_VS + s * 16 + ld] = va[s];
            }
        }
        __syncwarp();

        // lane-local q row (8 dims of its head)
        u64 qr[8];
#pragma unroll
        for (int j = 0; j < 8; j += 2) {
            float4 t = *reinterpret_cast<const float4*>(&stf[F2_QS + qi * 16 + hb + j]);
            qr[j] = pack2(t.x, t.y); qr[j + 1] = pack2(t.z, t.w);
        }
        // scores
        float e0[S], e1[S];
#pragma unroll
        for (int ki = 0; ki < S; ki++) {
            u64 acc = pack2(0.f, 0.f);
#pragma unroll
            for (int j = 0; j < 8; j += 2) {
                float4 kv = *reinterpret_cast<const float4*>(&stf[F2_KS + ki * 16 + hb + j]);
                acc = fma2(qr[j],     pack2(kv.x, kv.y), acc);
                acc = fma2(qr[j + 1], pack2(kv.z, kv.w), acc);
            }
            unpack2(acc, e0[ki], e1[ki]);
        }
        // softmax (lane-local)
        float m0 = e0[0], m1 = e1[0];
#pragma unroll
        for (int ki = 1; ki < S; ki++) { m0 = fmaxf(m0, e0[ki]); m1 = fmaxf(m1, e1[ki]); }
        float den0 = 0.f, den1 = 0.f;
#pragma unroll
        for (int ki = 0; ki < S; ki++) {
            e0[ki] = __expf(e0[ki] - m0); den0 += e0[ki];
            e1[ki] = __expf(e1[ki] - m1); den1 += e1[ki];
        }
        // ctx = attn @ v (lane-local over 8 dims)
        u64 cacc[8];
#pragma unroll
        for (int j = 0; j < 8; j++) cacc[j] = pack2(0.f, 0.f);
#pragma unroll
        for (int ki = 0; ki < S; ki++) {
            u64 ev = pack2(e0[ki], e1[ki]);
#pragma unroll
            for (int j = 0; j < 8; j += 2) {
                float4 vv = *reinterpret_cast<const float4*>(&stf[F2_VS + ki * 16 + hb + j]);
                cacc[j]     = fma2(ev, pack2(vv.x, vv.y), cacc[j]);
                cacc[j + 1] = fma2(ev, pack2(vv.z, vv.w), cacc[j + 1]);
            }
        }
        if (lane < 22) {
            u64 inv = pack2(1.0f / den0, 1.0f / den1);
            int cb = F2_CTX + qi * CTX_STR + (p * 2 + hl) * 8;
#pragma unroll
            for (int j = 0; j < 8; j++) stg[cb + j] = mul2(cacc[j], inv);
        }
        __syncwarp();
    }

    // ---------------- output projection + residual + LN_A -------------------
    u64 o[S];
    {
        u64 bo = dup2(W[O_OUTB + lane]);
#pragma unroll
        for (int s = 0; s < S; s++) o[s] = bo;
    }
    for (int d0 = 0; d0 < 32; d0 += 2) {
        u64 w0 = dup2(W[O_OUTW + d0 * OUTW_STR + lane]);
        u64 w1 = dup2(W[O_OUTW + (d0 + 1) * OUTW_STR + lane]);
#pragma unroll
        for (int s = 0; s < S; s++) {
            float4 cv = *reinterpret_cast<const float4*>(&stf[F2_CTX + s * CTX_STR + d0]);
            o[s] = fma2(pack2(cv.x, cv.y), w0, o[s]);
            o[s] = fma2(pack2(cv.z, cv.w), w1, o[s]);
        }
    }
    {
        u64 lg = dup2(W[O_LNAG + lane]), lb = dup2(W[O_LNAB + lane]);
#pragma unroll
        for (int s = 0; s < S; s++)
            h2u[s * 32 + lane] = ln_norm(add2(o[s], h2u[s * 32 + lane]), lg, lb);
    }
    __syncwarp();

    // ---------------- FFN in two token-halves (smem budget) -----------------
    ffn_pass<0, 6>(h2u, stg, W, lane);
    ffn_pass<6, 5>(h2u, stg, W, lane);
}

__global__ void __launch_bounds__(THREADS)
tab_transformer_kernel(KParams p)
{
    const int tid = threadIdx.x;

    // ================== stage misc + block0 weights ========================
    for (int i = tid; i < 320; i += THREADS) smem[O_WFEAT + i] = p.in[1][i];
    for (int i = tid; i < 320; i += THREADS) smem[O_BFEAT + i] = p.in[2][i];
    if (tid < 32) {
        smem[O_CLS  + tid] = p.in[3][tid];
        smem[O_CLFW + tid] = p.in[28][tid];
    }
    if (tid == 0) smem[O_CLFB] = p.in[29][0];
    stage_block(&smem[O_BLKW], &p.in[4], tid);
    __syncthreads();

    const int warp = tid >> 5, lane = tid & 31;
    int pr = blockIdx.x * NW + warp;
    const bool valid = (pr < NPAIR);
    if (!valid) pr = NPAIR - 1;                  // clamp; no early return (barriers)
    const int b0 = pr * 2;

    const int hoff = O_ACT + warp * ACT_F;
    const int soff = hoff + H2_F;
    u64* h2u = reinterpret_cast<u64*>(&smem[hoff]);

    // ================== embedding ==========================================
    float xv0 = (lane < 10) ? p.in[0][(size_t)b0 * 10 + lane] : 0.f;
    float xv1 = (lane < 10) ? p.in[0][(size_t)(b0 + 1) * 10 + lane] : 0.f;
    h2u[lane] = dup2(smem[O_CLS + lane]);
#pragma unroll
    for (int i = 0; i < 10; i++) {
        float a = __shfl_sync(0xffffffffu, xv0, i);
        float b = __shfl_sync(0xffffffffu, xv1, i);
        u64 w  = dup2(smem[O_WFEAT + i * 32 + lane]);
        u64 bb = dup2(smem[O_BFEAT + i * 32 + lane]);
        h2u[(i + 1) * 32 + lane] = fma2(pack2(a, b), w, bb);
    }
    __syncwarp();

    block_pair(hoff, soff, lane);

    // ================== swap in block1 weights =============================
    __syncthreads();
    stage_block(&smem[O_BLKW], &p.in[16], tid);
    __syncthreads();

    block_pair(hoff, soff, lane);

    // ================== classifier on cls token ============================
    u64 v = mul2(h2u[lane], dup2(smem[O_CLFW + lane]));
#pragma unroll
    for (int mk = 16; mk; mk >>= 1) v = add2(v, shflx2(v, mk));
    if (valid && lane == 0) {
        float r0, r1; unpack2(v, r0, r1);
        float cb = smem[O_CLFB];
        *reinterpret_cast<float2*>(&p.out[b0]) = make_float2(r0 + cb, r1 + cb);
    }
}

extern "C" void kernel_launch(void* const* d_in, const int* in_sizes, int n_in,
                              void* d_out, int out_size)
{
    (void)in_sizes; (void)n_in; (void)out_size;
    KParams p;
    for (int i = 0; i < 30; i++) p.in[i] = (const float*)d_in[i];
    p.out = (float*)d_out;

    cudaFuncSetAttribute(tab_transformer_kernel,
                         cudaFuncAttributeMaxDynamicSharedMemorySize, SMEM_BYTES);

    const int grid = (NPAIR + NW - 1) / NW;   // 4370
    tab_transformer_kernel<<<grid, THREADS, SMEM_BYTES>>>(p);
}

// round 6
// speedup vs baseline: 1.3518x; 1.0043x over previous
#include <cuda_runtime.h>

// Fused 2-block tiny-transformer, 131072 sequences. One warp = TWO batches
// packed as f32x2. Shuffle-free attention; LN via shfl butterfly. Weights
// staged one block at a time in OUTPUT-MAJOR rows (stride % 32 == 4) so each
// lane loads 4 input-dim weights with one LDS.128 (conflict-free).

namespace {
constexpr int S  = 11;
constexpr int NW = 15;
constexpr int THREADS = NW * 32;                  // 480
constexpr int BTOT = 131072;
constexpr int NPAIR = BTOT / 2;                   // 65536

// --- per-block weight layout (floats), output-major rows, stride%32==4 ------
constexpr int QKVW_STR = 36;                      // [96 out][36] cols 0..31
constexpr int OUTW_STR = 36;                      // [32 out][36]
constexpr int W1_STR   = 36;                      // [128 out][36]
constexpr int W2_STR   = 132;                     // [32 out][132] cols 0..127

constexpr int O_QKVW = 0;                         // 96*36 = 3456
constexpr int O_QKVB = O_QKVW + 96 * QKVW_STR;    // 3456 (96)
constexpr int O_OUTW = O_QKVB + 96;               // 3552 (32*36 = 1152)
constexpr int O_OUTB = O_OUTW + 32 * OUTW_STR;    // 4704 (32)
constexpr int O_LNAG = O_OUTB + 32;               // 4736
constexpr int O_LNAB = O_LNAG + 32;               // 4768
constexpr int O_W1   = O_LNAB + 32;               // 4800 (128*36 = 4608)
constexpr int O_B1   = O_W1 + 128 * W1_STR;       // 9408 (128)
constexpr int O_W2   = O_B1 + 128;                // 9536 (32*132 = 4224)
constexpr int O_B2   = O_W2 + 32 * W2_STR;        // 13760 (32)
constexpr int O_LNBG = O_B2 + 32;                 // 13792
constexpr int O_LNBB = O_LNBG + 32;               // 13824
constexpr int BLK_SZ = O_LNBB + 32;               // 13856

// --- global smem layout (floats) ---
constexpr int O_WFEAT = 0;
constexpr int O_BFEAT = O_WFEAT + 320;
constexpr int O_CLS   = O_BFEAT + 320;
constexpr int O_CLFW  = O_CLS + 32;
constexpr int O_CLFB  = O_CLFW + 32;
constexpr int O_BLKW  = 720;                      // single staged weight block
constexpr int O_ACT   = O_BLKW + BLK_SZ;          // 14576 (16B-aligned*4)

// per-warp activation region (floats)
constexpr int H2_F   = 12 * 32 * 2;               // h2 [12][32] float2 = 768
// staging region (float2 units): q[11][16], k[11][16], v[11][16], ctx[11][34]
constexpr int F2_QS  = 0;
constexpr int F2_KS  = 176;
constexpr int F2_VS  = 352;
constexpr int F2_CTX = 528;
constexpr int CTX_STR = 34;                       // f2 stride, 16B-aligned rows
constexpr int STG_F2 = 912;                       // >= 528+374, >= g2 768
constexpr int ACT_F  = H2_F + STG_F2 * 2;         // 2592 floats / warp
constexpr int SMEM_FLOATS = O_ACT + NW * ACT_F;   // 53456
constexpr int SMEM_BYTES  = SMEM_FLOATS * 4;      // 213824 (<= 232448)
}

extern __shared__ float smem[];

using u64 = unsigned long long;

static __device__ __forceinline__ u64 pack2(float x, float y) {
    u64 r; asm("mov.b64 %0,{%1,%2};" : "=l"(r) : "f"(x), "f"(y)); return r;
}
static __device__ __forceinline__ void unpack2(u64 v, float& x, float& y) {
    asm("mov.b64 {%0,%1},%2;" : "=f"(x), "=f"(y) : "l"(v));
}
static __device__ __forceinline__ u64 dup2(float x) { return pack2(x, x); }
static __device__ __forceinline__ u64 fma2(u64 a, u64 b, u64 c) {
    u64 d; asm("fma.rn.f32x2 %0,%1,%2,%3;" : "=l"(d) : "l"(a), "l"(b), "l"(c)); return d;
}
static __device__ __forceinline__ u64 add2(u64 a, u64 b) {
    u64 d; asm("add.rn.f32x2 %0,%1,%2;" : "=l"(d) : "l"(a), "l"(b)); return d;
}
static __device__ __forceinline__ u64 mul2(u64 a, u64 b) {
    u64 d; asm("mul.rn.f32x2 %0,%1,%2;" : "=l"(d) : "l"(a), "l"(b)); return d;
}
static __device__ __forceinline__ u64 shflx2(u64 v, int m) {
    float x, y; unpack2(v, x, y);
    x = __shfl_xor_sync(0xffffffffu, x, m);
    y = __shfl_xor_sync(0xffffffffu, y, m);
    return pack2(x, y);
}
static __device__ __forceinline__ float gelu1(float x) {
    return 0.5f * x * (1.0f + erff(x * 0.7071067811865475f));
}
// residual-normed value via butterfly warp reduction (mean/var over 32 lanes)
static __device__ __forceinline__ u64 ln_norm(u64 v, u64 lg, u64 lb) {
    u64 sum = v, sq = mul2(v, v);
#pragma unroll
    for (int mk = 16; mk; mk >>= 1) {
        sum = add2(sum, shflx2(sum, mk));
        sq  = add2(sq,  shflx2(sq,  mk));
    }
    float s0, s1, q0, q1, v0, v1;
    unpack2(sum, s0, s1); unpack2(sq, q0, q1); unpack2(v, v0, v1);
    float mu0 = s0 * 0.03125f, mu1 = s1 * 0.03125f;
    float r0 = rsqrtf(fmaf(-mu0, mu0, q0 * 0.03125f) + 1e-5f);
    float r1 = rsqrtf(fmaf(-mu1, mu1, q1 * 0.03125f) + 1e-5f);
    return fma2(pack2((v0 - mu0) * r0, (v1 - mu1) * r1), lg, lb);
}

struct KParams {
    const float* in[30];
    float* out;
};

// Stage one block's weights: straight strided float4 copies (output-major).
static __device__ __forceinline__ void stage_block(float* W, const float* const* q,
                                                   int tid)
{
    // q: in_w, in_b, out_w, out_b, lnag, lnab, w1, b1, w2, b2, lnbg, lnbb
    for (int i4 = tid; i4 < 768; i4 += THREADS) {         // qkv [96][32]
        float4 v = reinterpret_cast<const float4*>(q[0])[i4];
        int e = i4 >> 3, c = (i4 & 7) * 4;
        *reinterpret_cast<float4*>(&W[O_QKVW + e * QKVW_STR + c]) = v;
    }
    for (int i = tid; i < 96; i += THREADS) W[O_QKVB + i] = q[1][i];
    for (int i4 = tid; i4 < 256; i4 += THREADS) {         // out_w [32][32]
        float4 v = reinterpret_cast<const float4*>(q[2])[i4];
        int e = i4 >> 3, c = (i4 & 7) * 4;
        *reinterpret_cast<float4*>(&W[O_OUTW + e * OUTW_STR + c]) = v;
    }
    if (tid < 32) {
        W[O_OUTB + tid] = q[3][tid];
        W[O_LNAG + tid] = q[4][tid];
        W[O_LNAB + tid] = q[5][tid];
    }
    for (int i4 = tid; i4 < 1024; i4 += THREADS) {        // w1 [128][32]
        float4 v = reinterpret_cast<const float4*>(q[6])[i4];
        int f = i4 >> 3, c = (i4 & 7) * 4;
        *reinterpret_cast<float4*>(&W[O_W1 + f * W1_STR + c]) = v;
    }
    for (int i = tid; i < 128; i += THREADS) W[O_B1 + i] = q[7][i];
    for (int i4 = tid; i4 < 1024; i4 += THREADS) {        // w2 [32][128]
        float4 v = reinterpret_cast<const float4*>(q[8])[i4];
        int d = i4 >> 5, c = (i4 & 31) * 4;
        *reinterpret_cast<float4*>(&W[O_W2 + d * W2_STR + c]) = v;
    }
    if (tid < 32) {
        W[O_B2   + tid] = q[9][tid];
        W[O_LNBG + tid] = q[10][tid];
        W[O_LNBB + tid] = q[11][tid];
    }
}

// FFN over tokens [SB, SB+SN): FFN1 -> GELU (staged) -> FFN2 -> +res -> LN_B
template <int SB, int SN>
static __device__ __forceinline__ void ffn_pass(u64* h2u, u64* g2u,
                                                const float* W, int lane)
{
    const float2* g2f = reinterpret_cast<const float2*>(g2u);
    const float2* h2f = reinterpret_cast<const float2*>(h2u);

    // ---- FFN1: 32 -> 128 (weights: one LDS.128 = 4 input dims per row) ----
    u64 ga[4][SN];
#pragma unroll
    for (int j = 0; j < 4; j++) {
        u64 b = dup2(W[O_B1 + lane + 32 * j]);
#pragma unroll
        for (int t = 0; t < SN; t++) ga[j][t] = b;
    }
    for (int d0 = 0; d0 < 32; d0 += 4) {
        u64 w[4][4];
#pragma unroll
        for (int j = 0; j < 4; j++) {
            float4 f = *reinterpret_cast<const float4*>(
                &W[O_W1 + (lane + 32 * j) * W1_STR + d0]);
            w[j][0] = dup2(f.x); w[j][1] = dup2(f.y);
            w[j][2] = dup2(f.z); w[j][3] = dup2(f.w);
        }
#pragma unroll
        for (int t = 0; t < SN; t++) {
            float4 a = *reinterpret_cast<const float4*>(&h2f[(SB + t) * 32 + d0]);
            float4 b = *reinterpret_cast<const float4*>(&h2f[(SB + t) * 32 + d0 + 2]);
            u64 x[4] = {pack2(a.x, a.y), pack2(a.z, a.w),
                        pack2(b.x, b.y), pack2(b.z, b.w)};
#pragma unroll
            for (int j = 0; j < 4; j++)
#pragma unroll
                for (int m = 0; m < 4; m++)
                    ga[j][t] = fma2(x[m], w[j][m], ga[j][t]);
        }
    }
#pragma unroll
    for (int j = 0; j < 4; j++)
#pragma unroll
        for (int t = 0; t < SN; t++) {
            float a, b; unpack2(ga[j][t], a, b);
            g2u[t * 128 + lane + 32 * j] = pack2(gelu1(a), gelu1(b));
        }
    __syncwarp();

    // ---- FFN2: 128 -> 32 (weights: one LDS.128 = 4 f dims) ----
    u64 o2[SN];
    {
        u64 b = dup2(W[O_B2 + lane]);
#pragma unroll
        for (int t = 0; t < SN; t++) o2[t] = b;
    }
    for (int f0 = 0; f0 < 128; f0 += 4) {
        float4 fw = *reinterpret_cast<const float4*>(&W[O_W2 + lane * W2_STR + f0]);
        u64 w0 = dup2(fw.x), w1 = dup2(fw.y), w2 = dup2(fw.z), w3 = dup2(fw.w);
#pragma unroll
        for (int t = 0; t < SN; t++) {
            float4 a = *reinterpret_cast<const float4*>(&g2f[t * 128 + f0]);
            float4 b = *reinterpret_cast<const float4*>(&g2f[t * 128 + f0 + 2]);
            o2[t] = fma2(pack2(a.x, a.y), w0, o2[t]);
            o2[t] = fma2(pack2(a.z, a.w), w1, o2[t]);
            o2[t] = fma2(pack2(b.x, b.y), w2, o2[t]);
            o2[t] = fma2(pack2(b.z, b.w), w3, o2[t]);
        }
    }
    u64 lg = dup2(W[O_LNBG + lane]), lb = dup2(W[O_LNBB + lane]);
#pragma unroll
    for (int t = 0; t < SN; t++)
        h2u[(SB + t) * 32 + lane] = ln_norm(add2(o2[t], h2u[(SB + t) * 32 + lane]), lg, lb);
    __syncwarp();
}

// One transformer block for a packed batch-pair.
__device__ __noinline__ void block_pair(int hoff, int soff, int lane)
{
    u64* h2u = reinterpret_cast<u64*>(&smem[hoff]);
    u64* stg = reinterpret_cast<u64*>(&smem[soff]);     // staging, f2 units
    const float2* h2f = reinterpret_cast<const float2*>(h2u);
    const float2* stf = reinterpret_cast<const float2*>(stg);
    const float* W = &smem[O_BLKW];

    // ---------------- QKV projection (lane = output dim) ----------------
    u64 qa[S], ka[S], va[S];
    {
        u64 bq = dup2(W[O_QKVB + lane]);
        u64 bk = dup2(W[O_QKVB + 32 + lane]);
        u64 bv = dup2(W[O_QKVB + 64 + lane]);
#pragma unroll
        for (int s = 0; s < S; s++) { qa[s] = bq; ka[s] = bk; va[s] = bv; }
    }
    for (int d0 = 0; d0 < 32; d0 += 4) {
        float4 fq = *reinterpret_cast<const float4*>(&W[O_QKVW + lane * QKVW_STR + d0]);
        float4 fk = *reinterpret_cast<const float4*>(&W[O_QKVW + (lane + 32) * QKVW_STR + d0]);
        float4 fv = *reinterpret_cast<const float4*>(&W[O_QKVW + (lane + 64) * QKVW_STR + d0]);
        u64 wq[4] = {dup2(fq.x), dup2(fq.y), dup2(fq.z), dup2(fq.w)};
        u64 wk[4] = {dup2(fk.x), dup2(fk.y), dup2(fk.z), dup2(fk.w)};
        u64 wv[4] = {dup2(fv.x), dup2(fv.y), dup2(fv.z), dup2(fv.w)};
#pragma unroll
        for (int s = 0; s < S; s++) {
            float4 a = *reinterpret_cast<const float4*>(&h2f[s * 32 + d0]);
            float4 b = *reinterpret_cast<const float4*>(&h2f[s * 32 + d0 + 2]);
            u64 x[4] = {pack2(a.x, a.y), pack2(a.z, a.w),
                        pack2(b.x, b.y), pack2(b.z, b.w)};
#pragma unroll
            for (int j = 0; j < 4; j++) {
                qa[s] = fma2(x[j], wq[j], qa[s]);
                ka[s] = fma2(x[j], wk[j], ka[s]);
                va[s] = fma2(x[j], wv[j], va[s]);
            }
        }
    }
    {
        u64 scl = dup2(0.35355339059327373f);   // 1/sqrt(8)
#pragma unroll
        for (int s = 0; s < S; s++) qa[s] = mul2(qa[s], scl);
    }

    // ---------------- attention: two head-pair passes, shuffle-free ---------
    const int qi = (lane >> 1) > 10 ? 10 : (lane >> 1);  // clamped map
    const int hl = lane & 1;                             // local head in pass
    const int hb = hl * 8;                               // f2 offset in slice
#pragma unroll
    for (int p = 0; p < 2; p++) {
        // stage this pass's 16 dims of q/k/v (lanes owning those dims)
        if ((lane >> 4) == p) {
            int ld = lane & 15;
#pragma unroll
            for (int s = 0; s < S; s++) {
                stg[F2_QS + s * 16 + ld] = qa[s];
                stg[F2_KS + s * 16 + ld] = ka[s];
                stg[F2_VS + s * 16 + ld] = va[s];
            }
        }
        __syncwarp();

        // lane-local q row (8 dims of its head)
        u64 qr[8];
#pragma unroll
        for (int j = 0; j < 8; j += 2) {
            float4 t = *reinterpret_cast<const float4*>(&stf[F2_QS + qi * 16 + hb + j]);
            qr[j] = pack2(t.x, t.y); qr[j + 1] = pack2(t.z, t.w);
        }
        // scores
        float e0[S], e1[S];
#pragma unroll
        for (int ki = 0; ki < S; ki++) {
            u64 acc = pack2(0.f, 0.f);
#pragma unroll
            for (int j = 0; j < 8; j += 2) {
                float4 kv = *reinterpret_cast<const float4*>(&stf[F2_KS + ki * 16 + hb + j]);
                acc = fma2(qr[j],     pack2(kv.x, kv.y), acc);
                acc = fma2(qr[j + 1], pack2(kv.z, kv.w), acc);
            }
            unpack2(acc, e0[ki], e1[ki]);
        }
        // softmax (lane-local)
        float m0 = e0[0], m1 = e1[0];
#pragma unroll
        for (int ki = 1; ki < S; ki++) { m0 = fmaxf(m0, e0[ki]); m1 = fmaxf(m1, e1[ki]); }
        float den0 = 0.f, den1 = 0.f;
#pragma unroll
        for (int ki = 0; ki < S; ki++) {
            e0[ki] = __expf(e0[ki] - m0); den0 += e0[ki];
            e1[ki] = __expf(e1[ki] - m1); den1 += e1[ki];
        }
        // ctx = attn @ v (lane-local over 8 dims)
        u64 cacc[8];
#pragma unroll
        for (int j = 0; j < 8; j++) cacc[j] = pack2(0.f, 0.f);
#pragma unroll
        for (int ki = 0; ki < S; ki++) {
            u64 ev = pack2(e0[ki], e1[ki]);
#pragma unroll
            for (int j = 0; j < 8; j += 2) {
                float4 vv = *reinterpret_cast<const float4*>(&stf[F2_VS + ki * 16 + hb + j]);
                cacc[j]     = fma2(ev, pack2(vv.x, vv.y), cacc[j]);
                cacc[j + 1] = fma2(ev, pack2(vv.z, vv.w), cacc[j + 1]);
            }
        }
        if (lane < 22) {
            u64 inv = pack2(1.0f / den0, 1.0f / den1);
            int cb = F2_CTX + qi * CTX_STR + (p * 2 + hl) * 8;
#pragma unroll
            for (int j = 0; j < 8; j++) stg[cb + j] = mul2(cacc[j], inv);
        }
        __syncwarp();
    }

    // ---------------- output projection + residual + LN_A -------------------
    u64 o[S];
    {
        u64 bo = dup2(W[O_OUTB + lane]);
#pragma unroll
        for (int s = 0; s < S; s++) o[s] = bo;
    }
    for (int d0 = 0; d0 < 32; d0 += 4) {
        float4 fw = *reinterpret_cast<const float4*>(&W[O_OUTW + lane * OUTW_STR + d0]);
        u64 w0 = dup2(fw.x), w1 = dup2(fw.y), w2 = dup2(fw.z), w3 = dup2(fw.w);
#pragma unroll
        for (int s = 0; s < S; s++) {
            float4 c0 = *reinterpret_cast<const float4*>(&stf[F2_CTX + s * CTX_STR + d0]);
            float4 c1 = *reinterpret_cast<const float4*>(&stf[F2_CTX + s * CTX_STR + d0 + 2]);
            o[s] = fma2(pack2(c0.x, c0.y), w0, o[s]);
            o[s] = fma2(pack2(c0.z, c0.w), w1, o[s]);
            o[s] = fma2(pack2(c1.x, c1.y), w2, o[s]);
            o[s] = fma2(pack2(c1.z, c1.w), w3, o[s]);
        }
    }
    {
        u64 lg = dup2(W[O_LNAG + lane]), lb = dup2(W[O_LNAB + lane]);
#pragma unroll
        for (int s = 0; s < S; s++)
            h2u[s * 32 + lane] = ln_norm(add2(o[s], h2u[s * 32 + lane]), lg, lb);
    }
    __syncwarp();

    // ---------------- FFN in two token-halves (register budget) -------------
    ffn_pass<0, 6>(h2u, stg, W, lane);
    ffn_pass<6, 5>(h2u, stg, W, lane);
}

__global__ void __launch_bounds__(THREADS)
tab_transformer_kernel(KParams p)
{
    const int tid = threadIdx.x;

    // ================== stage misc + block0 weights ========================
    for (int i = tid; i < 320; i += THREADS) smem[O_WFEAT + i] = p.in[1][i];
    for (int i = tid; i < 320; i += THREADS) smem[O_BFEAT + i] = p.in[2][i];
    if (tid < 32) {
        smem[O_CLS  + tid] = p.in[3][tid];
        smem[O_CLFW + tid] = p.in[28][tid];
    }
    if (tid == 0) smem[O_CLFB] = p.in[29][0];
    stage_block(&smem[O_BLKW], &p.in[4], tid);
    __syncthreads();

    const int warp = tid >> 5, lane = tid & 31;
    int pr = blockIdx.x * NW + warp;
    const bool valid = (pr < NPAIR);
    if (!valid) pr = NPAIR - 1;                  // clamp; no early return (barriers)
    const int b0 = pr * 2;

    const int hoff = O_ACT + warp * ACT_F;
    const int soff = hoff + H2_F;
    u64* h2u = reinterpret_cast<u64*>(&smem[hoff]);

    // ================== embedding ==========================================
    float xv0 = (lane < 10) ? p.in[0][(size_t)b0 * 10 + lane] : 0.f;
    float xv1 = (lane < 10) ? p.in[0][(size_t)(b0 + 1) * 10 + lane] : 0.f;
    h2u[lane] = dup2(smem[O_CLS + lane]);
#pragma unroll
    for (int i = 0; i < 10; i++) {
        float a = __shfl_sync(0xffffffffu, xv0, i);
        float b = __shfl_sync(0xffffffffu, xv1, i);
        u64 w  = dup2(smem[O_WFEAT + i * 32 + lane]);
        u64 bb = dup2(smem[O_BFEAT + i * 32 + lane]);
        h2u[(i + 1) * 32 + lane] = fma2(pack2(a, b), w, bb);
    }
    __syncwarp();

    block_pair(hoff, soff, lane);

    // ================== swap in block1 weights =============================
    __syncthreads();
    stage_block(&smem[O_BLKW], &p.in[16], tid);
    __syncthreads();

    block_pair(hoff, soff, lane);

    // ================== classifier on cls token ============================
    u64 v = mul2(h2u[lane], dup2(smem[O_CLFW + lane]));
#pragma unroll
    for (int mk = 16; mk; mk >>= 1) v = add2(v, shflx2(v, mk));
    if (valid && lane == 0) {
        float r0, r1; unpack2(v, r0, r1);
        float cb = smem[O_CLFB];
        *reinterpret_cast<float2*>(&p.out[b0]) = make_float2(r0 + cb, r1 + cb);
    }
}

extern "C" void kernel_launch(void* const* d_in, const int* in_sizes, int n_in,
                              void* d_out, int out_size)
{
    (void)in_sizes; (void)n_in; (void)out_size;
    KParams p;
    for (int i = 0; i < 30; i++) p.in[i] = (const float*)d_in[i];
    p.out = (float*)d_out;

    cudaFuncSetAttribute(tab_transformer_kernel,
                         cudaFuncAttributeMaxDynamicSharedMemorySize, SMEM_BYTES);

    const int grid = (NPAIR + NW - 1) / NW;   // 4370
    tab_transformer_kernel<<<grid, THREADS, SMEM_BYTES>>>(p);
}

// round 7
// speedup vs baseline: 1.4494x; 1.0722x over previous
#include <cuda_runtime.h>

// Fused 2-block tiny-transformer, 131072 sequences. One warp = TWO batches
// packed as f32x2. Shuffle-free attention; LayerNorm stats via staged
// per-token-lane reduction in shared (no butterflies). Weights staged one
// block at a time, output-major rows (stride % 32 == 4), LDS.128 loads.

namespace {
constexpr int S  = 11;
constexpr int NW = 16;
constexpr int THREADS = NW * 32;                  // 512
constexpr int BTOT = 131072;
constexpr int NPAIR = BTOT / 2;                   // 65536

// --- per-block weight layout (floats), output-major rows, stride%32==4 ------
constexpr int QKVW_STR = 36;                      // [96 out][36] cols 0..31
constexpr int OUTW_STR = 36;                      // [32 out][36]
constexpr int W1_STR   = 36;                      // [128 out][36]
constexpr int W2_STR   = 132;                     // [32 out][132] cols 0..127

constexpr int O_QKVW = 0;                         // 96*36 = 3456
constexpr int O_QKVB = O_QKVW + 96 * QKVW_STR;    // 3456 (96)
constexpr int O_OUTW = O_QKVB + 96;               // 3552 (32*36 = 1152)
constexpr int O_OUTB = O_OUTW + 32 * OUTW_STR;    // 4704 (32)
constexpr int O_LNAG = O_OUTB + 32;               // 4736
constexpr int O_LNAB = O_LNAG + 32;               // 4768
constexpr int O_W1   = O_LNAB + 32;               // 4800 (128*36 = 4608)
constexpr int O_B1   = O_W1 + 128 * W1_STR;       // 9408 (128)
constexpr int O_W2   = O_B1 + 128;                // 9536 (32*132 = 4224)
constexpr int O_B2   = O_W2 + 32 * W2_STR;        // 13760 (32)
constexpr int O_LNBG = O_B2 + 32;                 // 13792
constexpr int O_LNBB = O_LNBG + 32;               // 13824
constexpr int BLK_SZ = O_LNBB + 32;               // 13856

// --- global smem layout (floats) ---
constexpr int O_WFEAT = 0;
constexpr int O_BFEAT = O_WFEAT + 320;
constexpr int O_CLS   = O_BFEAT + 320;
constexpr int O_CLFW  = O_CLS + 32;
constexpr int O_CLFB  = O_CLFW + 32;
constexpr int O_BLKW  = 720;                      // single staged weight block
constexpr int O_ACT   = O_BLKW + BLK_SZ;          // 14576 (16B-aligned*4)

// per-warp activation region (floats)
constexpr int H2_F   = 12 * 32 * 2;               // h2 [12][32] float2 = 768
// staging region (float2 units): q[11][16], k[11][16], v[11][16], ctx[11][34]
// LN scratch reuses dead areas: LN_A -> ctx region, LN_B -> g2 region.
constexpr int F2_QS  = 0;
constexpr int F2_KS  = 176;
constexpr int F2_VS  = 352;
constexpr int F2_CTX = 528;
constexpr int CTX_STR = 34;                       // f2 stride (16B-aligned rows)
constexpr int LN_MU  = 374;                       // mu/sig offset within LN buf
constexpr int STG_F2 = 928;                       // >= 528+398, >= g2 768
constexpr int ACT_F  = H2_F + STG_F2 * 2;         // 2624 floats / warp
constexpr int SMEM_FLOATS = O_ACT + NW * ACT_F;   // 56560
constexpr int SMEM_BYTES  = SMEM_FLOATS * 4;      // 226240
}

extern __shared__ float smem[];

using u64 = unsigned long long;

static __device__ __forceinline__ u64 pack2(float x, float y) {
    u64 r; asm("mov.b64 %0,{%1,%2};" : "=l"(r) : "f"(x), "f"(y)); return r;
}
static __device__ __forceinline__ void unpack2(u64 v, float& x, float& y) {
    asm("mov.b64 {%0,%1},%2;" : "=f"(x), "=f"(y) : "l"(v));
}
static __device__ __forceinline__ u64 dup2(float x) { return pack2(x, x); }
static __device__ __forceinline__ u64 fma2(u64 a, u64 b, u64 c) {
    u64 d; asm("fma.rn.f32x2 %0,%1,%2,%3;" : "=l"(d) : "l"(a), "l"(b), "l"(c)); return d;
}
static __device__ __forceinline__ u64 add2(u64 a, u64 b) {
    u64 d; asm("add.rn.f32x2 %0,%1,%2;" : "=l"(d) : "l"(a), "l"(b)); return d;
}
static __device__ __forceinline__ u64 mul2(u64 a, u64 b) {
    u64 d; asm("mul.rn.f32x2 %0,%1,%2;" : "=l"(d) : "l"(a), "l"(b)); return d;
}
static __device__ __forceinline__ u64 neg2(u64 x) {
    return x ^ 0x8000000080000000ULL;             // flip both f32 signs
}
static __device__ __forceinline__ u64 shflx2(u64 v, int m) {
    float x, y; unpack2(v, x, y);
    x = __shfl_xor_sync(0xffffffffu, x, m);
    y = __shfl_xor_sync(0xffffffffu, y, m);
    return pack2(x, y);
}
static __device__ __forceinline__ float gelu1(float x) {
    return 0.5f * x * (1.0f + erff(x * 0.7071067811865475f));
}

struct KParams {
    const float* in[30];
    float* out;
};

// LayerNorm over SN tokens: v[] (residual-added, f32x2) in registers, lane=dim.
// buf: u64 scratch, rows at t*34 (stride 34 f2, 16B-aligned), mu/sig at LN_MU.
// Stats computed once per token by lane t; applied by all lanes from broadcast.
template <int SN>
static __device__ __forceinline__ void ln_apply(u64* h2u, int hbase, u64* buf,
                                                const u64* v, u64 lg, u64 lb,
                                                int lane)
{
#pragma unroll
    for (int t = 0; t < SN; t++) buf[t * 34 + lane] = v[t];
    __syncwarp();
    if (lane < SN) {
        const float2* row = reinterpret_cast<const float2*>(&buf[lane * 34]);
        u64 s = pack2(0.f, 0.f), q = pack2(0.f, 0.f);
#pragma unroll
        for (int i = 0; i < 16; i++) {
            float4 c = *reinterpret_cast<const float4*>(&row[i * 2]);
            u64 a = pack2(c.x, c.y), b = pack2(c.z, c.w);
            s = add2(s, add2(a, b));
            q = fma2(a, a, q); q = fma2(b, b, q);
        }
        float s0, s1, q0, q1;
        unpack2(s, s0, s1); unpack2(q, q0, q1);
        float mu0 = s0 * 0.03125f, mu1 = s1 * 0.03125f;
        float r0 = rsqrtf(fmaf(-mu0, mu0, q0 * 0.03125f) + 1e-5f);
        float r1 = rsqrtf(fmaf(-mu1, mu1, q1 * 0.03125f) + 1e-5f);
        *reinterpret_cast<float4*>(&buf[LN_MU + 2 * lane]) =
            make_float4(mu0, mu1, r0, r1);
    }
    __syncwarp();
#pragma unroll
    for (int t = 0; t < SN; t++) {
        float4 ms = *reinterpret_cast<const float4*>(&buf[LN_MU + 2 * t]);
        u64 mu = pack2(ms.x, ms.y), rs = pack2(ms.z, ms.w);
        u64 t1 = mul2(rs, lg);
        h2u[hbase + t * 32 + lane] = fma2(v[t], t1, add2(lb, neg2(mul2(mu, t1))));
    }
    __syncwarp();
}

// Stage one block's weights: straight strided float4 copies (output-major).
static __device__ __forceinline__ void stage_block(float* W, const float* const* q,
                                                   int tid)
{
    // q: in_w, in_b, out_w, out_b, lnag, lnab, w1, b1, w2, b2, lnbg, lnbb
    for (int i4 = tid; i4 < 768; i4 += THREADS) {         // qkv [96][32]
        float4 v = reinterpret_cast<const float4*>(q[0])[i4];
        int e = i4 >> 3, c = (i4 & 7) * 4;
        *reinterpret_cast<float4*>(&W[O_QKVW + e * QKVW_STR + c]) = v;
    }
    for (int i = tid; i < 96; i += THREADS) W[O_QKVB + i] = q[1][i];
    for (int i4 = tid; i4 < 256; i4 += THREADS) {         // out_w [32][32]
        float4 v = reinterpret_cast<const float4*>(q[2])[i4];
        int e = i4 >> 3, c = (i4 & 7) * 4;
        *reinterpret_cast<float4*>(&W[O_OUTW + e * OUTW_STR + c]) = v;
    }
    if (tid < 32) {
        W[O_OUTB + tid] = q[3][tid];
        W[O_LNAG + tid] = q[4][tid];
        W[O_LNAB + tid] = q[5][tid];
    }
    for (int i4 = tid; i4 < 1024; i4 += THREADS) {        // w1 [128][32]
        float4 v = reinterpret_cast<const float4*>(q[6])[i4];
        int f = i4 >> 3, c = (i4 & 7) * 4;
        *reinterpret_cast<float4*>(&W[O_W1 + f * W1_STR + c]) = v;
    }
    for (int i = tid; i < 128; i += THREADS) W[O_B1 + i] = q[7][i];
    for (int i4 = tid; i4 < 1024; i4 += THREADS) {        // w2 [32][128]
        float4 v = reinterpret_cast<const float4*>(q[8])[i4];
        int d = i4 >> 5, c = (i4 & 31) * 4;
        *reinterpret_cast<float4*>(&W[O_W2 + d * W2_STR + c]) = v;
    }
    if (tid < 32) {
        W[O_B2   + tid] = q[9][tid];
        W[O_LNBG + tid] = q[10][tid];
        W[O_LNBB + tid] = q[11][tid];
    }
}

// FFN over tokens [SB, SB+SN): FFN1 -> GELU (staged) -> FFN2 -> +res -> LN_B
template <int SB, int SN>
static __device__ __forceinline__ void ffn_pass(u64* h2u, u64* g2u,
                                                const float* W, int lane)
{
    const float2* g2f = reinterpret_cast<const float2*>(g2u);
    const float2* h2f = reinterpret_cast<const float2*>(h2u);

    // ---- FFN1: 32 -> 128 ----
    u64 ga[4][SN];
#pragma unroll
    for (int j = 0; j < 4; j++) {
        u64 b = dup2(W[O_B1 + lane + 32 * j]);
#pragma unroll
        for (int t = 0; t < SN; t++) ga[j][t] = b;
    }
    for (int d0 = 0; d0 < 32; d0 += 4) {
        u64 w[4][4];
#pragma unroll
        for (int j = 0; j < 4; j++) {
            float4 f = *reinterpret_cast<const float4*>(
                &W[O_W1 + (lane + 32 * j) * W1_STR + d0]);
            w[j][0] = dup2(f.x); w[j][1] = dup2(f.y);
            w[j][2] = dup2(f.z); w[j][3] = dup2(f.w);
        }
#pragma unroll
        for (int t = 0; t < SN; t++) {
            float4 a = *reinterpret_cast<const float4*>(&h2f[(SB + t) * 32 + d0]);
            float4 b = *reinterpret_cast<const float4*>(&h2f[(SB + t) * 32 + d0 + 2]);
            u64 x[4] = {pack2(a.x, a.y), pack2(a.z, a.w),
                        pack2(b.x, b.y), pack2(b.z, b.w)};
#pragma unroll
            for (int j = 0; j < 4; j++)
#pragma unroll
                for (int m = 0; m < 4; m++)
                    ga[j][t] = fma2(x[m], w[j][m], ga[j][t]);
        }
    }
#pragma unroll
    for (int j = 0; j < 4; j++)
#pragma unroll
        for (int t = 0; t < SN; t++) {
            float a, b; unpack2(ga[j][t], a, b);
            g2u[t * 128 + lane + 32 * j] = pack2(gelu1(a), gelu1(b));
        }
    __syncwarp();

    // ---- FFN2: 128 -> 32 ----
    u64 o2[SN];
    {
        u64 b = dup2(W[O_B2 + lane]);
#pragma unroll
        for (int t = 0; t < SN; t++) o2[t] = b;
    }
    for (int f0 = 0; f0 < 128; f0 += 4) {
        float4 fw = *reinterpret_cast<const float4*>(&W[O_W2 + lane * W2_STR + f0]);
        u64 w0 = dup2(fw.x), w1 = dup2(fw.y), w2 = dup2(fw.z), w3 = dup2(fw.w);
#pragma unroll
        for (int t = 0; t < SN; t++) {
            float4 a = *reinterpret_cast<const float4*>(&g2f[t * 128 + f0]);
            float4 b = *reinterpret_cast<const float4*>(&g2f[t * 128 + f0 + 2]);
            o2[t] = fma2(pack2(a.x, a.y), w0, o2[t]);
            o2[t] = fma2(pack2(a.z, a.w), w1, o2[t]);
            o2[t] = fma2(pack2(b.x, b.y), w2, o2[t]);
            o2[t] = fma2(pack2(b.z, b.w), w3, o2[t]);
        }
    }
    // residual + LN_B (staged stats; scratch reuses g2 region — reads done)
#pragma unroll
    for (int t = 0; t < SN; t++)
        o2[t] = add2(o2[t], h2u[(SB + t) * 32 + lane]);
    __syncwarp();
    ln_apply<SN>(h2u, SB * 32, g2u,
                 o2, dup2(W[O_LNBG + lane]), dup2(W[O_LNBB + lane]), lane);
}

// One transformer block for a packed batch-pair.
__device__ __noinline__ void block_pair(int hoff, int soff, int lane)
{
    u64* h2u = reinterpret_cast<u64*>(&smem[hoff]);
    u64* stg = reinterpret_cast<u64*>(&smem[soff]);     // staging, f2 units
    const float2* h2f = reinterpret_cast<const float2*>(h2u);
    const float2* stf = reinterpret_cast<const float2*>(stg);
    const float* W = &smem[O_BLKW];

    // ---------------- QKV projection (lane = output dim) ----------------
    u64 qa[S], ka[S], va[S];
    {
        u64 bq = dup2(W[O_QKVB + lane]);
        u64 bk = dup2(W[O_QKVB + 32 + lane]);
        u64 bv = dup2(W[O_QKVB + 64 + lane]);
#pragma unroll
        for (int s = 0; s < S; s++) { qa[s] = bq; ka[s] = bk; va[s] = bv; }
    }
    for (int d0 = 0; d0 < 32; d0 += 4) {
        float4 fq = *reinterpret_cast<const float4*>(&W[O_QKVW + lane * QKVW_STR + d0]);
        float4 fk = *reinterpret_cast<const float4*>(&W[O_QKVW + (lane + 32) * QKVW_STR + d0]);
        float4 fv = *reinterpret_cast<const float4*>(&W[O_QKVW + (lane + 64) * QKVW_STR + d0]);
        u64 wq[4] = {dup2(fq.x), dup2(fq.y), dup2(fq.z), dup2(fq.w)};
        u64 wk[4] = {dup2(fk.x), dup2(fk.y), dup2(fk.z), dup2(fk.w)};
        u64 wv[4] = {dup2(fv.x), dup2(fv.y), dup2(fv.z), dup2(fv.w)};
#pragma unroll
        for (int s = 0; s < S; s++) {
            float4 a = *reinterpret_cast<const float4*>(&h2f[s * 32 + d0]);
            float4 b = *reinterpret_cast<const float4*>(&h2f[s * 32 + d0 + 2]);
            u64 x[4] = {pack2(a.x, a.y), pack2(a.z, a.w),
                        pack2(b.x, b.y), pack2(b.z, b.w)};
#pragma unroll
            for (int j = 0; j < 4; j++) {
                qa[s] = fma2(x[j], wq[j], qa[s]);
                ka[s] = fma2(x[j], wk[j], ka[s]);
                va[s] = fma2(x[j], wv[j], va[s]);
            }
        }
    }
    {
        u64 scl = dup2(0.35355339059327373f);   // 1/sqrt(8)
#pragma unroll
        for (int s = 0; s < S; s++) qa[s] = mul2(qa[s], scl);
    }

    // ---------------- attention: two head-pair passes, shuffle-free ---------
    const int qi = (lane >> 1) > 10 ? 10 : (lane >> 1);  // clamped map
    const int hl = lane & 1;                             // local head in pass
    const int hb = hl * 8;                               // f2 offset in slice
#pragma unroll
    for (int p = 0; p < 2; p++) {
        // stage this pass's 16 dims of q/k/v (lanes owning those dims)
        if ((lane >> 4) == p) {
            int ld = lane & 15;
#pragma unroll
            for (int s = 0; s < S; s++) {
                stg[F2_QS + s * 16 + ld] = qa[s];
                stg[F2_KS + s * 16 + ld] = ka[s];
                stg[F2_VS + s * 16 + ld] = va[s];
            }
        }
        __syncwarp();

        // lane-local q row (8 dims of its head)
        u64 qr[8];
#pragma unroll
        for (int j = 0; j < 8; j += 2) {
            float4 t = *reinterpret_cast<const float4*>(&stf[F2_QS + qi * 16 + hb + j]);
            qr[j] = pack2(t.x, t.y); qr[j + 1] = pack2(t.z, t.w);
        }
        // scores
        float e0[S], e1[S];
#pragma unroll
        for (int ki = 0; ki < S; ki++) {
            u64 acc = pack2(0.f, 0.f);
#pragma unroll
            for (int j = 0; j < 8; j += 2) {
                float4 kv = *reinterpret_cast<const float4*>(&stf[F2_KS + ki * 16 + hb + j]);
                acc = fma2(qr[j],     pack2(kv.x, kv.y), acc);
                acc = fma2(qr[j + 1], pack2(kv.z, kv.w), acc);
            }
            unpack2(acc, e0[ki], e1[ki]);
        }
        // softmax (lane-local)
        float m0 = e0[0], m1 = e1[0];
#pragma unroll
        for (int ki = 1; ki < S; ki++) { m0 = fmaxf(m0, e0[ki]); m1 = fmaxf(m1, e1[ki]); }
        float den0 = 0.f, den1 = 0.f;
#pragma unroll
        for (int ki = 0; ki < S; ki++) {
            e0[ki] = __expf(e0[ki] - m0); den0 += e0[ki];
            e1[ki] = __expf(e1[ki] - m1); den1 += e1[ki];
        }
        // ctx = attn @ v (lane-local over 8 dims)
        u64 cacc[8];
#pragma unroll
        for (int j = 0; j < 8; j++) cacc[j] = pack2(0.f, 0.f);
#pragma unroll
        for (int ki = 0; ki < S; ki++) {
            u64 ev = pack2(e0[ki], e1[ki]);
#pragma unroll
            for (int j = 0; j < 8; j += 2) {
                float4 vv = *reinterpret_cast<const float4*>(&stf[F2_VS + ki * 16 + hb + j]);
                cacc[j]     = fma2(ev, pack2(vv.x, vv.y), cacc[j]);
                cacc[j + 1] = fma2(ev, pack2(vv.z, vv.w), cacc[j + 1]);
            }
        }
        if (lane < 22) {
            u64 inv = pack2(1.0f / den0, 1.0f / den1);
            int cb = F2_CTX + qi * CTX_STR + (p * 2 + hl) * 8;
#pragma unroll
            for (int j = 0; j < 8; j++) stg[cb + j] = mul2(cacc[j], inv);
        }
        __syncwarp();
    }

    // ---------------- output projection + residual + LN_A -------------------
    u64 o[S];
    {
        u64 bo = dup2(W[O_OUTB + lane]);
#pragma unroll
        for (int s = 0; s < S; s++) o[s] = bo;
    }
    for (int d0 = 0; d0 < 32; d0 += 4) {
        float4 fw = *reinterpret_cast<const float4*>(&W[O_OUTW + lane * OUTW_STR + d0]);
        u64 w0 = dup2(fw.x), w1 = dup2(fw.y), w2 = dup2(fw.z), w3 = dup2(fw.w);
#pragma unroll
        for (int s = 0; s < S; s++) {
            float4 c0 = *reinterpret_cast<const float4*>(&stf[F2_CTX + s * CTX_STR + d0]);
            float4 c1 = *reinterpret_cast<const float4*>(&stf[F2_CTX + s * CTX_STR + d0 + 2]);
            o[s] = fma2(pack2(c0.x, c0.y), w0, o[s]);
            o[s] = fma2(pack2(c0.z, c0.w), w1, o[s]);
            o[s] = fma2(pack2(c1.x, c1.y), w2, o[s]);
            o[s] = fma2(pack2(c1.z, c1.w), w3, o[s]);
        }
    }
#pragma unroll
    for (int s = 0; s < S; s++)
        o[s] = add2(o[s], h2u[s * 32 + lane]);
    __syncwarp();
    // LN_A staged stats; scratch reuses ctx region (reads done)
    ln_apply<S>(h2u, 0, stg + F2_CTX,
                o, dup2(W[O_LNAG + lane]), dup2(W[O_LNAB + lane]), lane);

    // ---------------- FFN in two token-halves (register budget) -------------
    ffn_pass<0, 6>(h2u, stg, W, lane);
    ffn_pass<6, 5>(h2u, stg, W, lane);
}

__global__ void __launch_bounds__(THREADS)
tab_transformer_kernel(KParams p)
{
    const int tid = threadIdx.x;

    // ================== stage misc + block0 weights ========================
    for (int i = tid; i < 320; i += THREADS) smem[O_WFEAT + i] = p.in[1][i];
    for (int i = tid; i < 320; i += THREADS) smem[O_BFEAT + i] = p.in[2][i];
    if (tid < 32) {
        smem[O_CLS  + tid] = p.in[3][tid];
        smem[O_CLFW + tid] = p.in[28][tid];
    }
    if (tid == 0) smem[O_CLFB] = p.in[29][0];
    stage_block(&smem[O_BLKW], &p.in[4], tid);
    __syncthreads();

    const int warp = tid >> 5, lane = tid & 31;
    int pr = blockIdx.x * NW + warp;
    const bool valid = (pr < NPAIR);
    if (!valid) pr = NPAIR - 1;                  // clamp; no early return (barriers)
    const int b0 = pr * 2;

    const int hoff = O_ACT + warp * ACT_F;
    const int soff = hoff + H2_F;
    u64* h2u = reinterpret_cast<u64*>(&smem[hoff]);

    // ================== embedding ==========================================
    float xv0 = (lane < 10) ? p.in[0][(size_t)b0 * 10 + lane] : 0.f;
    float xv1 = (lane < 10) ? p.in[0][(size_t)(b0 + 1) * 10 + lane] : 0.f;
    h2u[lane] = dup2(smem[O_CLS + lane]);
#pragma unroll
    for (int i = 0; i < 10; i++) {
        float a = __shfl_sync(0xffffffffu, xv0, i);
        float b = __shfl_sync(0xffffffffu, xv1, i);
        u64 w  = dup2(smem[O_WFEAT + i * 32 + lane]);
        u64 bb = dup2(smem[O_BFEAT + i * 32 + lane]);
        h2u[(i + 1) * 32 + lane] = fma2(pack2(a, b), w, bb);
    }
    __syncwarp();

    block_pair(hoff, soff, lane);

    // ================== swap in block1 weights =============================
    __syncthreads();
    stage_block(&smem[O_BLKW], &p.in[16], tid);
    __syncthreads();

    block_pair(hoff, soff, lane);

    // ================== classifier on cls token ============================
    u64 v = mul2(h2u[lane], dup2(smem[O_CLFW + lane]));
#pragma unroll
    for (int mk = 16; mk; mk >>= 1) v = add2(v, shflx2(v, mk));
    if (valid && lane == 0) {
        float r0, r1; unpack2(v, r0, r1);
        float cb = smem[O_CLFB];
        *reinterpret_cast<float2*>(&p.out[b0]) = make_float2(r0 + cb, r1 + cb);
    }
}

extern "C" void kernel_launch(void* const* d_in, const int* in_sizes, int n_in,
                              void* d_out, int out_size)
{
    (void)in_sizes; (void)n_in; (void)out_size;
    KParams p;
    for (int i = 0; i < 30; i++) p.in[i] = (const float*)d_in[i];
    p.out = (float*)d_out;

    cudaFuncSetAttribute(tab_transformer_kernel,
                         cudaFuncAttributeMaxDynamicSharedMemorySize, SMEM_BYTES);

    const int grid = (NPAIR + NW - 1) / NW;   // 4096
    tab_transformer_kernel<<<grid, THREADS, SMEM_BYTES>>>(p);
}

// round 8
// speedup vs baseline: 2.2420x; 1.5469x over previous
#include <cuda_runtime.h>

// Fused 2-block tiny-transformer, 131072 sequences. One warp = TWO batches
// packed as f32x2. Block 1: full 11-token block (shuffle-free attention,
// staged-LN). Block 2: CLS-token-specialized — only K/V computed for all
// tokens; q/attention/out-proj/FFN/LNs computed for token 0 only (the
// classifier consumes only h[:,0,:]).

namespace {
constexpr int S  = 11;
constexpr int NW = 16;
constexpr int THREADS = NW * 32;                  // 512
constexpr int BTOT = 131072;
constexpr int NPAIR = BTOT / 2;                   // 65536

// --- per-block weight layout (floats), output-major rows, stride%32==4 ------
constexpr int QKVW_STR = 36;
constexpr int OUTW_STR = 36;
constexpr int W1_STR   = 36;
constexpr int W2_STR   = 132;

constexpr int O_QKVW = 0;
constexpr int O_QKVB = O_QKVW + 96 * QKVW_STR;    // 3456
constexpr int O_OUTW = O_QKVB + 96;               // 3552
constexpr int O_OUTB = O_OUTW + 32 * OUTW_STR;    // 4704
constexpr int O_LNAG = O_OUTB + 32;
constexpr int O_LNAB = O_LNAG + 32;
constexpr int O_W1   = O_LNAB + 32;               // 4800
constexpr int O_B1   = O_W1 + 128 * W1_STR;       // 9408
constexpr int O_W2   = O_B1 + 128;                // 9536
constexpr int O_B2   = O_W2 + 32 * W2_STR;        // 13760
constexpr int O_LNBG = O_B2 + 32;
constexpr int O_LNBB = O_LNBG + 32;
constexpr int BLK_SZ = O_LNBB + 32;               // 13856

// --- global smem layout (floats) ---
constexpr int O_WFEAT = 0;
constexpr int O_BFEAT = O_WFEAT + 320;
constexpr int O_CLS   = O_BFEAT + 320;
constexpr int O_CLFW  = O_CLS + 32;
constexpr int O_CLFB  = O_CLFW + 32;
constexpr int O_BLKW  = 720;
constexpr int O_ACT   = O_BLKW + BLK_SZ;          // 14576

// per-warp activation region (floats)
constexpr int H2_F   = 12 * 32 * 2;               // h2 [12][32] float2 = 768
// block1 staging (float2 units): q[11][16], k[11][16], v[11][16], ctx[11][34]
constexpr int F2_QS  = 0;
constexpr int F2_KS  = 176;
constexpr int F2_VS  = 352;
constexpr int F2_CTX = 528;
constexpr int CTX_STR = 34;
constexpr int LN_MU  = 374;                       // mu/sig offset in LN buf
// block2 staging (float2 units): q0[32], k[11][32], v[11][32], ctx[32]
constexpr int F2_Q2  = 0;
constexpr int F2_K2  = 32;
constexpr int F2_V2  = 384;
constexpr int F2_C2  = 736;
constexpr int F2_G2  = 0;                         // ffn2 g buffer (reuse)
constexpr int STG_F2 = 928;
constexpr int ACT_F  = H2_F + STG_F2 * 2;         // 2624 floats / warp
constexpr int SMEM_FLOATS = O_ACT + NW * ACT_F;   // 56560
constexpr int SMEM_BYTES  = SMEM_FLOATS * 4;      // 226240
}

extern __shared__ float smem[];

using u64 = unsigned long long;

static __device__ __forceinline__ u64 pack2(float x, float y) {
    u64 r; asm("mov.b64 %0,{%1,%2};" : "=l"(r) : "f"(x), "f"(y)); return r;
}
static __device__ __forceinline__ void unpack2(u64 v, float& x, float& y) {
    asm("mov.b64 {%0,%1},%2;" : "=f"(x), "=f"(y) : "l"(v));
}
static __device__ __forceinline__ u64 dup2(float x) { return pack2(x, x); }
static __device__ __forceinline__ u64 fma2(u64 a, u64 b, u64 c) {
    u64 d; asm("fma.rn.f32x2 %0,%1,%2,%3;" : "=l"(d) : "l"(a), "l"(b), "l"(c)); return d;
}
static __device__ __forceinline__ u64 add2(u64 a, u64 b) {
    u64 d; asm("add.rn.f32x2 %0,%1,%2;" : "=l"(d) : "l"(a), "l"(b)); return d;
}
static __device__ __forceinline__ u64 mul2(u64 a, u64 b) {
    u64 d; asm("mul.rn.f32x2 %0,%1,%2;" : "=l"(d) : "l"(a), "l"(b)); return d;
}
static __device__ __forceinline__ u64 neg2(u64 x) {
    return x ^ 0x8000000080000000ULL;
}
static __device__ __forceinline__ u64 shflx2(u64 v, int m) {
    float x, y; unpack2(v, x, y);
    x = __shfl_xor_sync(0xffffffffu, x, m);
    y = __shfl_xor_sync(0xffffffffu, y, m);
    return pack2(x, y);
}
static __device__ __forceinline__ float gelu1(float x) {
    return 0.5f * x * (1.0f + erff(x * 0.7071067811865475f));
}
// single-token LN via butterfly (used in CLS-specialized block 2)
static __device__ __forceinline__ u64 ln_norm(u64 v, u64 lg, u64 lb) {
    u64 sum = v, sq = mul2(v, v);
#pragma unroll
    for (int mk = 16; mk; mk >>= 1) {
        sum = add2(sum, shflx2(sum, mk));
        sq  = add2(sq,  shflx2(sq,  mk));
    }
    float s0, s1, q0, q1, v0, v1;
    unpack2(sum, s0, s1); unpack2(sq, q0, q1); unpack2(v, v0, v1);
    float mu0 = s0 * 0.03125f, mu1 = s1 * 0.03125f;
    float r0 = rsqrtf(fmaf(-mu0, mu0, q0 * 0.03125f) + 1e-5f);
    float r1 = rsqrtf(fmaf(-mu1, mu1, q1 * 0.03125f) + 1e-5f);
    return fma2(pack2((v0 - mu0) * r0, (v1 - mu1) * r1), lg, lb);
}

struct KParams {
    const float* in[30];
    float* out;
};

// Staged LayerNorm over SN tokens (block 1): stats by lane t, applied by all.
template <int SN>
static __device__ __forceinline__ void ln_apply(u64* h2u, int hbase, u64* buf,
                                                const u64* v, u64 lg, u64 lb,
                                                int lane)
{
#pragma unroll
    for (int t = 0; t < SN; t++) buf[t * 34 + lane] = v[t];
    __syncwarp();
    if (lane < SN) {
        const float2* row = reinterpret_cast<const float2*>(&buf[lane * 34]);
        u64 s = pack2(0.f, 0.f), q = pack2(0.f, 0.f);
#pragma unroll
        for (int i = 0; i < 16; i++) {
            float4 c = *reinterpret_cast<const float4*>(&row[i * 2]);
            u64 a = pack2(c.x, c.y), b = pack2(c.z, c.w);
            s = add2(s, add2(a, b));
            q = fma2(a, a, q); q = fma2(b, b, q);
        }
        float s0, s1, q0, q1;
        unpack2(s, s0, s1); unpack2(q, q0, q1);
        float mu0 = s0 * 0.03125f, mu1 = s1 * 0.03125f;
        float r0 = rsqrtf(fmaf(-mu0, mu0, q0 * 0.03125f) + 1e-5f);
        float r1 = rsqrtf(fmaf(-mu1, mu1, q1 * 0.03125f) + 1e-5f);
        *reinterpret_cast<float4*>(&buf[LN_MU + 2 * lane]) =
            make_float4(mu0, mu1, r0, r1);
    }
    __syncwarp();
#pragma unroll
    for (int t = 0; t < SN; t++) {
        float4 ms = *reinterpret_cast<const float4*>(&buf[LN_MU + 2 * t]);
        u64 mu = pack2(ms.x, ms.y), rs = pack2(ms.z, ms.w);
        u64 t1 = mul2(rs, lg);
        h2u[hbase + t * 32 + lane] = fma2(v[t], t1, add2(lb, neg2(mul2(mu, t1))));
    }
    __syncwarp();
}

// Stage one block's weights: straight strided float4 copies (output-major).
static __device__ __forceinline__ void stage_block(float* W, const float* const* q,
                                                   int tid)
{
    for (int i4 = tid; i4 < 768; i4 += THREADS) {         // qkv [96][32]
        float4 v = reinterpret_cast<const float4*>(q[0])[i4];
        int e = i4 >> 3, c = (i4 & 7) * 4;
        *reinterpret_cast<float4*>(&W[O_QKVW + e * QKVW_STR + c]) = v;
    }
    for (int i = tid; i < 96; i += THREADS) W[O_QKVB + i] = q[1][i];
    for (int i4 = tid; i4 < 256; i4 += THREADS) {         // out_w [32][32]
        float4 v = reinterpret_cast<const float4*>(q[2])[i4];
        int e = i4 >> 3, c = (i4 & 7) * 4;
        *reinterpret_cast<float4*>(&W[O_OUTW + e * OUTW_STR + c]) = v;
    }
    if (tid < 32) {
        W[O_OUTB + tid] = q[3][tid];
        W[O_LNAG + tid] = q[4][tid];
        W[O_LNAB + tid] = q[5][tid];
    }
    for (int i4 = tid; i4 < 1024; i4 += THREADS) {        // w1 [128][32]
        float4 v = reinterpret_cast<const float4*>(q[6])[i4];
        int f = i4 >> 3, c = (i4 & 7) * 4;
        *reinterpret_cast<float4*>(&W[O_W1 + f * W1_STR + c]) = v;
    }
    for (int i = tid; i < 128; i += THREADS) W[O_B1 + i] = q[7][i];
    for (int i4 = tid; i4 < 1024; i4 += THREADS) {        // w2 [32][128]
        float4 v = reinterpret_cast<const float4*>(q[8])[i4];
        int d = i4 >> 5, c = (i4 & 31) * 4;
        *reinterpret_cast<float4*>(&W[O_W2 + d * W2_STR + c]) = v;
    }
    if (tid < 32) {
        W[O_B2   + tid] = q[9][tid];
        W[O_LNBG + tid] = q[10][tid];
        W[O_LNBB + tid] = q[11][tid];
    }
}

// FFN over tokens [SB, SB+SN) (block 1).
template <int SB, int SN>
static __device__ __forceinline__ void ffn_pass(u64* h2u, u64* g2u,
                                                const float* W, int lane)
{
    const float2* g2f = reinterpret_cast<const float2*>(g2u);
    const float2* h2f = reinterpret_cast<const float2*>(h2u);

    u64 ga[4][SN];
#pragma unroll
    for (int j = 0; j < 4; j++) {
        u64 b = dup2(W[O_B1 + lane + 32 * j]);
#pragma unroll
        for (int t = 0; t < SN; t++) ga[j][t] = b;
    }
    for (int d0 = 0; d0 < 32; d0 += 4) {
        u64 w[4][4];
#pragma unroll
        for (int j = 0; j < 4; j++) {
            float4 f = *reinterpret_cast<const float4*>(
                &W[O_W1 + (lane + 32 * j) * W1_STR + d0]);
            w[j][0] = dup2(f.x); w[j][1] = dup2(f.y);
            w[j][2] = dup2(f.z); w[j][3] = dup2(f.w);
        }
#pragma unroll
        for (int t = 0; t < SN; t++) {
            float4 a = *reinterpret_cast<const float4*>(&h2f[(SB + t) * 32 + d0]);
            float4 b = *reinterpret_cast<const float4*>(&h2f[(SB + t) * 32 + d0 + 2]);
            u64 x[4] = {pack2(a.x, a.y), pack2(a.z, a.w),
                        pack2(b.x, b.y), pack2(b.z, b.w)};
#pragma unroll
            for (int j = 0; j < 4; j++)
#pragma unroll
                for (int m = 0; m < 4; m++)
                    ga[j][t] = fma2(x[m], w[j][m], ga[j][t]);
        }
    }
#pragma unroll
    for (int j = 0; j < 4; j++)
#pragma unroll
        for (int t = 0; t < SN; t++) {
            float a, b; unpack2(ga[j][t], a, b);
            g2u[t * 128 + lane + 32 * j] = pack2(gelu1(a), gelu1(b));
        }
    __syncwarp();

    u64 o2[SN];
    {
        u64 b = dup2(W[O_B2 + lane]);
#pragma unroll
        for (int t = 0; t < SN; t++) o2[t] = b;
    }
    for (int f0 = 0; f0 < 128; f0 += 4) {
        float4 fw = *reinterpret_cast<const float4*>(&W[O_W2 + lane * W2_STR + f0]);
        u64 w0 = dup2(fw.x), w1 = dup2(fw.y), w2 = dup2(fw.z), w3 = dup2(fw.w);
#pragma unroll
        for (int t = 0; t < SN; t++) {
            float4 a = *reinterpret_cast<const float4*>(&g2f[t * 128 + f0]);
            float4 b = *reinterpret_cast<const float4*>(&g2f[t * 128 + f0 + 2]);
            o2[t] = fma2(pack2(a.x, a.y), w0, o2[t]);
            o2[t] = fma2(pack2(a.z, a.w), w1, o2[t]);
            o2[t] = fma2(pack2(b.x, b.y), w2, o2[t]);
            o2[t] = fma2(pack2(b.z, b.w), w3, o2[t]);
        }
    }
#pragma unroll
    for (int t = 0; t < SN; t++)
        o2[t] = add2(o2[t], h2u[(SB + t) * 32 + lane]);
    __syncwarp();
    ln_apply<SN>(h2u, SB * 32, g2u,
                 o2, dup2(W[O_LNBG + lane]), dup2(W[O_LNBB + lane]), lane);
}

// Block 1: full transformer block for a packed batch-pair.
__device__ __noinline__ void block_pair(int hoff, int soff, int lane)
{
    u64* h2u = reinterpret_cast<u64*>(&smem[hoff]);
    u64* stg = reinterpret_cast<u64*>(&smem[soff]);
    const float2* h2f = reinterpret_cast<const float2*>(h2u);
    const float2* stf = reinterpret_cast<const float2*>(stg);
    const float* W = &smem[O_BLKW];

    // ---------------- QKV projection (lane = output dim) ----------------
    u64 qa[S], ka[S], va[S];
    {
        u64 bq = dup2(W[O_QKVB + lane]);
        u64 bk = dup2(W[O_QKVB + 32 + lane]);
        u64 bv = dup2(W[O_QKVB + 64 + lane]);
#pragma unroll
        for (int s = 0; s < S; s++) { qa[s] = bq; ka[s] = bk; va[s] = bv; }
    }
    for (int d0 = 0; d0 < 32; d0 += 4) {
        float4 fq = *reinterpret_cast<const float4*>(&W[O_QKVW + lane * QKVW_STR + d0]);
        float4 fk = *reinterpret_cast<const float4*>(&W[O_QKVW + (lane + 32) * QKVW_STR + d0]);
        float4 fv = *reinterpret_cast<const float4*>(&W[O_QKVW + (lane + 64) * QKVW_STR + d0]);
        u64 wq[4] = {dup2(fq.x), dup2(fq.y), dup2(fq.z), dup2(fq.w)};
        u64 wk[4] = {dup2(fk.x), dup2(fk.y), dup2(fk.z), dup2(fk.w)};
        u64 wv[4] = {dup2(fv.x), dup2(fv.y), dup2(fv.z), dup2(fv.w)};
#pragma unroll
        for (int s = 0; s < S; s++) {
            float4 a = *reinterpret_cast<const float4*>(&h2f[s * 32 + d0]);
            float4 b = *reinterpret_cast<const float4*>(&h2f[s * 32 + d0 + 2]);
            u64 x[4] = {pack2(a.x, a.y), pack2(a.z, a.w),
                        pack2(b.x, b.y), pack2(b.z, b.w)};
#pragma unroll
            for (int j = 0; j < 4; j++) {
                qa[s] = fma2(x[j], wq[j], qa[s]);
                ka[s] = fma2(x[j], wk[j], ka[s]);
                va[s] = fma2(x[j], wv[j], va[s]);
            }
        }
    }
    {
        u64 scl = dup2(0.35355339059327373f);
#pragma unroll
        for (int s = 0; s < S; s++) qa[s] = mul2(qa[s], scl);
    }

    // ---------------- attention: two head-pair passes, shuffle-free ---------
    const int qi = (lane >> 1) > 10 ? 10 : (lane >> 1);
    const int hl = lane & 1;
    const int hb = hl * 8;
#pragma unroll
    for (int p = 0; p < 2; p++) {
        if ((lane >> 4) == p) {
            int ld = lane & 15;
#pragma unroll
            for (int s = 0; s < S; s++) {
                stg[F2_QS + s * 16 + ld] = qa[s];
                stg[F2_KS + s * 16 + ld] = ka[s];
                stg[F2_VS + s * 16 + ld] = va[s];
            }
        }
        __syncwarp();

        u64 qr[8];
#pragma unroll
        for (int j = 0; j < 8; j += 2) {
            float4 t = *reinterpret_cast<const float4*>(&stf[F2_QS + qi * 16 + hb + j]);
            qr[j] = pack2(t.x, t.y); qr[j + 1] = pack2(t.z, t.w);
        }
        float e0[S], e1[S];
#pragma unroll
        for (int ki = 0; ki < S; ki++) {
            u64 acc = pack2(0.f, 0.f);
#pragma unroll
            for (int j = 0; j < 8; j += 2) {
                float4 kv = *reinterpret_cast<const float4*>(&stf[F2_KS + ki * 16 + hb + j]);
                acc = fma2(qr[j],     pack2(kv.x, kv.y), acc);
                acc = fma2(qr[j + 1], pack2(kv.z, kv.w), acc);
            }
            unpack2(acc, e0[ki], e1[ki]);
        }
        float m0 = e0[0], m1 = e1[0];
#pragma unroll
        for (int ki = 1; ki < S; ki++) { m0 = fmaxf(m0, e0[ki]); m1 = fmaxf(m1, e1[ki]); }
        float den0 = 0.f, den1 = 0.f;
#pragma unroll
        for (int ki = 0; ki < S; ki++) {
            e0[ki] = __expf(e0[ki] - m0); den0 += e0[ki];
            e1[ki] = __expf(e1[ki] - m1); den1 += e1[ki];
        }
        u64 cacc[8];
#pragma unroll
        for (int j = 0; j < 8; j++) cacc[j] = pack2(0.f, 0.f);
#pragma unroll
        for (int ki = 0; ki < S; ki++) {
            u64 ev = pack2(e0[ki], e1[ki]);
#pragma unroll
            for (int j = 0; j < 8; j += 2) {
                float4 vv = *reinterpret_cast<const float4*>(&stf[F2_VS + ki * 16 + hb + j]);
                cacc[j]     = fma2(ev, pack2(vv.x, vv.y), cacc[j]);
                cacc[j + 1] = fma2(ev, pack2(vv.z, vv.w), cacc[j + 1]);
            }
        }
        if (lane < 22) {
            u64 inv = pack2(1.0f / den0, 1.0f / den1);
            int cb = F2_CTX + qi * CTX_STR + (p * 2 + hl) * 8;
#pragma unroll
            for (int j = 0; j < 8; j++) stg[cb + j] = mul2(cacc[j], inv);
        }
        __syncwarp();
    }

    // ---------------- output projection + residual + LN_A -------------------
    u64 o[S];
    {
        u64 bo = dup2(W[O_OUTB + lane]);
#pragma unroll
        for (int s = 0; s < S; s++) o[s] = bo;
    }
    for (int d0 = 0; d0 < 32; d0 += 4) {
        float4 fw = *reinterpret_cast<const float4*>(&W[O_OUTW + lane * OUTW_STR + d0]);
        u64 w0 = dup2(fw.x), w1 = dup2(fw.y), w2 = dup2(fw.z), w3 = dup2(fw.w);
#pragma unroll
        for (int s = 0; s < S; s++) {
            float4 c0 = *reinterpret_cast<const float4*>(&stf[F2_CTX + s * CTX_STR + d0]);
            float4 c1 = *reinterpret_cast<const float4*>(&stf[F2_CTX + s * CTX_STR + d0 + 2]);
            o[s] = fma2(pack2(c0.x, c0.y), w0, o[s]);
            o[s] = fma2(pack2(c0.z, c0.w), w1, o[s]);
            o[s] = fma2(pack2(c1.x, c1.y), w2, o[s]);
            o[s] = fma2(pack2(c1.z, c1.w), w3, o[s]);
        }
    }
#pragma unroll
    for (int s = 0; s < S; s++)
        o[s] = add2(o[s], h2u[s * 32 + lane]);
    __syncwarp();
    ln_apply<S>(h2u, 0, stg + F2_CTX,
                o, dup2(W[O_LNAG + lane]), dup2(W[O_LNAB + lane]), lane);

    ffn_pass<0, 6>(h2u, stg, W, lane);
    ffn_pass<6, 5>(h2u, stg, W, lane);
}

// Block 2: CLS-specialized — K/V for all tokens, everything else token 0 only.
__device__ __noinline__ void block2_pair(int hoff, int soff, int lane)
{
    u64* h2u = reinterpret_cast<u64*>(&smem[hoff]);
    u64* stg = reinterpret_cast<u64*>(&smem[soff]);
    const float2* h2f = reinterpret_cast<const float2*>(h2u);
    const float2* stf = reinterpret_cast<const float2*>(stg);
    const float* W = &smem[O_BLKW];

    // ---------------- QKV: k,v all tokens; q token 0 only -------------------
    u64 ka[S], va[S];
    u64 q0 = dup2(W[O_QKVB + lane]);
    {
        u64 bk = dup2(W[O_QKVB + 32 + lane]);
        u64 bv = dup2(W[O_QKVB + 64 + lane]);
#pragma unroll
        for (int s = 0; s < S; s++) { ka[s] = bk; va[s] = bv; }
    }
    for (int d0 = 0; d0 < 32; d0 += 4) {
        float4 fq = *reinterpret_cast<const float4*>(&W[O_QKVW + lane * QKVW_STR + d0]);
        float4 fk = *reinterpret_cast<const float4*>(&W[O_QKVW + (lane + 32) * QKVW_STR + d0]);
        float4 fv = *reinterpret_cast<const float4*>(&W[O_QKVW + (lane + 64) * QKVW_STR + d0]);
        u64 wq[4] = {dup2(fq.x), dup2(fq.y), dup2(fq.z), dup2(fq.w)};
        u64 wk[4] = {dup2(fk.x), dup2(fk.y), dup2(fk.z), dup2(fk.w)};
        u64 wv[4] = {dup2(fv.x), dup2(fv.y), dup2(fv.z), dup2(fv.w)};
#pragma unroll
        for (int s = 0; s < S; s++) {
            float4 a = *reinterpret_cast<const float4*>(&h2f[s * 32 + d0]);
            float4 b = *reinterpret_cast<const float4*>(&h2f[s * 32 + d0 + 2]);
            u64 x[4] = {pack2(a.x, a.y), pack2(a.z, a.w),
                        pack2(b.x, b.y), pack2(b.z, b.w)};
#pragma unroll
            for (int j = 0; j < 4; j++) {
                ka[s] = fma2(x[j], wk[j], ka[s]);
                va[s] = fma2(x[j], wv[j], va[s]);
            }
            if (s == 0) {
#pragma unroll
                for (int j = 0; j < 4; j++) q0 = fma2(x[j], wq[j], q0);
            }
        }
    }
    q0 = mul2(q0, dup2(0.35355339059327373f));

    // stage q0 / K / V (lane = dim; rows stride 32 f2)
    stg[F2_Q2 + lane] = q0;
#pragma unroll
    for (int s = 0; s < S; s++) {
        stg[F2_K2 + s * 32 + lane] = ka[s];
        stg[F2_V2 + s * 32 + lane] = va[s];
    }
    __syncwarp();

    // ---------------- attention row 0: lane = dim, head = lane>>3 -----------
    const int hb2 = (lane >> 3) * 8;     // head base (f2)
    u64 qr[8];
#pragma unroll
    for (int j = 0; j < 8; j += 2) {
        float4 t = *reinterpret_cast<const float4*>(&stf[F2_Q2 + hb2 + j]);
        qr[j] = pack2(t.x, t.y); qr[j + 1] = pack2(t.z, t.w);
    }
    float e0[S], e1[S];
#pragma unroll
    for (int ki = 0; ki < S; ki++) {
        u64 acc = pack2(0.f, 0.f);
#pragma unroll
        for (int j = 0; j < 8; j += 2) {
            float4 kv = *reinterpret_cast<const float4*>(&stf[F2_K2 + ki * 32 + hb2 + j]);
            acc = fma2(qr[j],     pack2(kv.x, kv.y), acc);
            acc = fma2(qr[j + 1], pack2(kv.z, kv.w), acc);
        }
        unpack2(acc, e0[ki], e1[ki]);
    }
    float m0 = e0[0], m1 = e1[0];
#pragma unroll
    for (int ki = 1; ki < S; ki++) { m0 = fmaxf(m0, e0[ki]); m1 = fmaxf(m1, e1[ki]); }
    float den0 = 0.f, den1 = 0.f;
#pragma unroll
    for (int ki = 0; ki < S; ki++) {
        e0[ki] = __expf(e0[ki] - m0); den0 += e0[ki];
        e1[ki] = __expf(e1[ki] - m1); den1 += e1[ki];
    }
    u64 c = pack2(0.f, 0.f);
#pragma unroll
    for (int ki = 0; ki < S; ki++)
        c = fma2(pack2(e0[ki], e1[ki]), stg[F2_V2 + ki * 32 + lane], c);
    c = mul2(c, pack2(1.0f / den0, 1.0f / den1));
    __syncwarp();                        // K2/V2 reads done before C2 write
    stg[F2_C2 + lane] = c;
    __syncwarp();

    // ---------------- out-proj token 0 + residual + LN_A --------------------
    u64 o = dup2(W[O_OUTB + lane]);
    for (int d0 = 0; d0 < 32; d0 += 4) {
        float4 fw = *reinterpret_cast<const float4*>(&W[O_OUTW + lane * OUTW_STR + d0]);
        float4 c0 = *reinterpret_cast<const float4*>(&stf[F2_C2 + d0]);
        float4 c1 = *reinterpret_cast<const float4*>(&stf[F2_C2 + d0 + 2]);
        o = fma2(pack2(c0.x, c0.y), dup2(fw.x), o);
        o = fma2(pack2(c0.z, c0.w), dup2(fw.y), o);
        o = fma2(pack2(c1.x, c1.y), dup2(fw.z), o);
        o = fma2(pack2(c1.z, c1.w), dup2(fw.w), o);
    }
    o = add2(o, h2u[lane]);
    u64 hn = ln_norm(o, dup2(W[O_LNAG + lane]), dup2(W[O_LNAB + lane]));
    h2u[lane] = hn;
    __syncwarp();

    // ---------------- FFN token 0 -------------------------------------------
    u64 ga[4];
#pragma unroll
    for (int j = 0; j < 4; j++) ga[j] = dup2(W[O_B1 + lane + 32 * j]);
    for (int d0 = 0; d0 < 32; d0 += 4) {
        float4 a = *reinterpret_cast<const float4*>(&h2f[d0]);
        float4 b = *reinterpret_cast<const float4*>(&h2f[d0 + 2]);
        u64 x[4] = {pack2(a.x, a.y), pack2(a.z, a.w),
                    pack2(b.x, b.y), pack2(b.z, b.w)};
#pragma unroll
        for (int j = 0; j < 4; j++) {
            float4 f = *reinterpret_cast<const float4*>(
                &W[O_W1 + (lane + 32 * j) * W1_STR + d0]);
            ga[j] = fma2(x[0], dup2(f.x), ga[j]);
            ga[j] = fma2(x[1], dup2(f.y), ga[j]);
            ga[j] = fma2(x[2], dup2(f.z), ga[j]);
            ga[j] = fma2(x[3], dup2(f.w), ga[j]);
        }
    }
#pragma unroll
    for (int j = 0; j < 4; j++) {
        float a, b; unpack2(ga[j], a, b);
        stg[F2_G2 + lane + 32 * j] = pack2(gelu1(a), gelu1(b));
    }
    __syncwarp();

    u64 o2 = dup2(W[O_B2 + lane]);
    for (int f0 = 0; f0 < 128; f0 += 4) {
        float4 fw = *reinterpret_cast<const float4*>(&W[O_W2 + lane * W2_STR + f0]);
        float4 a = *reinterpret_cast<const float4*>(&stf[F2_G2 + f0]);
        float4 b = *reinterpret_cast<const float4*>(&stf[F2_G2 + f0 + 2]);
        o2 = fma2(pack2(a.x, a.y), dup2(fw.x), o2);
        o2 = fma2(pack2(a.z, a.w), dup2(fw.y), o2);
        o2 = fma2(pack2(b.x, b.y), dup2(fw.z), o2);
        o2 = fma2(pack2(b.z, b.w), dup2(fw.w), o2);
    }
    o2 = add2(o2, hn);
    h2u[lane] = ln_norm(o2, dup2(W[O_LNBG + lane]), dup2(W[O_LNBB + lane]));
    __syncwarp();
}

__global__ void __launch_bounds__(THREADS)
tab_transformer_kernel(KParams p)
{
    const int tid = threadIdx.x;

    for (int i = tid; i < 320; i += THREADS) smem[O_WFEAT + i] = p.in[1][i];
    for (int i = tid; i < 320; i += THREADS) smem[O_BFEAT + i] = p.in[2][i];
    if (tid < 32) {
        smem[O_CLS  + tid] = p.in[3][tid];
        smem[O_CLFW + tid] = p.in[28][tid];
    }
    if (tid == 0) smem[O_CLFB] = p.in[29][0];
    stage_block(&smem[O_BLKW], &p.in[4], tid);
    __syncthreads();

    const int warp = tid >> 5, lane = tid & 31;
    int pr = blockIdx.x * NW + warp;
    const bool valid = (pr < NPAIR);
    if (!valid) pr = NPAIR - 1;
    const int b0 = pr * 2;

    const int hoff = O_ACT + warp * ACT_F;
    const int soff = hoff + H2_F;
    u64* h2u = reinterpret_cast<u64*>(&smem[hoff]);

    float xv0 = (lane < 10) ? p.in[0][(size_t)b0 * 10 + lane] : 0.f;
    float xv1 = (lane < 10) ? p.in[0][(size_t)(b0 + 1) * 10 + lane] : 0.f;
    h2u[lane] = dup2(smem[O_CLS + lane]);
#pragma unroll
    for (int i = 0; i < 10; i++) {
        float a = __shfl_sync(0xffffffffu, xv0, i);
        float b = __shfl_sync(0xffffffffu, xv1, i);
        u64 w  = dup2(smem[O_WFEAT + i * 32 + lane]);
        u64 bb = dup2(smem[O_BFEAT + i * 32 + lane]);
        h2u[(i + 1) * 32 + lane] = fma2(pack2(a, b), w, bb);
    }
    __syncwarp();

    block_pair(hoff, soff, lane);

    __syncthreads();
    stage_block(&smem[O_BLKW], &p.in[16], tid);
    __syncthreads();

    block2_pair(hoff, soff, lane);

    u64 v = mul2(h2u[lane], dup2(smem[O_CLFW + lane]));
#pragma unroll
    for (int mk = 16; mk; mk >>= 1) v = add2(v, shflx2(v, mk));
    if (valid && lane == 0) {
        float r0, r1; unpack2(v, r0, r1);
        float cb = smem[O_CLFB];
        *reinterpret_cast<float2*>(&p.out[b0]) = make_float2(r0 + cb, r1 + cb);
    }
}

extern "C" void kernel_launch(void* const* d_in, const int* in_sizes, int n_in,
                              void* d_out, int out_size)
{
    (void)in_sizes; (void)n_in; (void)out_size;
    KParams p;
    for (int i = 0; i < 30; i++) p.in[i] = (const float*)d_in[i];
    p.out = (float*)d_out;

    cudaFuncSetAttribute(tab_transformer_kernel,
                         cudaFuncAttributeMaxDynamicSharedMemorySize, SMEM_BYTES);

    const int grid = (NPAIR + NW - 1) / NW;   // 4096
    tab_transformer_kernel<<<grid, THREADS, SMEM_BYTES>>>(p);
}

// round 9
// speedup vs baseline: 2.2511x; 1.0040x over previous
#include <cuda_runtime.h>

// Fused 2-block tiny-transformer, 131072 sequences. One warp = TWO batches
// packed as f32x2. Block 1: full 11-token block (shuffle-free attention,
// staged-LN). Block 2: CLS-token-specialized — only K/V computed for all
// tokens; q/attention/out-proj/FFN/LNs computed for token 0 only (the
// classifier consumes only h[:,0,:]).

namespace {
constexpr int S  = 11;
constexpr int NW = 16;
constexpr int THREADS = NW * 32;                  // 512
constexpr int BTOT = 131072;
constexpr int NPAIR = BTOT / 2;                   // 65536

// --- per-block weight layout (floats), output-major rows, stride%32==4 ------
constexpr int QKVW_STR = 36;
constexpr int OUTW_STR = 36;
constexpr int W1_STR   = 36;
constexpr int W2_STR   = 132;

constexpr int O_QKVW = 0;
constexpr int O_QKVB = O_QKVW + 96 * QKVW_STR;    // 3456
constexpr int O_OUTW = O_QKVB + 96;               // 3552
constexpr int O_OUTB = O_OUTW + 32 * OUTW_STR;    // 4704
constexpr int O_LNAG = O_OUTB + 32;
constexpr int O_LNAB = O_LNAG + 32;
constexpr int O_W1   = O_LNAB + 32;               // 4800
constexpr int O_B1   = O_W1 + 128 * W1_STR;       // 9408
constexpr int O_W2   = O_B1 + 128;                // 9536
constexpr int O_B2   = O_W2 + 32 * W2_STR;        // 13760
constexpr int O_LNBG = O_B2 + 32;
constexpr int O_LNBB = O_LNBG + 32;
constexpr int BLK_SZ = O_LNBB + 32;               // 13856

// --- global smem layout (floats) ---
constexpr int O_WFEAT = 0;
constexpr int O_BFEAT = O_WFEAT + 320;
constexpr int O_CLS   = O_BFEAT + 320;
constexpr int O_CLFW  = O_CLS + 32;
constexpr int O_CLFB  = O_CLFW + 32;
constexpr int O_BLKW  = 720;
constexpr int O_ACT   = O_BLKW + BLK_SZ;          // 14576

// per-warp activation region (floats)
constexpr int H2_F   = 12 * 32 * 2;               // h2 [12][32] float2 = 768
// block1 staging (float2 units): q[11][16], k[11][16], v[11][16], ctx[11][34]
constexpr int F2_QS  = 0;
constexpr int F2_KS  = 176;
constexpr int F2_VS  = 352;
constexpr int F2_CTX = 528;
constexpr int CTX_STR = 34;
constexpr int LN_MU  = 374;                       // mu/sig offset in LN buf
// block2 staging (float2 units): q0[32], k[11][32], v[11][32], ctx[32]
constexpr int F2_Q2  = 0;
constexpr int F2_K2  = 32;
constexpr int F2_V2  = 384;
constexpr int F2_C2  = 736;
constexpr int F2_G2  = 0;                         // ffn2 g buffer (reuse)
constexpr int STG_F2 = 928;
constexpr int ACT_F  = H2_F + STG_F2 * 2;         // 2624 floats / warp
constexpr int SMEM_FLOATS = O_ACT + NW * ACT_F;   // 56560
constexpr int SMEM_BYTES  = SMEM_FLOATS * 4;      // 226240
}

extern __shared__ float smem[];

using u64 = unsigned long long;

static __device__ __forceinline__ u64 pack2(float x, float y) {
    u64 r; asm("mov.b64 %0,{%1,%2};" : "=l"(r) : "f"(x), "f"(y)); return r;
}
static __device__ __forceinline__ void unpack2(u64 v, float& x, float& y) {
    asm("mov.b64 {%0,%1},%2;" : "=f"(x), "=f"(y) : "l"(v));
}
static __device__ __forceinline__ u64 dup2(float x) { return pack2(x, x); }
static __device__ __forceinline__ u64 fma2(u64 a, u64 b, u64 c) {
    u64 d; asm("fma.rn.f32x2 %0,%1,%2,%3;" : "=l"(d) : "l"(a), "l"(b), "l"(c)); return d;
}
static __device__ __forceinline__ u64 add2(u64 a, u64 b) {
    u64 d; asm("add.rn.f32x2 %0,%1,%2;" : "=l"(d) : "l"(a), "l"(b)); return d;
}
static __device__ __forceinline__ u64 mul2(u64 a, u64 b) {
    u64 d; asm("mul.rn.f32x2 %0,%1,%2;" : "=l"(d) : "l"(a), "l"(b)); return d;
}
static __device__ __forceinline__ u64 neg2(u64 x) {
    return x ^ 0x8000000080000000ULL;
}
static __device__ __forceinline__ u64 shflx2(u64 v, int m) {
    float x, y; unpack2(v, x, y);
    x = __shfl_xor_sync(0xffffffffu, x, m);
    y = __shfl_xor_sync(0xffffffffu, y, m);
    return pack2(x, y);
}
static __device__ __forceinline__ float gelu1(float x) {
    return 0.5f * x * (1.0f + erff(x * 0.7071067811865475f));
}
// single-token LN via butterfly (used in CLS-specialized block 2)
static __device__ __forceinline__ u64 ln_norm(u64 v, u64 lg, u64 lb) {
    u64 sum = v, sq = mul2(v, v);
#pragma unroll
    for (int mk = 16; mk; mk >>= 1) {
        sum = add2(sum, shflx2(sum, mk));
        sq  = add2(sq,  shflx2(sq,  mk));
    }
    float s0, s1, q0, q1, v0, v1;
    unpack2(sum, s0, s1); unpack2(sq, q0, q1); unpack2(v, v0, v1);
    float mu0 = s0 * 0.03125f, mu1 = s1 * 0.03125f;
    float r0 = rsqrtf(fmaf(-mu0, mu0, q0 * 0.03125f) + 1e-5f);
    float r1 = rsqrtf(fmaf(-mu1, mu1, q1 * 0.03125f) + 1e-5f);
    return fma2(pack2((v0 - mu0) * r0, (v1 - mu1) * r1), lg, lb);
}

struct KParams {
    const float* in[30];
    float* out;
};

// Staged LayerNorm over SN tokens (block 1): stats by lane t, applied by all.
template <int SN>
static __device__ __forceinline__ void ln_apply(u64* h2u, int hbase, u64* buf,
                                                const u64* v, u64 lg, u64 lb,
                                                int lane)
{
#pragma unroll
    for (int t = 0; t < SN; t++) buf[t * 34 + lane] = v[t];
    __syncwarp();
    if (lane < SN) {
        const float2* row = reinterpret_cast<const float2*>(&buf[lane * 34]);
        u64 s = pack2(0.f, 0.f), q = pack2(0.f, 0.f);
#pragma unroll
        for (int i = 0; i < 16; i++) {
            float4 c = *reinterpret_cast<const float4*>(&row[i * 2]);
            u64 a = pack2(c.x, c.y), b = pack2(c.z, c.w);
            s = add2(s, add2(a, b));
            q = fma2(a, a, q); q = fma2(b, b, q);
        }
        float s0, s1, q0, q1;
        unpack2(s, s0, s1); unpack2(q, q0, q1);
        float mu0 = s0 * 0.03125f, mu1 = s1 * 0.03125f;
        float r0 = rsqrtf(fmaf(-mu0, mu0, q0 * 0.03125f) + 1e-5f);
        float r1 = rsqrtf(fmaf(-mu1, mu1, q1 * 0.03125f) + 1e-5f);
        *reinterpret_cast<float4*>(&buf[LN_MU + 2 * lane]) =
            make_float4(mu0, mu1, r0, r1);
    }
    __syncwarp();
#pragma unroll
    for (int t = 0; t < SN; t++) {
        float4 ms = *reinterpret_cast<const float4*>(&buf[LN_MU + 2 * t]);
        u64 mu = pack2(ms.x, ms.y), rs = pack2(ms.z, ms.w);
        u64 t1 = mul2(rs, lg);
        h2u[hbase + t * 32 + lane] = fma2(v[t], t1, add2(lb, neg2(mul2(mu, t1))));
    }
    __syncwarp();
}

// Stage one block's weights: straight strided float4 copies (output-major).
static __device__ __forceinline__ void stage_block(float* W, const float* const* q,
                                                   int tid)
{
    for (int i4 = tid; i4 < 768; i4 += THREADS) {         // qkv [96][32]
        float4 v = reinterpret_cast<const float4*>(q[0])[i4];
        int e = i4 >> 3, c = (i4 & 7) * 4;
        *reinterpret_cast<float4*>(&W[O_QKVW + e * QKVW_STR + c]) = v;
    }
    for (int i = tid; i < 96; i += THREADS) W[O_QKVB + i] = q[1][i];
    for (int i4 = tid; i4 < 256; i4 += THREADS) {         // out_w [32][32]
        float4 v = reinterpret_cast<const float4*>(q[2])[i4];
        int e = i4 >> 3, c = (i4 & 7) * 4;
        *reinterpret_cast<float4*>(&W[O_OUTW + e * OUTW_STR + c]) = v;
    }
    if (tid < 32) {
        W[O_OUTB + tid] = q[3][tid];
        W[O_LNAG + tid] = q[4][tid];
        W[O_LNAB + tid] = q[5][tid];
    }
    for (int i4 = tid; i4 < 1024; i4 += THREADS) {        // w1 [128][32]
        float4 v = reinterpret_cast<const float4*>(q[6])[i4];
        int f = i4 >> 3, c = (i4 & 7) * 4;
        *reinterpret_cast<float4*>(&W[O_W1 + f * W1_STR + c]) = v;
    }
    for (int i = tid; i < 128; i += THREADS) W[O_B1 + i] = q[7][i];
    for (int i4 = tid; i4 < 1024; i4 += THREADS) {        // w2 [32][128]
        float4 v = reinterpret_cast<const float4*>(q[8])[i4];
        int d = i4 >> 5, c = (i4 & 31) * 4;
        *reinterpret_cast<float4*>(&W[O_W2 + d * W2_STR + c]) = v;
    }
    if (tid < 32) {
        W[O_B2   + tid] = q[9][tid];
        W[O_LNBG + tid] = q[10][tid];
        W[O_LNBB + tid] = q[11][tid];
    }
}

// FFN over tokens [SB, SB+SN) (block 1).
template <int SB, int SN>
static __device__ __forceinline__ void ffn_pass(u64* h2u, u64* g2u,
                                                const float* W, int lane)
{
    const float2* g2f = reinterpret_cast<const float2*>(g2u);
    const float2* h2f = reinterpret_cast<const float2*>(h2u);

    u64 ga[4][SN];
#pragma unroll
    for (int j = 0; j < 4; j++) {
        u64 b = dup2(W[O_B1 + lane + 32 * j]);
#pragma unroll
        for (int t = 0; t < SN; t++) ga[j][t] = b;
    }
    for (int d0 = 0; d0 < 32; d0 += 4) {
        u64 w[4][4];
#pragma unroll
        for (int j = 0; j < 4; j++) {
            float4 f = *reinterpret_cast<const float4*>(
                &W[O_W1 + (lane + 32 * j) * W1_STR + d0]);
            w[j][0] = dup2(f.x); w[j][1] = dup2(f.y);
            w[j][2] = dup2(f.z); w[j][3] = dup2(f.w);
        }
#pragma unroll
        for (int t = 0; t < SN; t++) {
            float4 a = *reinterpret_cast<const float4*>(&h2f[(SB + t) * 32 + d0]);
            float4 b = *reinterpret_cast<const float4*>(&h2f[(SB + t) * 32 + d0 + 2]);
            u64 x[4] = {pack2(a.x, a.y), pack2(a.z, a.w),
                        pack2(b.x, b.y), pack2(b.z, b.w)};
#pragma unroll
            for (int j = 0; j < 4; j++)
#pragma unroll
                for (int m = 0; m < 4; m++)
                    ga[j][t] = fma2(x[m], w[j][m], ga[j][t]);
        }
    }
#pragma unroll
    for (int j = 0; j < 4; j++)
#pragma unroll
        for (int t = 0; t < SN; t++) {
            float a, b; unpack2(ga[j][t], a, b);
            g2u[t * 128 + lane + 32 * j] = pack2(gelu1(a), gelu1(b));
        }
    __syncwarp();

    u64 o2[SN];
    {
        u64 b = dup2(W[O_B2 + lane]);
#pragma unroll
        for (int t = 0; t < SN; t++) o2[t] = b;
    }
    for (int f0 = 0; f0 < 128; f0 += 4) {
        float4 fw = *reinterpret_cast<const float4*>(&W[O_W2 + lane * W2_STR + f0]);
        u64 w0 = dup2(fw.x), w1 = dup2(fw.y), w2 = dup2(fw.z), w3 = dup2(fw.w);
#pragma unroll
        for (int t = 0; t < SN; t++) {
            float4 a = *reinterpret_cast<const float4*>(&g2f[t * 128 + f0]);
            float4 b = *reinterpret_cast<const float4*>(&g2f[t * 128 + f0 + 2]);
            o2[t] = fma2(pack2(a.x, a.y), w0, o2[t]);
            o2[t] = fma2(pack2(a.z, a.w), w1, o2[t]);
            o2[t] = fma2(pack2(b.x, b.y), w2, o2[t]);
            o2[t] = fma2(pack2(b.z, b.w), w3, o2[t]);
        }
    }
#pragma unroll
    for (int t = 0; t < SN; t++)
        o2[t] = add2(o2[t], h2u[(SB + t) * 32 + lane]);
    __syncwarp();
    ln_apply<SN>(h2u, SB * 32, g2u,
                 o2, dup2(W[O_LNBG + lane]), dup2(W[O_LNBB + lane]), lane);
}

// Block 1: full transformer block for a packed batch-pair.
__device__ __noinline__ void block_pair(int hoff, int soff, int lane)
{
    u64* h2u = reinterpret_cast<u64*>(&smem[hoff]);
    u64* stg = reinterpret_cast<u64*>(&smem[soff]);
    const float2* h2f = reinterpret_cast<const float2*>(h2u);
    const float2* stf = reinterpret_cast<const float2*>(stg);
    const float* W = &smem[O_BLKW];

    // ---------------- QKV projection (lane = output dim) ----------------
    u64 qa[S], ka[S], va[S];
    {
        u64 bq = dup2(W[O_QKVB + lane]);
        u64 bk = dup2(W[O_QKVB + 32 + lane]);
        u64 bv = dup2(W[O_QKVB + 64 + lane]);
#pragma unroll
        for (int s = 0; s < S; s++) { qa[s] = bq; ka[s] = bk; va[s] = bv; }
    }
    for (int d0 = 0; d0 < 32; d0 += 4) {
        float4 fq = *reinterpret_cast<const float4*>(&W[O_QKVW + lane * QKVW_STR + d0]);
        float4 fk = *reinterpret_cast<const float4*>(&W[O_QKVW + (lane + 32) * QKVW_STR + d0]);
        float4 fv = *reinterpret_cast<const float4*>(&W[O_QKVW + (lane + 64) * QKVW_STR + d0]);
        u64 wq[4] = {dup2(fq.x), dup2(fq.y), dup2(fq.z), dup2(fq.w)};
        u64 wk[4] = {dup2(fk.x), dup2(fk.y), dup2(fk.z), dup2(fk.w)};
        u64 wv[4] = {dup2(fv.x), dup2(fv.y), dup2(fv.z), dup2(fv.w)};
#pragma unroll
        for (int s = 0; s < S; s++) {
            float4 a = *reinterpret_cast<const float4*>(&h2f[s * 32 + d0]);
            float4 b = *reinterpret_cast<const float4*>(&h2f[s * 32 + d0 + 2]);
            u64 x[4] = {pack2(a.x, a.y), pack2(a.z, a.w),
                        pack2(b.x, b.y), pack2(b.z, b.w)};
#pragma unroll
            for (int j = 0; j < 4; j++) {
                qa[s] = fma2(x[j], wq[j], qa[s]);
                ka[s] = fma2(x[j], wk[j], ka[s]);
                va[s] = fma2(x[j], wv[j], va[s]);
            }
        }
    }
    {
        u64 scl = dup2(0.35355339059327373f);
#pragma unroll
        for (int s = 0; s < S; s++) qa[s] = mul2(qa[s], scl);
    }

    // ---------------- attention: two head-pair passes, shuffle-free ---------
    const int qi = (lane >> 1) > 10 ? 10 : (lane >> 1);
    const int hl = lane & 1;
    const int hb = hl * 8;
#pragma unroll
    for (int p = 0; p < 2; p++) {
        if ((lane >> 4) == p) {
            int ld = lane & 15;
#pragma unroll
            for (int s = 0; s < S; s++) {
                stg[F2_QS + s * 16 + ld] = qa[s];
                stg[F2_KS + s * 16 + ld] = ka[s];
                stg[F2_VS + s * 16 + ld] = va[s];
            }
        }
        __syncwarp();

        u64 qr[8];
#pragma unroll
        for (int j = 0; j < 8; j += 2) {
            float4 t = *reinterpret_cast<const float4*>(&stf[F2_QS + qi * 16 + hb + j]);
            qr[j] = pack2(t.x, t.y); qr[j + 1] = pack2(t.z, t.w);
        }
        float e0[S], e1[S];
#pragma unroll
        for (int ki = 0; ki < S; ki++) {
            u64 acc = pack2(0.f, 0.f);
#pragma unroll
            for (int j = 0; j < 8; j += 2) {
                float4 kv = *reinterpret_cast<const float4*>(&stf[F2_KS + ki * 16 + hb + j]);
                acc = fma2(qr[j],     pack2(kv.x, kv.y), acc);
                acc = fma2(qr[j + 1], pack2(kv.z, kv.w), acc);
            }
            unpack2(acc, e0[ki], e1[ki]);
        }
        float m0 = e0[0], m1 = e1[0];
#pragma unroll
        for (int ki = 1; ki < S; ki++) { m0 = fmaxf(m0, e0[ki]); m1 = fmaxf(m1, e1[ki]); }
        float den0 = 0.f, den1 = 0.f;
#pragma unroll
        for (int ki = 0; ki < S; ki++) {
            e0[ki] = __expf(e0[ki] - m0); den0 += e0[ki];
            e1[ki] = __expf(e1[ki] - m1); den1 += e1[ki];
        }
        u64 cacc[8];
#pragma unroll
        for (int j = 0; j < 8; j++) cacc[j] = pack2(0.f, 0.f);
#pragma unroll
        for (int ki = 0; ki < S; ki++) {
            u64 ev = pack2(e0[ki], e1[ki]);
#pragma unroll
            for (int j = 0; j < 8; j += 2) {
                float4 vv = *reinterpret_cast<const float4*>(&stf[F2_VS + ki * 16 + hb + j]);
                cacc[j]     = fma2(ev, pack2(vv.x, vv.y), cacc[j]);
                cacc[j + 1] = fma2(ev, pack2(vv.z, vv.w), cacc[j + 1]);
            }
        }
        if (lane < 22) {
            u64 inv = pack2(1.0f / den0, 1.0f / den1);
            int cb = F2_CTX + qi * CTX_STR + (p * 2 + hl) * 8;
#pragma unroll
            for (int j = 0; j < 8; j++) stg[cb + j] = mul2(cacc[j], inv);
        }
        __syncwarp();
    }

    // ---------------- output projection + residual + LN_A -------------------
    u64 o[S];
    {
        u64 bo = dup2(W[O_OUTB + lane]);
#pragma unroll
        for (int s = 0; s < S; s++) o[s] = bo;
    }
    for (int d0 = 0; d0 < 32; d0 += 4) {
        float4 fw = *reinterpret_cast<const float4*>(&W[O_OUTW + lane * OUTW_STR + d0]);
        u64 w0 = dup2(fw.x), w1 = dup2(fw.y), w2 = dup2(fw.z), w3 = dup2(fw.w);
#pragma unroll
        for (int s = 0; s < S; s++) {
            float4 c0 = *reinterpret_cast<const float4*>(&stf[F2_CTX + s * CTX_STR + d0]);
            float4 c1 = *reinterpret_cast<const float4*>(&stf[F2_CTX + s * CTX_STR + d0 + 2]);
            o[s] = fma2(pack2(c0.x, c0.y), w0, o[s]);
            o[s] = fma2(pack2(c0.z, c0.w), w1, o[s]);
            o[s] = fma2(pack2(c1.x, c1.y), w2, o[s]);
            o[s] = fma2(pack2(c1.z, c1.w), w3, o[s]);
        }
    }
#pragma unroll
    for (int s = 0; s < S; s++)
        o[s] = add2(o[s], h2u[s * 32 + lane]);
    __syncwarp();
    ln_apply<S>(h2u, 0, stg + F2_CTX,
                o, dup2(W[O_LNAG + lane]), dup2(W[O_LNAB + lane]), lane);

    ffn_pass<0, 6>(h2u, stg, W, lane);
    ffn_pass<6, 5>(h2u, stg, W, lane);
}

// Block 2: CLS-specialized — K/V for all tokens, everything else token 0 only.
__device__ __noinline__ void block2_pair(int hoff, int soff, int lane)
{
    u64* h2u = reinterpret_cast<u64*>(&smem[hoff]);
    u64* stg = reinterpret_cast<u64*>(&smem[soff]);
    const float2* h2f = reinterpret_cast<const float2*>(h2u);
    const float2* stf = reinterpret_cast<const float2*>(stg);
    const float* W = &smem[O_BLKW];

    // ---------------- QKV: k,v all tokens; q token 0 only -------------------
    u64 ka[S], va[S];
    u64 q0 = dup2(W[O_QKVB + lane]);
    {
        u64 bk = dup2(W[O_QKVB + 32 + lane]);
        u64 bv = dup2(W[O_QKVB + 64 + lane]);
#pragma unroll
        for (int s = 0; s < S; s++) { ka[s] = bk; va[s] = bv; }
    }
    for (int d0 = 0; d0 < 32; d0 += 4) {
        float4 fq = *reinterpret_cast<const float4*>(&W[O_QKVW + lane * QKVW_STR + d0]);
        float4 fk = *reinterpret_cast<const float4*>(&W[O_QKVW + (lane + 32) * QKVW_STR + d0]);
        float4 fv = *reinterpret_cast<const float4*>(&W[O_QKVW + (lane + 64) * QKVW_STR + d0]);
        u64 wq[4] = {dup2(fq.x), dup2(fq.y), dup2(fq.z), dup2(fq.w)};
        u64 wk[4] = {dup2(fk.x), dup2(fk.y), dup2(fk.z), dup2(fk.w)};
        u64 wv[4] = {dup2(fv.x), dup2(fv.y), dup2(fv.z), dup2(fv.w)};
#pragma unroll
        for (int s = 0; s < S; s++) {
            float4 a = *reinterpret_cast<const float4*>(&h2f[s * 32 + d0]);
            float4 b = *reinterpret_cast<const float4*>(&h2f[s * 32 + d0 + 2]);
            u64 x[4] = {pack2(a.x, a.y), pack2(a.z, a.w),
                        pack2(b.x, b.y), pack2(b.z, b.w)};
#pragma unroll
            for (int j = 0; j < 4; j++) {
                ka[s] = fma2(x[j], wk[j], ka[s]);
                va[s] = fma2(x[j], wv[j], va[s]);
            }
            if (s == 0) {
#pragma unroll
                for (int j = 0; j < 4; j++) q0 = fma2(x[j], wq[j], q0);
            }
        }
    }
    q0 = mul2(q0, dup2(0.35355339059327373f));

    // stage q0 / K / V (lane = dim; rows stride 32 f2)
    stg[F2_Q2 + lane] = q0;
#pragma unroll
    for (int s = 0; s < S; s++) {
        stg[F2_K2 + s * 32 + lane] = ka[s];
        stg[F2_V2 + s * 32 + lane] = va[s];
    }
    __syncwarp();

    // ---------------- attention row 0: lane = dim, head = lane>>3 -----------
    const int hb2 = (lane >> 3) * 8;     // head base (f2)
    u64 qr[8];
#pragma unroll
    for (int j = 0; j < 8; j += 2) {
        float4 t = *reinterpret_cast<const float4*>(&stf[F2_Q2 + hb2 + j]);
        qr[j] = pack2(t.x, t.y); qr[j + 1] = pack2(t.z, t.w);
    }
    float e0[S], e1[S];
#pragma unroll
    for (int ki = 0; ki < S; ki++) {
        u64 acc = pack2(0.f, 0.f);
#pragma unroll
        for (int j = 0; j < 8; j += 2) {
            float4 kv = *reinterpret_cast<const float4*>(&stf[F2_K2 + ki * 32 + hb2 + j]);
            acc = fma2(qr[j],     pack2(kv.x, kv.y), acc);
            acc = fma2(qr[j + 1], pack2(kv.z, kv.w), acc);
        }
        unpack2(acc, e0[ki], e1[ki]);
    }
    float m0 = e0[0], m1 = e1[0];
#pragma unroll
    for (int ki = 1; ki < S; ki++) { m0 = fmaxf(m0, e0[ki]); m1 = fmaxf(m1, e1[ki]); }
    float den0 = 0.f, den1 = 0.f;
#pragma unroll
    for (int ki = 0; ki < S; ki++) {
        e0[ki] = __expf(e0[ki] - m0); den0 += e0[ki];
        e1[ki] = __expf(e1[ki] - m1); den1 += e1[ki];
    }
    u64 c = pack2(0.f, 0.f);
#pragma unroll
    for (int ki = 0; ki < S; ki++)
        c = fma2(pack2(e0[ki], e1[ki]), stg[F2_V2 + ki * 32 + lane], c);
    c = mul2(c, pack2(1.0f / den0, 1.0f / den1));
    __syncwarp();                        // K2/V2 reads done before C2 write
    stg[F2_C2 + lane] = c;
    __syncwarp();

    // ---------------- out-proj token 0 + residual + LN_A --------------------
    u64 o = dup2(W[O_OUTB + lane]);
    for (int d0 = 0; d0 < 32; d0 += 4) {
        float4 fw = *reinterpret_cast<const float4*>(&W[O_OUTW + lane * OUTW_STR + d0]);
        float4 c0 = *reinterpret_cast<const float4*>(&stf[F2_C2 + d0]);
        float4 c1 = *reinterpret_cast<const float4*>(&stf[F2_C2 + d0 + 2]);
        o = fma2(pack2(c0.x, c0.y), dup2(fw.x), o);
        o = fma2(pack2(c0.z, c0.w), dup2(fw.y), o);
        o = fma2(pack2(c1.x, c1.y), dup2(fw.z), o);
        o = fma2(pack2(c1.z, c1.w), dup2(fw.w), o);
    }
    o = add2(o, h2u[lane]);
    u64 hn = ln_norm(o, dup2(W[O_LNAG + lane]), dup2(W[O_LNAB + lane]));
    h2u[lane] = hn;
    __syncwarp();

    // ---------------- FFN token 0 -------------------------------------------
    u64 ga[4];
#pragma unroll
    for (int j = 0; j < 4; j++) ga[j] = dup2(W[O_B1 + lane + 32 * j]);
    for (int d0 = 0; d0 < 32; d0 += 4) {
        float4 a = *reinterpret_cast<const float4*>(&h2f[d0]);
        float4 b = *reinterpret_cast<const float4*>(&h2f[d0 + 2]);
        u64 x[4] = {pack2(a.x, a.y), pack2(a.z, a.w),
                    pack2(b.x, b.y), pack2(b.z, b.w)};
#pragma unroll
        for (int j = 0; j < 4; j++) {
            float4 f = *reinterpret_cast<const float4*>(
                &W[O_W1 + (lane + 32 * j) * W1_STR + d0]);
            ga[j] = fma2(x[0], dup2(f.x), ga[j]);
            ga[j] = fma2(x[1], dup2(f.y), ga[j]);
            ga[j] = fma2(x[2], dup2(f.z), ga[j]);
            ga[j] = fma2(x[3], dup2(f.w), ga[j]);
        }
    }
#pragma unroll
    for (int j = 0; j < 4; j++) {
        float a, b; unpack2(ga[j], a, b);
        stg[F2_G2 + lane + 32 * j] = pack2(gelu1(a), gelu1(b));
    }
    __syncwarp();

    u64 o2 = dup2(W[O_B2 + lane]);
    for (int f0 = 0; f0 < 128; f0 += 4) {
        float4 fw = *reinterpret_cast<const float4*>(&W[O_W2 + lane * W2_STR + f0]);
        float4 a = *reinterpret_cast<const float4*>(&stf[F2_G2 + f0]);
        float4 b = *reinterpret_cast<const float4*>(&stf[F2_G2 + f0 + 2]);
        o2 = fma2(pack2(a.x, a.y), dup2(fw.x), o2);
        o2 = fma2(pack2(a.z, a.w), dup2(fw.y), o2);
        o2 = fma2(pack2(b.x, b.y), dup2(fw.z), o2);
        o2 = fma2(pack2(b.z, b.w), dup2(fw.w), o2);
    }
    o2 = add2(o2, hn);
    h2u[lane] = ln_norm(o2, dup2(W[O_LNBG + lane]), dup2(W[O_LNBB + lane]));
    __syncwarp();
}

__global__ void __launch_bounds__(THREADS)
tab_transformer_kernel(KParams p)
{
    const int tid = threadIdx.x;

    for (int i = tid; i < 320; i += THREADS) smem[O_WFEAT + i] = p.in[1][i];
    for (int i = tid; i < 320; i += THREADS) smem[O_BFEAT + i] = p.in[2][i];
    if (tid < 32) {
        smem[O_CLS  + tid] = p.in[3][tid];
        smem[O_CLFW + tid] = p.in[28][tid];
    }
    if (tid == 0) smem[O_CLFB] = p.in[29][0];
    stage_block(&smem[O_BLKW], &p.in[4], tid);
    __syncthreads();

    const int warp = tid >> 5, lane = tid & 31;
    int pr = blockIdx.x * NW + warp;
    const bool valid = (pr < NPAIR);
    if (!valid) pr = NPAIR - 1;
    const int b0 = pr * 2;

    const int hoff = O_ACT + warp * ACT_F;
    const int soff = hoff + H2_F;
    u64* h2u = reinterpret_cast<u64*>(&smem[hoff]);

    float xv0 = (lane < 10) ? p.in[0][(size_t)b0 * 10 + lane] : 0.f;
    float xv1 = (lane < 10) ? p.in[0][(size_t)(b0 + 1) * 10 + lane] : 0.f;
    h2u[lane] = dup2(smem[O_CLS + lane]);
#pragma unroll
    for (int i = 0; i < 10; i++) {
        float a = __shfl_sync(0xffffffffu, xv0, i);
        float b = __shfl_sync(0xffffffffu, xv1, i);
        u64 w  = dup2(smem[O_WFEAT + i * 32 + lane]);
        u64 bb = dup2(smem[O_BFEAT + i * 32 + lane]);
        h2u[(i + 1) * 32 + lane] = fma2(pack2(a, b), w, bb);
    }
    __syncwarp();

    block_pair(hoff, soff, lane);

    __syncthreads();
    stage_block(&smem[O_BLKW], &p.in[16], tid);
    __syncthreads();

    block2_pair(hoff, soff, lane);

    u64 v = mul2(h2u[lane], dup2(smem[O_CLFW + lane]));
#pragma unroll
    for (int mk = 16; mk; mk >>= 1) v = add2(v, shflx2(v, mk));
    if (valid && lane == 0) {
        float r0, r1; unpack2(v, r0, r1);
        float cb = smem[O_CLFB];
        *reinterpret_cast<float2*>(&p.out[b0]) = make_float2(r0 + cb, r1 + cb);
    }
}

extern "C" void kernel_launch(void* const* d_in, const int* in_sizes, int n_in,
                              void* d_out, int out_size)
{
    (void)in_sizes; (void)n_in; (void)out_size;
    KParams p;
    for (int i = 0; i < 30; i++) p.in[i] = (const float*)d_in[i];
    p.out = (float*)d_out;

    cudaFuncSetAttribute(tab_transformer_kernel,
                         cudaFuncAttributeMaxDynamicSharedMemorySize, SMEM_BYTES);

    const int grid = (NPAIR + NW - 1) / NW;   // 4096
    tab_transformer_kernel<<<grid, THREADS, SMEM_BYTES>>>(p);
}

// round 11
// speedup vs baseline: 2.4352x; 1.0818x over previous
#include <cuda_runtime.h>

// Fused 2-block tiny-transformer, 131072 sequences. One warp = TWO batches
// packed as f32x2. Block 1: full 11-token block; FFN2 split-half across lane
// groups (halves broadcast LDS wavefronts). Block 2: CLS-specialized; V kept
// in registers (no staging).

namespace {
constexpr int S  = 11;
constexpr int NW = 16;
constexpr int THREADS = NW * 32;                  // 512
constexpr int BTOT = 131072;
constexpr int NPAIR = BTOT / 2;                   // 65536

// --- per-block weight layout (floats), output-major rows, stride%32==4 ------
constexpr int QKVW_STR = 36;
constexpr int OUTW_STR = 36;
constexpr int W1_STR   = 36;
constexpr int W2_STR   = 132;

constexpr int O_QKVW = 0;
constexpr int O_QKVB = O_QKVW + 96 * QKVW_STR;    // 3456
constexpr int O_OUTW = O_QKVB + 96;               // 3552
constexpr int O_OUTB = O_OUTW + 32 * OUTW_STR;    // 4704
constexpr int O_LNAG = O_OUTB + 32;
constexpr int O_LNAB = O_LNAG + 32;
constexpr int O_W1   = O_LNAB + 32;               // 4800
constexpr int O_B1   = O_W1 + 128 * W1_STR;       // 9408
constexpr int O_W2   = O_B1 + 128;                // 9536
constexpr int O_B2   = O_W2 + 32 * W2_STR;        // 13760
constexpr int O_LNBG = O_B2 + 32;
constexpr int O_LNBB = O_LNBG + 32;
constexpr int BLK_SZ = O_LNBB + 32;               // 13856

// --- global smem layout (floats) ---
constexpr int O_WFEAT = 0;
constexpr int O_BFEAT = O_WFEAT + 320;
constexpr int O_CLS   = O_BFEAT + 320;
constexpr int O_CLFW  = O_CLS + 32;
constexpr int O_CLFB  = O_CLFW + 32;
constexpr int O_BLKW  = 720;
constexpr int O_ACT   = O_BLKW + BLK_SZ;          // 14576

// per-warp activation region (floats)
constexpr int H2_F   = 12 * 32 * 2;               // h2 [12][32] float2 = 768
// block1 staging (float2 units): q[11][16], k[11][16], v[11][16], ctx[11][34]
constexpr int F2_QS  = 0;
constexpr int F2_KS  = 176;
constexpr int F2_VS  = 352;
constexpr int F2_CTX = 528;
constexpr int CTX_STR = 34;
constexpr int LN_MU  = 374;                       // mu/sig offset in LN buf
// block2 staging (float2 units): q0[32], k[11][32], ctx[32]
constexpr int F2_Q2  = 0;
constexpr int F2_K2  = 32;
constexpr int F2_C2  = 736;
constexpr int F2_G2  = 0;                         // ffn g buffer (reuse)
constexpr int STG_F2 = 928;
constexpr int ACT_F  = H2_F + STG_F2 * 2;         // 2624 floats / warp
constexpr int SMEM_FLOATS = O_ACT + NW * ACT_F;   // 56560
constexpr int SMEM_BYTES  = SMEM_FLOATS * 4;      // 226240
}

extern __shared__ float smem[];

using u64 = unsigned long long;

static __device__ __forceinline__ u64 pack2(float x, float y) {
    u64 r; asm("mov.b64 %0,{%1,%2};" : "=l"(r) : "f"(x), "f"(y)); return r;
}
static __device__ __forceinline__ void unpack2(u64 v, float& x, float& y) {
    asm("mov.b64 {%0,%1},%2;" : "=f"(x), "=f"(y) : "l"(v));
}
static __device__ __forceinline__ u64 dup2(float x) { return pack2(x, x); }
static __device__ __forceinline__ u64 fma2(u64 a, u64 b, u64 c) {
    u64 d; asm("fma.rn.f32x2 %0,%1,%2,%3;" : "=l"(d) : "l"(a), "l"(b), "l"(c)); return d;
}
static __device__ __forceinline__ u64 add2(u64 a, u64 b) {
    u64 d; asm("add.rn.f32x2 %0,%1,%2;" : "=l"(d) : "l"(a), "l"(b)); return d;
}
static __device__ __forceinline__ u64 mul2(u64 a, u64 b) {
    u64 d; asm("mul.rn.f32x2 %0,%1,%2;" : "=l"(d) : "l"(a), "l"(b)); return d;
}
static __device__ __forceinline__ u64 neg2(u64 x) {
    return x ^ 0x8000000080000000ULL;
}
static __device__ __forceinline__ u64 shflx2(u64 v, int m) {
    float x, y; unpack2(v, x, y);
    x = __shfl_xor_sync(0xffffffffu, x, m);
    y = __shfl_xor_sync(0xffffffffu, y, m);
    return pack2(x, y);
}
static __device__ __forceinline__ float gelu1(float x) {
    return 0.5f * x * (1.0f + erff(x * 0.7071067811865475f));
}
// single-token LN via butterfly (block 2)
static __device__ __forceinline__ u64 ln_norm(u64 v, u64 lg, u64 lb) {
    u64 sum = v, sq = mul2(v, v);
#pragma unroll
    for (int mk = 16; mk; mk >>= 1) {
        sum = add2(sum, shflx2(sum, mk));
        sq  = add2(sq,  shflx2(sq,  mk));
    }
    float s0, s1, q0, q1, v0, v1;
    unpack2(sum, s0, s1); unpack2(sq, q0, q1); unpack2(v, v0, v1);
    float mu0 = s0 * 0.03125f, mu1 = s1 * 0.03125f;
    float r0 = rsqrtf(fmaf(-mu0, mu0, q0 * 0.03125f) + 1e-5f);
    float r1 = rsqrtf(fmaf(-mu1, mu1, q1 * 0.03125f) + 1e-5f);
    return fma2(pack2((v0 - mu0) * r0, (v1 - mu1) * r1), lg, lb);
}

struct KParams {
    const float* in[30];
    float* out;
};

// Staged LayerNorm over SN tokens (block 1): stats by lane t, applied by all.
template <int SN>
static __device__ __forceinline__ void ln_apply(u64* h2u, int hbase, u64* buf,
                                                const u64* v, u64 lg, u64 lb,
                                                int lane)
{
#pragma unroll
    for (int t = 0; t < SN; t++) buf[t * 34 + lane] = v[t];
    __syncwarp();
    if (lane < SN) {
        const float2* row = reinterpret_cast<const float2*>(&buf[lane * 34]);
        u64 s = pack2(0.f, 0.f), q = pack2(0.f, 0.f);
#pragma unroll
        for (int i = 0; i < 16; i++) {
            float4 c = *reinterpret_cast<const float4*>(&row[i * 2]);
            u64 a = pack2(c.x, c.y), b = pack2(c.z, c.w);
            s = add2(s, add2(a, b));
            q = fma2(a, a, q); q = fma2(b, b, q);
        }
        float s0, s1, q0, q1;
        unpack2(s, s0, s1); unpack2(q, q0, q1);
        float mu0 = s0 * 0.03125f, mu1 = s1 * 0.03125f;
        float r0 = rsqrtf(fmaf(-mu0, mu0, q0 * 0.03125f) + 1e-5f);
        float r1 = rsqrtf(fmaf(-mu1, mu1, q1 * 0.03125f) + 1e-5f);
        *reinterpret_cast<float4*>(&buf[LN_MU + 2 * lane]) =
            make_float4(mu0, mu1, r0, r1);
    }
    __syncwarp();
#pragma unroll
    for (int t = 0; t < SN; t++) {
        float4 ms = *reinterpret_cast<const float4*>(&buf[LN_MU + 2 * t]);
        u64 mu = pack2(ms.x, ms.y), rs = pack2(ms.z, ms.w);
        u64 t1 = mul2(rs, lg);
        h2u[hbase + t * 32 + lane] = fma2(v[t], t1, add2(lb, neg2(mul2(mu, t1))));
    }
    __syncwarp();
}

// Stage one block's weights: straight strided float4 copies (output-major).
static __device__ __forceinline__ void stage_block(float* W, const float* const* q,
                                                   int tid)
{
    for (int i4 = tid; i4 < 768; i4 += THREADS) {         // qkv [96][32]
        float4 v = reinterpret_cast<const float4*>(q[0])[i4];
        int e = i4 >> 3, c = (i4 & 7) * 4;
        *reinterpret_cast<float4*>(&W[O_QKVW + e * QKVW_STR + c]) = v;
    }
    for (int i = tid; i < 96; i += THREADS) W[O_QKVB + i] = q[1][i];
    for (int i4 = tid; i4 < 256; i4 += THREADS) {         // out_w [32][32]
        float4 v = reinterpret_cast<const float4*>(q[2])[i4];
        int e = i4 >> 3, c = (i4 & 7) * 4;
        *reinterpret_cast<float4*>(&W[O_OUTW + e * OUTW_STR + c]) = v;
    }
    if (tid < 32) {
        W[O_OUTB + tid] = q[3][tid];
        W[O_LNAG + tid] = q[4][tid];
        W[O_LNAB + tid] = q[5][tid];
    }
    for (int i4 = tid; i4 < 1024; i4 += THREADS) {        // w1 [128][32]
        float4 v = reinterpret_cast<const float4*>(q[6])[i4];
        int f = i4 >> 3, c = (i4 & 7) * 4;
        *reinterpret_cast<float4*>(&W[O_W1 + f * W1_STR + c]) = v;
    }
    for (int i = tid; i < 128; i += THREADS) W[O_B1 + i] = q[7][i];
    for (int i4 = tid; i4 < 1024; i4 += THREADS) {        // w2 [32][128]
        float4 v = reinterpret_cast<const float4*>(q[8])[i4];
        int d = i4 >> 5, c = (i4 & 31) * 4;
        *reinterpret_cast<float4*>(&W[O_W2 + d * W2_STR + c]) = v;
    }
    if (tid < 32) {
        W[O_B2   + tid] = q[9][tid];
        W[O_LNBG + tid] = q[10][tid];
        W[O_LNBB + tid] = q[11][tid];
    }
}

// FFN over tokens [SB, SB+SN) (block 1): FFN1 -> GELU -> FFN2 split-half
// -> +res -> LN_B.
template <int SB, int SN>
static __device__ __forceinline__ void ffn_pass(u64* h2u, u64* g2u,
                                                const float* W, int lane)
{
    const float2* g2f = reinterpret_cast<const float2*>(g2u);
    const float2* h2f = reinterpret_cast<const float2*>(h2u);

    // ---- FFN1: 32 -> 128 ----
    u64 ga[4][SN];
#pragma unroll
    for (int j = 0; j < 4; j++) {
        u64 b = dup2(W[O_B1 + lane + 32 * j]);
#pragma unroll
        for (int t = 0; t < SN; t++) ga[j][t] = b;
    }
    for (int d0 = 0; d0 < 32; d0 += 4) {
        u64 w[4][4];
#pragma unroll
        for (int j = 0; j < 4; j++) {
            float4 f = *reinterpret_cast<const float4*>(
                &W[O_W1 + (lane + 32 * j) * W1_STR + d0]);
            w[j][0] = dup2(f.x); w[j][1] = dup2(f.y);
            w[j][2] = dup2(f.z); w[j][3] = dup2(f.w);
        }
#pragma unroll
        for (int t = 0; t < SN; t++) {
            float4 a = *reinterpret_cast<const float4*>(&h2f[(SB + t) * 32 + d0]);
            float4 b = *reinterpret_cast<const float4*>(&h2f[(SB + t) * 32 + d0 + 2]);
            u64 x[4] = {pack2(a.x, a.y), pack2(a.z, a.w),
                        pack2(b.x, b.y), pack2(b.z, b.w)};
#pragma unroll
            for (int j = 0; j < 4; j++)
#pragma unroll
                for (int m = 0; m < 4; m++)
                    ga[j][t] = fma2(x[m], w[j][m], ga[j][t]);
        }
    }
#pragma unroll
    for (int j = 0; j < 4; j++)
#pragma unroll
        for (int t = 0; t < SN; t++) {
            float a, b; unpack2(ga[j][t], a, b);
            g2u[t * 128 + lane + 32 * j] = pack2(gelu1(a), gelu1(b));
        }
    __syncwarp();

    // ---- FFN2: 128 -> 32, split-half: group g = lane>>4 reads f-half g.
    // Lane accumulates partials for outputs lg and lg+16; combined via shfl.
    const int g  = lane >> 4;
    const int lg = lane & 15;
    u64 p0[SN], p1[SN];
#pragma unroll
    for (int t = 0; t < SN; t++) { p0[t] = 0ull; p1[t] = 0ull; }
    const float*  w2a = &W[O_W2 + lg * W2_STR + g * 64];
    const float*  w2b = &W[O_W2 + (lg + 16) * W2_STR + g * 64];
    const float2* gh  = &g2f[g * 64];            // f2 offset of this f-half
    for (int fo = 0; fo < 64; fo += 4) {         // 4 f-dims (2 f2-LDS) per iter
        float4 wa = *reinterpret_cast<const float4*>(&w2a[fo]);
        float4 wb = *reinterpret_cast<const float4*>(&w2b[fo]);
        u64 wa0 = dup2(wa.x), wa1 = dup2(wa.y), wa2 = dup2(wa.z), wa3 = dup2(wa.w);
        u64 wb0 = dup2(wb.x), wb1 = dup2(wb.y), wb2 = dup2(wb.z), wb3 = dup2(wb.w);
#pragma unroll
        for (int t = 0; t < SN; t++) {
            float4 a = *reinterpret_cast<const float4*>(&gh[t * 128 + fo]);
            float4 b = *reinterpret_cast<const float4*>(&gh[t * 128 + fo + 2]);
            u64 x0 = pack2(a.x, a.y), x1 = pack2(a.z, a.w);
            u64 x2 = pack2(b.x, b.y), x3 = pack2(b.z, b.w);
            p0[t] = fma2(x0, wa0, p0[t]); p0[t] = fma2(x1, wa1, p0[t]);
            p0[t] = fma2(x2, wa2, p0[t]); p0[t] = fma2(x3, wa3, p0[t]);
            p1[t] = fma2(x0, wb0, p1[t]); p1[t] = fma2(x1, wb1, p1[t]);
            p1[t] = fma2(x2, wb2, p1[t]); p1[t] = fma2(x3, wb3, p1[t]);
        }
    }
    u64 o2[SN];
    {
        u64 bias = dup2(W[O_B2 + lane]);
#pragma unroll
        for (int t = 0; t < SN; t++) {
            u64 r0 = add2(p0[t], shflx2(p0[t], 16));   // full out lg
            u64 r1 = add2(p1[t], shflx2(p1[t], 16));   // full out lg+16
            o2[t] = add2(add2((lane < 16) ? r0 : r1, bias),
                         h2u[(SB + t) * 32 + lane]);
        }
    }
    __syncwarp();
    ln_apply<SN>(h2u, SB * 32, g2u,
                 o2, dup2(W[O_LNBG + lane]), dup2(W[O_LNBB + lane]), lane);
}

// Block 1: full transformer block for a packed batch-pair.
__device__ __noinline__ void block_pair(int hoff, int soff, int lane)
{
    u64* h2u = reinterpret_cast<u64*>(&smem[hoff]);
    u64* stg = reinterpret_cast<u64*>(&smem[soff]);
    const float2* h2f = reinterpret_cast<const float2*>(h2u);
    const float2* stf = reinterpret_cast<const float2*>(stg);
    const float* W = &smem[O_BLKW];

    // ---------------- QKV projection (lane = output dim) ----------------
    u64 qa[S], ka[S], va[S];
    {
        u64 bq = dup2(W[O_QKVB + lane]);
        u64 bk = dup2(W[O_QKVB + 32 + lane]);
        u64 bv = dup2(W[O_QKVB + 64 + lane]);
#pragma unroll
        for (int s = 0; s < S; s++) { qa[s] = bq; ka[s] = bk; va[s] = bv; }
    }
    for (int d0 = 0; d0 < 32; d0 += 4) {
        float4 fq = *reinterpret_cast<const float4*>(&W[O_QKVW + lane * QKVW_STR + d0]);
        float4 fk = *reinterpret_cast<const float4*>(&W[O_QKVW + (lane + 32) * QKVW_STR + d0]);
        float4 fv = *reinterpret_cast<const float4*>(&W[O_QKVW + (lane + 64) * QKVW_STR + d0]);
        u64 wq[4] = {dup2(fq.x), dup2(fq.y), dup2(fq.z), dup2(fq.w)};
        u64 wk[4] = {dup2(fk.x), dup2(fk.y), dup2(fk.z), dup2(fk.w)};
        u64 wv[4] = {dup2(fv.x), dup2(fv.y), dup2(fv.z), dup2(fv.w)};
#pragma unroll
        for (int s = 0; s < S; s++) {
            float4 a = *reinterpret_cast<const float4*>(&h2f[s * 32 + d0]);
            float4 b = *reinterpret_cast<const float4*>(&h2f[s * 32 + d0 + 2]);
            u64 x[4] = {pack2(a.x, a.y), pack2(a.z, a.w),
                        pack2(b.x, b.y), pack2(b.z, b.w)};
#pragma unroll
            for (int j = 0; j < 4; j++) {
                qa[s] = fma2(x[j], wq[j], qa[s]);
                ka[s] = fma2(x[j], wk[j], ka[s]);
                va[s] = fma2(x[j], wv[j], va[s]);
            }
        }
    }
    {
        u64 scl = dup2(0.35355339059327373f);
#pragma unroll
        for (int s = 0; s < S; s++) qa[s] = mul2(qa[s], scl);
    }

    // ---------------- attention: two head-pair passes, shuffle-free ---------
    const int qi = (lane >> 1) > 10 ? 10 : (lane >> 1);
    const int hl = lane & 1;
    const int hb = hl * 8;
#pragma unroll
    for (int p = 0; p < 2; p++) {
        if ((lane >> 4) == p) {
            int ld = lane & 15;
#pragma unroll
            for (int s = 0; s < S; s++) {
                stg[F2_QS + s * 16 + ld] = qa[s];
                stg[F2_KS + s * 16 + ld] = ka[s];
                stg[F2_VS + s * 16 + ld] = va[s];
            }
        }
        __syncwarp();

        u64 qr[8];
#pragma unroll
        for (int j = 0; j < 8; j += 2) {
            float4 t = *reinterpret_cast<const float4*>(&stf[F2_QS + qi * 16 + hb + j]);
            qr[j] = pack2(t.x, t.y); qr[j + 1] = pack2(t.z, t.w);
        }
        float e0[S], e1[S];
#pragma unroll
        for (int ki = 0; ki < S; ki++) {
            u64 acc = pack2(0.f, 0.f);
#pragma unroll
            for (int j = 0; j < 8; j += 2) {
                float4 kv = *reinterpret_cast<const float4*>(&stf[F2_KS + ki * 16 + hb + j]);
                acc = fma2(qr[j],     pack2(kv.x, kv.y), acc);
                acc = fma2(qr[j + 1], pack2(kv.z, kv.w), acc);
            }
            unpack2(acc, e0[ki], e1[ki]);
        }
        float m0 = e0[0], m1 = e1[0];
#pragma unroll
        for (int ki = 1; ki < S; ki++) { m0 = fmaxf(m0, e0[ki]); m1 = fmaxf(m1, e1[ki]); }
        float den0 = 0.f, den1 = 0.f;
#pragma unroll
        for (int ki = 0; ki < S; ki++) {
            e0[ki] = __expf(e0[ki] - m0); den0 += e0[ki];
            e1[ki] = __expf(e1[ki] - m1); den1 += e1[ki];
        }
        u64 cacc[8];
#pragma unroll
        for (int j = 0; j < 8; j++) cacc[j] = pack2(0.f, 0.f);
#pragma unroll
        for (int ki = 0; ki < S; ki++) {
            u64 ev = pack2(e0[ki], e1[ki]);
#pragma unroll
            for (int j = 0; j < 8; j += 2) {
                float4 vv = *reinterpret_cast<const float4*>(&stf[F2_VS + ki * 16 + hb + j]);
                cacc[j]     = fma2(ev, pack2(vv.x, vv.y), cacc[j]);
                cacc[j + 1] = fma2(ev, pack2(vv.z, vv.w), cacc[j + 1]);
            }
        }
        if (lane < 22) {
            u64 inv = pack2(1.0f / den0, 1.0f / den1);
            int cb = F2_CTX + qi * CTX_STR + (p * 2 + hl) * 8;
#pragma unroll
            for (int j = 0; j < 8; j++) stg[cb + j] = mul2(cacc[j], inv);
        }
        __syncwarp();
    }

    // ---------------- output projection + residual + LN_A -------------------
    u64 o[S];
    {
        u64 bo = dup2(W[O_OUTB + lane]);
#pragma unroll
        for (int s = 0; s < S; s++) o[s] = bo;
    }
    for (int d0 = 0; d0 < 32; d0 += 4) {
        float4 fw = *reinterpret_cast<const float4*>(&W[O_OUTW + lane * OUTW_STR + d0]);
        u64 w0 = dup2(fw.x), w1 = dup2(fw.y), w2 = dup2(fw.z), w3 = dup2(fw.w);
#pragma unroll
        for (int s = 0; s < S; s++) {
            float4 c0 = *reinterpret_cast<const float4*>(&stf[F2_CTX + s * CTX_STR + d0]);
            float4 c1 = *reinterpret_cast<const float4*>(&stf[F2_CTX + s * CTX_STR + d0 + 2]);
            o[s] = fma2(pack2(c0.x, c0.y), w0, o[s]);
            o[s] = fma2(pack2(c0.z, c0.w), w1, o[s]);
            o[s] = fma2(pack2(c1.x, c1.y), w2, o[s]);
            o[s] = fma2(pack2(c1.z, c1.w), w3, o[s]);
        }
    }
#pragma unroll
    for (int s = 0; s < S; s++)
        o[s] = add2(o[s], h2u[s * 32 + lane]);
    __syncwarp();
    ln_apply<S>(h2u, 0, stg + F2_CTX,
                o, dup2(W[O_LNAG + lane]), dup2(W[O_LNAB + lane]), lane);

    ffn_pass<0, 6>(h2u, stg, W, lane);
    ffn_pass<6, 5>(h2u, stg, W, lane);
}

// Block 2: CLS-specialized — K/V for all tokens; V stays in registers.
__device__ __noinline__ void block2_pair(int hoff, int soff, int lane)
{
    u64* h2u = reinterpret_cast<u64*>(&smem[hoff]);
    u64* stg = reinterpret_cast<u64*>(&smem[soff]);
    const float2* h2f = reinterpret_cast<const float2*>(h2u);
    const float2* stf = reinterpret_cast<const float2*>(stg);
    const float* W = &smem[O_BLKW];

    // ---------------- QKV: k,v all tokens; q token 0 only -------------------
    u64 ka[S], va[S];
    u64 q0 = dup2(W[O_QKVB + lane]);
    {
        u64 bk = dup2(W[O_QKVB + 32 + lane]);
        u64 bv = dup2(W[O_QKVB + 64 + lane]);
#pragma unroll
        for (int s = 0; s < S; s++) { ka[s] = bk; va[s] = bv; }
    }
    for (int d0 = 0; d0 < 32; d0 += 4) {
        float4 fq = *reinterpret_cast<const float4*>(&W[O_QKVW + lane * QKVW_STR + d0]);
        float4 fk = *reinterpret_cast<const float4*>(&W[O_QKVW + (lane + 32) * QKVW_STR + d0]);
        float4 fv = *reinterpret_cast<const float4*>(&W[O_QKVW + (lane + 64) * QKVW_STR + d0]);
        u64 wq[4] = {dup2(fq.x), dup2(fq.y), dup2(fq.z), dup2(fq.w)};
        u64 wk[4] = {dup2(fk.x), dup2(fk.y), dup2(fk.z), dup2(fk.w)};
        u64 wv[4] = {dup2(fv.x), dup2(fv.y), dup2(fv.z), dup2(fv.w)};
#pragma unroll
        for (int s = 0; s < S; s++) {
            float4 a = *reinterpret_cast<const float4*>(&h2f[s * 32 + d0]);
            float4 b = *reinterpret_cast<const float4*>(&h2f[s * 32 + d0 + 2]);
            u64 x[4] = {pack2(a.x, a.y), pack2(a.z, a.w),
                        pack2(b.x, b.y), pack2(b.z, b.w)};
#pragma unroll
            for (int j = 0; j < 4; j++) {
                ka[s] = fma2(x[j], wk[j], ka[s]);
                va[s] = fma2(x[j], wv[j], va[s]);
            }
            if (s == 0) {
#pragma unroll
                for (int j = 0; j < 4; j++) q0 = fma2(x[j], wq[j], q0);
            }
        }
    }
    q0 = mul2(q0, dup2(0.35355339059327373f));

    // stage q0 / K only (lane = dim); V stays in registers
    stg[F2_Q2 + lane] = q0;
#pragma unroll
    for (int s = 0; s < S; s++)
        stg[F2_K2 + s * 32 + lane] = ka[s];
    __syncwarp();

    // ---------------- attention row 0: lane = dim, head = lane>>3 -----------
    const int hb2 = (lane >> 3) * 8;
    u64 qr[8];
#pragma unroll
    for (int j = 0; j < 8; j += 2) {
        float4 t = *reinterpret_cast<const float4*>(&stf[F2_Q2 + hb2 + j]);
        qr[j] = pack2(t.x, t.y); qr[j + 1] = pack2(t.z, t.w);
    }
    float e0[S], e1[S];
#pragma unroll
    for (int ki = 0; ki < S; ki++) {
        u64 acc = pack2(0.f, 0.f);
#pragma unroll
        for (int j = 0; j < 8; j += 2) {
            float4 kv = *reinterpret_cast<const float4*>(&stf[F2_K2 + ki * 32 + hb2 + j]);
            acc = fma2(qr[j],     pack2(kv.x, kv.y), acc);
            acc = fma2(qr[j + 1], pack2(kv.z, kv.w), acc);
        }
        unpack2(acc, e0[ki], e1[ki]);
    }
    float m0 = e0[0], m1 = e1[0];
#pragma unroll
    for (int ki = 1; ki < S; ki++) { m0 = fmaxf(m0, e0[ki]); m1 = fmaxf(m1, e1[ki]); }
    float den0 = 0.f, den1 = 0.f;
#pragma unroll
    for (int ki = 0; ki < S; ki++) {
        e0[ki] = __expf(e0[ki] - m0); den0 += e0[ki];
        e1[ki] = __expf(e1[ki] - m1); den1 += e1[ki];
    }
    u64 c = pack2(0.f, 0.f);
#pragma unroll
    for (int ki = 0; ki < S; ki++)
        c = fma2(pack2(e0[ki], e1[ki]), va[ki], c);    // V from registers
    c = mul2(c, pack2(1.0f / den0, 1.0f / den1));
    stg[F2_C2 + lane] = c;
    __syncwarp();

    // ---------------- out-proj token 0 + residual + LN_A --------------------
    u64 o = dup2(W[O_OUTB + lane]);
    for (int d0 = 0; d0 < 32; d0 += 4) {
        float4 fw = *reinterpret_cast<const float4*>(&W[O_OUTW + lane * OUTW_STR + d0]);
        float4 c0 = *reinterpret_cast<const float4*>(&stf[F2_C2 + d0]);
        float4 c1 = *reinterpret_cast<const float4*>(&stf[F2_C2 + d0 + 2]);
        o = fma2(pack2(c0.x, c0.y), dup2(fw.x), o);
        o = fma2(pack2(c0.z, c0.w), dup2(fw.y), o);
        o = fma2(pack2(c1.x, c1.y), dup2(fw.z), o);
        o = fma2(pack2(c1.z, c1.w), dup2(fw.w), o);
    }
    o = add2(o, h2u[lane]);
    u64 hn = ln_norm(o, dup2(W[O_LNAG + lane]), dup2(W[O_LNAB + lane]));
    h2u[lane] = hn;
    __syncwarp();

    // ---------------- FFN token 0 -------------------------------------------
    u64 ga[4];
#pragma unroll
    for (int j = 0; j < 4; j++) ga[j] = dup2(W[O_B1 + lane + 32 * j]);
    for (int d0 = 0; d0 < 32; d0 += 4) {
        float4 a = *reinterpret_cast<const float4*>(&h2f[d0]);
        float4 b = *reinterpret_cast<const float4*>(&h2f[d0 + 2]);
        u64 x[4] = {pack2(a.x, a.y), pack2(a.z, a.w),
                    pack2(b.x, b.y), pack2(b.z, b.w)};
#pragma unroll
        for (int j = 0; j < 4; j++) {
            float4 f = *reinterpret_cast<const float4*>(
                &W[O_W1 + (lane + 32 * j) * W1_STR + d0]);
            ga[j] = fma2(x[0], dup2(f.x), ga[j]);
            ga[j] = fma2(x[1], dup2(f.y), ga[j]);
            ga[j] = fma2(x[2], dup2(f.z), ga[j]);
            ga[j] = fma2(x[3], dup2(f.w), ga[j]);
        }
    }
#pragma unroll
    for (int j = 0; j < 4; j++) {
        float a, b; unpack2(ga[j], a, b);
        stg[F2_G2 + lane + 32 * j] = pack2(gelu1(a), gelu1(b));
    }
    __syncwarp();

    u64 o2 = dup2(W[O_B2 + lane]);
    for (int f0 = 0; f0 < 128; f0 += 4) {
        float4 fw = *reinterpret_cast<const float4*>(&W[O_W2 + lane * W2_STR + f0]);
        float4 a = *reinterpret_cast<const float4*>(&stf[F2_G2 + f0]);
        float4 b = *reinterpret_cast<const float4*>(&stf[F2_G2 + f0 + 2]);
        o2 = fma2(pack2(a.x, a.y), dup2(fw.x), o2);
        o2 = fma2(pack2(a.z, a.w), dup2(fw.y), o2);
        o2 = fma2(pack2(b.x, b.y), dup2(fw.z), o2);
        o2 = fma2(pack2(b.z, b.w), dup2(fw.w), o2);
    }
    o2 = add2(o2, hn);
    h2u[lane] = ln_norm(o2, dup2(W[O_LNBG + lane]), dup2(W[O_LNBB + lane]));
    __syncwarp();
}

__global__ void __launch_bounds__(THREADS)
tab_transformer_kernel(KParams p)
{
    const int tid = threadIdx.x;

    for (int i = tid; i < 320; i += THREADS) smem[O_WFEAT + i] = p.in[1][i];
    for (int i = tid; i < 320; i += THREADS) smem[O_BFEAT + i] = p.in[2][i];
    if (tid < 32) {
        smem[O_CLS  + tid] = p.in[3][tid];
        smem[O_CLFW + tid] = p.in[28][tid];
    }
    if (tid == 0) smem[O_CLFB] = p.in[29][0];
    stage_block(&smem[O_BLKW], &p.in[4], tid);
    __syncthreads();

    const int warp = tid >> 5, lane = tid & 31;
    int pr = blockIdx.x * NW + warp;
    const bool valid = (pr < NPAIR);
    if (!valid) pr = NPAIR - 1;
    const int b0 = pr * 2;

    const int hoff = O_ACT + warp * ACT_F;
    const int soff = hoff + H2_F;
    u64* h2u = reinterpret_cast<u64*>(&smem[hoff]);

    float xv0 = (lane < 10) ? p.in[0][(size_t)b0 * 10 + lane] : 0.f;
    float xv1 = (lane < 10) ? p.in[0][(size_t)(b0 + 1) * 10 + lane] : 0.f;
    h2u[lane] = dup2(smem[O_CLS + lane]);
#pragma unroll
    for (int i = 0; i < 10; i++) {
        float a = __shfl_sync(0xffffffffu, xv0, i);
        float b = __shfl_sync(0xffffffffu, xv1, i);
        u64 w  = dup2(smem[O_WFEAT + i * 32 + lane]);
        u64 bb = dup2(smem[O_BFEAT + i * 32 + lane]);
        h2u[(i + 1) * 32 + lane] = fma2(pack2(a, b), w, bb);
    }
    __syncwarp();

    block_pair(hoff, soff, lane);

    __syncthreads();
    stage_block(&smem[O_BLKW], &p.in[16], tid);
    __syncthreads();

    block2_pair(hoff, soff, lane);

    u64 v = mul2(h2u[lane], dup2(smem[O_CLFW + lane]));
#pragma unroll
    for (int mk = 16; mk; mk >>= 1) v = add2(v, shflx2(v, mk));
    if (valid && lane == 0) {
        float r0, r1; unpack2(v, r0, r1);
        float cb = smem[O_CLFB];
        *reinterpret_cast<float2*>(&p.out[b0]) = make_float2(r0 + cb, r1 + cb);
    }
}

extern "C" void kernel_launch(void* const* d_in, const int* in_sizes, int n_in,
                              void* d_out, int out_size)
{
    (void)in_sizes; (void)n_in; (void)out_size;
    KParams p;
    for (int i = 0; i < 30; i++) p.in[i] = (const float*)d_in[i];
    p.out = (float*)d_out;

    cudaFuncSetAttribute(tab_transformer_kernel,
                         cudaFuncAttributeMaxDynamicSharedMemorySize, SMEM_BYTES);

    const int grid = (NPAIR + NW - 1) / NW;   // 4096
    tab_transformer_kernel<<<grid, THREADS, SMEM_BYTES>>>(p);
}